// round 2
// baseline (speedup 1.0000x reference)
#include <cuda_runtime.h>
#include <cuda_bf16.h>
#include <math.h>
#include <stdint.h>

// Problem constants
#define Bq   8
#define Sq   1024
#define Dq   1024
#define Hq   16
#define DKq  64
#define DFFq 4096
#define MROWS (Bq * Sq)          // 8192

// ---------------------------------------------------------------------------
// Scratch (device globals — allocation-free per harness rules)
// ---------------------------------------------------------------------------
__device__ float g_q   [MROWS * Dq];
__device__ float g_k   [MROWS * Dq];
__device__ float g_v   [MROWS * Dq];
__device__ float g_attn[MROWS * Dq];
__device__ float g_tmp [MROWS * Dq];
__device__ float g_x1  [MROWS * Dq];
__device__ float g_ff  [MROWS * DFFq];

// ---------------------------------------------------------------------------
// 3xTF32 tensor-core GEMM: C[M,N] = A[M,K] @ B[K,N] + bias (optional ReLU)
// Block tile 128x128, BK=16, 256 threads (8 warps), warp tile 64x32.
// Each fp32 value is split x = hi + lo (both tf32); accumulate
// hi*hi + lo*hi + hi*lo in fp32 -> fp32-level accuracy at 3x tensor cost.
// smem stores {hi,lo} interleaved as float2 so one LDS.64 fetches both limbs.
// A stored [k][m] (stride 132 float2), B stored [n][k] (stride 20 float2);
// both fragment loads and the transposing stores are bank-conflict-free.
// ---------------------------------------------------------------------------
#define LDA_S 132   // float2 stride for As2 rows   (2*132 % 32 == 8)
#define LDB_S 20    // float2 stride for Bs2 rows   (2*20  % 32 == 8)

__device__ __forceinline__ float2 split_tf32(float x) {
    uint32_t h;
    asm("cvt.rna.tf32.f32 %0, %1;" : "=r"(h) : "f"(x));
    float hf = __uint_as_float(h);
    float l = x - hf;
    uint32_t hl;
    asm("cvt.rna.tf32.f32 %0, %1;" : "=r"(hl) : "f"(l));
    return make_float2(hf, __uint_as_float(hl));
}

#define MMA_TF32(d, a, b)                                                     \
    asm volatile(                                                             \
        "mma.sync.aligned.m16n8k8.row.col.f32.tf32.tf32.f32 "                 \
        "{%0,%1,%2,%3},{%4,%5,%6,%7},{%8,%9},{%0,%1,%2,%3};"                  \
        : "+f"(d[0]), "+f"(d[1]), "+f"(d[2]), "+f"(d[3])                      \
        : "r"(a[0]), "r"(a[1]), "r"(a[2]), "r"(a[3]), "r"(b[0]), "r"(b[1]))

__global__ __launch_bounds__(256) void tf32gemm_bias(
    const float* __restrict__ A, const float* __restrict__ B,
    const float* __restrict__ bias, float* __restrict__ C,
    int M, int N, int K, int doRelu)
{
    __shared__ float2 As2[16][LDA_S];    // [k][m] {hi,lo}
    __shared__ float2 Bs2[128][LDB_S];   // [n][k] {hi,lo}

    const int tid  = threadIdx.x;
    const int warp = tid >> 5;
    const int lane = tid & 31;
    const int lr   = lane >> 2;          // 0..7
    const int lc   = lane & 3;           // 0..3
    const int wr   = warp & 1;           // 2 warp rows
    const int wc   = warp >> 1;          // 4 warp cols
    const int m0   = wr * 64;
    const int n0   = wc * 32;

    const int bm = blockIdx.y * 128;
    const int bn = blockIdx.x * 128;

    // Global->smem thread mappings (coalesced-enough, conflict-free STS)
    const int aRow = tid & 127;          // A: row within tile
    const int aKq  = (tid >> 7) * 4;     // k quad: 0 or 4 (second load +8)
    const int bK   = tid & 15;           // B: k within tile
    const int bN4  = (tid >> 4) * 4;     // n quad (second load +64)

    const float* Ag = A + (size_t)(bm + aRow) * K + aKq;
    const float* Bg = B + (size_t)bK * N + bn + bN4;

    float acc[4][4][4];
#pragma unroll
    for (int i = 0; i < 4; i++)
#pragma unroll
        for (int j = 0; j < 4; j++)
#pragma unroll
            for (int r = 0; r < 4; r++) acc[i][j][r] = 0.f;

    // Prologue: load + split + store first tile
    float4 ra0 = *(const float4*)(Ag);
    float4 ra1 = *(const float4*)(Ag + 8);
    float4 rb0 = *(const float4*)(Bg);
    float4 rb1 = *(const float4*)(Bg + 64);

    {
        const float* a0p = &ra0.x;
        const float* a1p = &ra1.x;
#pragma unroll
        for (int c = 0; c < 4; c++) {
            As2[aKq + c][aRow]     = split_tf32(a0p[c]);
            As2[aKq + 8 + c][aRow] = split_tf32(a1p[c]);
        }
        const float* b0p = &rb0.x;
        const float* b1p = &rb1.x;
#pragma unroll
        for (int c = 0; c < 4; c++) {
            Bs2[bN4 + c][bK]      = split_tf32(b0p[c]);
            Bs2[bN4 + 64 + c][bK] = split_tf32(b1p[c]);
        }
    }
    __syncthreads();

    for (int k0 = 0; k0 < K; k0 += 16) {
        const bool last = (k0 + 16 >= K);
        if (!last) {
            const float* Agn = Ag + k0 + 16;
            const float* Bgn = Bg + (size_t)(k0 + 16) * N;
            ra0 = *(const float4*)(Agn);
            ra1 = *(const float4*)(Agn + 8);
            rb0 = *(const float4*)(Bgn);
            rb1 = *(const float4*)(Bgn + 64);
        }

        // Compute 2 k-steps of 8
#pragma unroll
        for (int ks = 0; ks < 2; ks++) {
            const int kb = ks * 8;
            uint32_t ah[4][4], al[4][4], bh[4][2], bl[4][2];
#pragma unroll
            for (int i = 0; i < 4; i++) {
                const int mrow = m0 + i * 16 + lr;
                float2 p0 = As2[kb + lc][mrow];
                float2 p1 = As2[kb + lc][mrow + 8];
                float2 p2 = As2[kb + lc + 4][mrow];
                float2 p3 = As2[kb + lc + 4][mrow + 8];
                ah[i][0] = __float_as_uint(p0.x); al[i][0] = __float_as_uint(p0.y);
                ah[i][1] = __float_as_uint(p1.x); al[i][1] = __float_as_uint(p1.y);
                ah[i][2] = __float_as_uint(p2.x); al[i][2] = __float_as_uint(p2.y);
                ah[i][3] = __float_as_uint(p3.x); al[i][3] = __float_as_uint(p3.y);
            }
#pragma unroll
            for (int j = 0; j < 4; j++) {
                const int nrow = n0 + j * 8 + lr;
                float2 q0 = Bs2[nrow][kb + lc];
                float2 q1 = Bs2[nrow][kb + lc + 4];
                bh[j][0] = __float_as_uint(q0.x); bl[j][0] = __float_as_uint(q0.y);
                bh[j][1] = __float_as_uint(q1.x); bl[j][1] = __float_as_uint(q1.y);
            }
#pragma unroll
            for (int i = 0; i < 4; i++)
#pragma unroll
                for (int j = 0; j < 4; j++) {
                    MMA_TF32(acc[i][j], ah[i], bh[j]);
                    MMA_TF32(acc[i][j], al[i], bh[j]);
                    MMA_TF32(acc[i][j], ah[i], bl[j]);
                }
        }

        if (!last) {
            __syncthreads();
            const float* a0p = &ra0.x;
            const float* a1p = &ra1.x;
#pragma unroll
            for (int c = 0; c < 4; c++) {
                As2[aKq + c][aRow]     = split_tf32(a0p[c]);
                As2[aKq + 8 + c][aRow] = split_tf32(a1p[c]);
            }
            const float* b0p = &rb0.x;
            const float* b1p = &rb1.x;
#pragma unroll
            for (int c = 0; c < 4; c++) {
                Bs2[bN4 + c][bK]      = split_tf32(b0p[c]);
                Bs2[bN4 + 64 + c][bK] = split_tf32(b1p[c]);
            }
            __syncthreads();
        }
    }

    // Epilogue: bias (+ReLU), float2 stores
#pragma unroll
    for (int j = 0; j < 4; j++) {
        const int cc = bn + n0 + j * 8 + 2 * lc;
        float2 bb = *(const float2*)(bias + cc);
#pragma unroll
        for (int i = 0; i < 4; i++) {
            const int r0 = bm + m0 + i * 16 + lr;
            float v0 = acc[i][j][0] + bb.x;
            float v1 = acc[i][j][1] + bb.y;
            float v2 = acc[i][j][2] + bb.x;
            float v3 = acc[i][j][3] + bb.y;
            if (doRelu) {
                v0 = fmaxf(v0, 0.f); v1 = fmaxf(v1, 0.f);
                v2 = fmaxf(v2, 0.f); v3 = fmaxf(v3, 0.f);
            }
            *(float2*)(C + (size_t)r0 * N + cc)       = make_float2(v0, v1);
            *(float2*)(C + (size_t)(r0 + 8) * N + cc) = make_float2(v2, v3);
        }
    }
}

// ---------------------------------------------------------------------------
// Flash-style attention (unchanged from round 1 — validated).
// ---------------------------------------------------------------------------
__global__ __launch_bounds__(128) void attention_kernel(
    const float* __restrict__ Q, const float* __restrict__ K,
    const float* __restrict__ V, const int* __restrict__ mask,
    float* __restrict__ O)
{
    __shared__ float Ks[64][64];
    __shared__ float Vs[64][64];
    __shared__ int   ms[64];

    const int b  = blockIdx.z;
    const int h  = blockIdx.y;
    const int qt = blockIdx.x;
    const int t  = threadIdx.x;
    const int qrow = qt * 128 + t;

    const float* qp = Q + ((size_t)(b * Sq + qrow)) * Dq + h * DKq;
    float qreg[DKq];
#pragma unroll
    for (int d = 0; d < DKq; d += 4) {
        float4 t4 = *(const float4*)(qp + d);
        qreg[d + 0] = t4.x * 0.125f;
        qreg[d + 1] = t4.y * 0.125f;
        qreg[d + 2] = t4.z * 0.125f;
        qreg[d + 3] = t4.w * 0.125f;
    }

    float acc[DKq];
#pragma unroll
    for (int d = 0; d < DKq; d++) acc[d] = 0.f;
    float l = 0.f;

    for (int kt = 0; kt < Sq; kt += 64) {
        for (int i = t; i < 64 * 16; i += 128) {
            int r = i >> 4;
            int c = (i & 15) << 2;
            size_t gidx = ((size_t)(b * Sq + kt + r)) * Dq + h * DKq + c;
            *(float4*)&Ks[r][c] = *(const float4*)(K + gidx);
            *(float4*)&Vs[r][c] = *(const float4*)(V + gidx);
        }
        if (t < 64) ms[t] = mask[b * Sq + kt + t];
        __syncthreads();

        for (int j = 0; j < 64; ++j) {
            float s = 0.f;
#pragma unroll
            for (int d = 0; d < DKq; d += 4) {
                float4 kk = *(const float4*)&Ks[j][d];
                s += qreg[d]     * kk.x;
                s += qreg[d + 1] * kk.y;
                s += qreg[d + 2] * kk.z;
                s += qreg[d + 3] * kk.w;
            }
            float p = ms[j] ? __expf(s) : 0.f;
            l += p;
#pragma unroll
            for (int d = 0; d < DKq; d += 4) {
                float4 vv = *(const float4*)&Vs[j][d];
                acc[d + 0] += p * vv.x;
                acc[d + 1] += p * vv.y;
                acc[d + 2] += p * vv.z;
                acc[d + 3] += p * vv.w;
            }
        }
        __syncthreads();
    }

    const float inv = 1.f / l;
    float* op = O + ((size_t)(b * Sq + qrow)) * Dq + h * DKq;
#pragma unroll
    for (int d = 0; d < DKq; d += 4) {
        float4 o4 = make_float4(acc[d] * inv, acc[d + 1] * inv,
                                acc[d + 2] * inv, acc[d + 3] * inv);
        *(float4*)(op + d) = o4;
    }
}

// ---------------------------------------------------------------------------
// Fused residual + LayerNorm over last dim (D=1024). One block per row.
// ---------------------------------------------------------------------------
__global__ __launch_bounds__(256) void residual_ln(
    const float* __restrict__ X, const float* __restrict__ Y,
    const float* __restrict__ Aw, const float* __restrict__ Bw,
    float* __restrict__ out)
{
    const int row = blockIdx.x;
    const int tid = threadIdx.x;
    const size_t base = (size_t)row * Dq + tid * 4;

    float4 xv = *(const float4*)(X + base);
    float4 yv = *(const float4*)(Y + base);
    float4 v  = make_float4(xv.x + yv.x, xv.y + yv.y, xv.z + yv.z, xv.w + yv.w);

    float s  = v.x + v.y + v.z + v.w;
    float ss = v.x * v.x + v.y * v.y + v.z * v.z + v.w * v.w;

#pragma unroll
    for (int o = 16; o > 0; o >>= 1) {
        s  += __shfl_xor_sync(0xffffffffu, s,  o);
        ss += __shfl_xor_sync(0xffffffffu, ss, o);
    }

    __shared__ float rs[8], rss[8];
    const int w = tid >> 5, lane = tid & 31;
    if (lane == 0) { rs[w] = s; rss[w] = ss; }
    __syncthreads();
    if (tid == 0) {
        float S = 0.f, SS = 0.f;
#pragma unroll
        for (int i = 0; i < 8; i++) { S += rs[i]; SS += rss[i]; }
        rs[0] = S; rss[0] = SS;
    }
    __syncthreads();

    const float mean = rs[0]  * (1.f / Dq);
    const float var  = rss[0] * (1.f / Dq) - mean * mean;
    const float rstd = rsqrtf(var + 1e-6f);

    float4 a4 = *(const float4*)(Aw + tid * 4);
    float4 b4 = *(const float4*)(Bw + tid * 4);
    float4 o4;
    o4.x = a4.x * (v.x - mean) * rstd + b4.x;
    o4.y = a4.y * (v.y - mean) * rstd + b4.y;
    o4.z = a4.z * (v.z - mean) * rstd + b4.z;
    o4.w = a4.w * (v.w - mean) * rstd + b4.w;
    *(float4*)(out + base) = o4;
}

// ---------------------------------------------------------------------------
// kernel_launch
// ---------------------------------------------------------------------------
extern "C" void kernel_launch(void* const* d_in, const int* in_sizes, int n_in,
                              void* d_out, int out_size)
{
    const float* x    = (const float*)d_in[0];
    const int*   mask = (const int*)  d_in[1];
    const float* wq   = (const float*)d_in[2];
    const float* bq   = (const float*)d_in[3];
    const float* wk   = (const float*)d_in[4];
    const float* bk   = (const float*)d_in[5];
    const float* wv   = (const float*)d_in[6];
    const float* bv   = (const float*)d_in[7];
    const float* wo   = (const float*)d_in[8];
    const float* bo   = (const float*)d_in[9];
    const float* l1a  = (const float*)d_in[10];
    const float* l1b  = (const float*)d_in[11];
    const float* l2a  = (const float*)d_in[12];
    const float* l2b  = (const float*)d_in[13];
    const float* w1   = (const float*)d_in[14];
    const float* b1   = (const float*)d_in[15];
    const float* w2   = (const float*)d_in[16];
    const float* b2   = (const float*)d_in[17];
    float* out = (float*)d_out;

    float *q, *k, *v, *attn, *tmp, *x1, *ff;
    cudaGetSymbolAddress((void**)&q,    g_q);
    cudaGetSymbolAddress((void**)&k,    g_k);
    cudaGetSymbolAddress((void**)&v,    g_v);
    cudaGetSymbolAddress((void**)&attn, g_attn);
    cudaGetSymbolAddress((void**)&tmp,  g_tmp);
    cudaGetSymbolAddress((void**)&x1,   g_x1);
    cudaGetSymbolAddress((void**)&ff,   g_ff);

    const dim3 gD(Dq / 128, MROWS / 128);      // (8, 64)
    const dim3 gF(DFFq / 128, MROWS / 128);    // (32, 64)

    // QKV projections (tensor cores, 3xTF32)
    tf32gemm_bias<<<gD, 256>>>(x, wq, bq, q, MROWS, Dq, Dq, 0);
    tf32gemm_bias<<<gD, 256>>>(x, wk, bk, k, MROWS, Dq, Dq, 0);
    tf32gemm_bias<<<gD, 256>>>(x, wv, bv, v, MROWS, Dq, Dq, 0);

    // Attention
    attention_kernel<<<dim3(Sq / 128, Hq, Bq), 128>>>(q, k, v, mask, attn);

    // O projection + residual + LN1
    tf32gemm_bias<<<gD, 256>>>(attn, wo, bo, tmp, MROWS, Dq, Dq, 0);
    residual_ln<<<MROWS, 256>>>(x, tmp, l1a, l1b, x1);

    // FFN
    tf32gemm_bias<<<gF, 256>>>(x1, w1, b1, ff, MROWS, DFFq, Dq, 1);
    tf32gemm_bias<<<gD, 256>>>(ff, w2, b2, tmp, MROWS, Dq, DFFq, 0);
    residual_ln<<<MROWS, 256>>>(x1, tmp, l2a, l2b, out);
}

// round 3
// speedup vs baseline: 1.0034x; 1.0034x over previous
#include <cuda_runtime.h>
#include <cuda_bf16.h>
#include <math.h>
#include <stdint.h>

// Problem constants
#define Bq   8
#define Sq   1024
#define Dq   1024
#define Hq   16
#define DKq  64
#define DFFq 4096
#define MROWS (Bq * Sq)          // 8192

// ---------------------------------------------------------------------------
// Scratch (device globals — allocation-free per harness rules)
// ---------------------------------------------------------------------------
__device__ float g_q   [MROWS * Dq];
__device__ float g_k   [MROWS * Dq];
__device__ float g_v   [MROWS * Dq];
__device__ float g_attn[MROWS * Dq];
__device__ float g_tmp [MROWS * Dq];
__device__ float g_x1  [MROWS * Dq];
__device__ float g_ff  [MROWS * DFFq];

// ---------------------------------------------------------------------------
// 3xTF32 tensor-core GEMM: C[M,N] = A[M,K] @ B[K,N] + bias (optional ReLU)
// Block tile 128x128, BK=16, 256 threads (8 warps), warp tile 64x32.
// Each fp32 value is split x = hi + lo (both tf32); accumulate
// hi*hi + lo*hi + hi*lo in fp32 -> fp32-level accuracy at 3x tensor cost.
// smem stores {hi,lo} interleaved as float2 so one LDS.64 fetches both limbs.
// A stored [k][m] (stride 132 float2), B stored [n][k] (stride 20 float2);
// both fragment loads and the transposing stores are bank-conflict-free.
// ---------------------------------------------------------------------------
#define LDA_S 132   // float2 stride for As2 rows   (2*132 % 32 == 8)
#define LDB_S 20    // float2 stride for Bs2 rows   (2*20  % 32 == 8)

__device__ __forceinline__ float2 split_tf32(float x) {
    uint32_t h;
    asm("cvt.rna.tf32.f32 %0, %1;" : "=r"(h) : "f"(x));
    float hf = __uint_as_float(h);
    float l = x - hf;
    uint32_t hl;
    asm("cvt.rna.tf32.f32 %0, %1;" : "=r"(hl) : "f"(l));
    return make_float2(hf, __uint_as_float(hl));
}

#define MMA_TF32(d, a, b)                                                     \
    asm volatile(                                                             \
        "mma.sync.aligned.m16n8k8.row.col.f32.tf32.tf32.f32 "                 \
        "{%0,%1,%2,%3},{%4,%5,%6,%7},{%8,%9},{%0,%1,%2,%3};"                  \
        : "+f"(d[0]), "+f"(d[1]), "+f"(d[2]), "+f"(d[3])                      \
        : "r"(a[0]), "r"(a[1]), "r"(a[2]), "r"(a[3]), "r"(b[0]), "r"(b[1]))

__global__ __launch_bounds__(256) void tf32gemm_bias(
    const float* __restrict__ A, const float* __restrict__ B,
    const float* __restrict__ bias, float* __restrict__ C,
    int M, int N, int K, int doRelu)
{
    __shared__ float2 As2[16][LDA_S];    // [k][m] {hi,lo}
    __shared__ float2 Bs2[128][LDB_S];   // [n][k] {hi,lo}

    const int tid  = threadIdx.x;
    const int warp = tid >> 5;
    const int lane = tid & 31;
    const int lr   = lane >> 2;          // 0..7
    const int lc   = lane & 3;           // 0..3
    const int wr   = warp & 1;           // 2 warp rows
    const int wc   = warp >> 1;          // 4 warp cols
    const int m0   = wr * 64;
    const int n0   = wc * 32;

    const int bm = blockIdx.y * 128;
    const int bn = blockIdx.x * 128;

    // Global->smem thread mappings (coalesced-enough, conflict-free STS)
    const int aRow = tid & 127;          // A: row within tile
    const int aKq  = (tid >> 7) * 4;     // k quad: 0 or 4 (second load +8)
    const int bK   = tid & 15;           // B: k within tile
    const int bN4  = (tid >> 4) * 4;     // n quad (second load +64)

    const float* Ag = A + (size_t)(bm + aRow) * K + aKq;
    const float* Bg = B + (size_t)bK * N + bn + bN4;

    float acc[4][4][4];
#pragma unroll
    for (int i = 0; i < 4; i++)
#pragma unroll
        for (int j = 0; j < 4; j++)
#pragma unroll
            for (int r = 0; r < 4; r++) acc[i][j][r] = 0.f;

    // Prologue: load + split + store first tile
    float4 ra0 = *(const float4*)(Ag);
    float4 ra1 = *(const float4*)(Ag + 8);
    float4 rb0 = *(const float4*)(Bg);
    float4 rb1 = *(const float4*)(Bg + 64);

    {
        const float* a0p = &ra0.x;
        const float* a1p = &ra1.x;
#pragma unroll
        for (int c = 0; c < 4; c++) {
            As2[aKq + c][aRow]     = split_tf32(a0p[c]);
            As2[aKq + 8 + c][aRow] = split_tf32(a1p[c]);
        }
        const float* b0p = &rb0.x;
        const float* b1p = &rb1.x;
#pragma unroll
        for (int c = 0; c < 4; c++) {
            Bs2[bN4 + c][bK]      = split_tf32(b0p[c]);
            Bs2[bN4 + 64 + c][bK] = split_tf32(b1p[c]);
        }
    }
    __syncthreads();

    for (int k0 = 0; k0 < K; k0 += 16) {
        const bool last = (k0 + 16 >= K);
        if (!last) {
            const float* Agn = Ag + k0 + 16;
            const float* Bgn = Bg + (size_t)(k0 + 16) * N;
            ra0 = *(const float4*)(Agn);
            ra1 = *(const float4*)(Agn + 8);
            rb0 = *(const float4*)(Bgn);
            rb1 = *(const float4*)(Bgn + 64);
        }

        // Compute 2 k-steps of 8
#pragma unroll
        for (int ks = 0; ks < 2; ks++) {
            const int kb = ks * 8;
            uint32_t ah[4][4], al[4][4], bh[4][2], bl[4][2];
#pragma unroll
            for (int i = 0; i < 4; i++) {
                const int mrow = m0 + i * 16 + lr;
                float2 p0 = As2[kb + lc][mrow];
                float2 p1 = As2[kb + lc][mrow + 8];
                float2 p2 = As2[kb + lc + 4][mrow];
                float2 p3 = As2[kb + lc + 4][mrow + 8];
                ah[i][0] = __float_as_uint(p0.x); al[i][0] = __float_as_uint(p0.y);
                ah[i][1] = __float_as_uint(p1.x); al[i][1] = __float_as_uint(p1.y);
                ah[i][2] = __float_as_uint(p2.x); al[i][2] = __float_as_uint(p2.y);
                ah[i][3] = __float_as_uint(p3.x); al[i][3] = __float_as_uint(p3.y);
            }
#pragma unroll
            for (int j = 0; j < 4; j++) {
                const int nrow = n0 + j * 8 + lr;
                float2 q0 = Bs2[nrow][kb + lc];
                float2 q1 = Bs2[nrow][kb + lc + 4];
                bh[j][0] = __float_as_uint(q0.x); bl[j][0] = __float_as_uint(q0.y);
                bh[j][1] = __float_as_uint(q1.x); bl[j][1] = __float_as_uint(q1.y);
            }
#pragma unroll
            for (int i = 0; i < 4; i++)
#pragma unroll
                for (int j = 0; j < 4; j++) {
                    MMA_TF32(acc[i][j], ah[i], bh[j]);
                    MMA_TF32(acc[i][j], al[i], bh[j]);
                    MMA_TF32(acc[i][j], ah[i], bl[j]);
                }
        }

        if (!last) {
            __syncthreads();
            const float* a0p = &ra0.x;
            const float* a1p = &ra1.x;
#pragma unroll
            for (int c = 0; c < 4; c++) {
                As2[aKq + c][aRow]     = split_tf32(a0p[c]);
                As2[aKq + 8 + c][aRow] = split_tf32(a1p[c]);
            }
            const float* b0p = &rb0.x;
            const float* b1p = &rb1.x;
#pragma unroll
            for (int c = 0; c < 4; c++) {
                Bs2[bN4 + c][bK]      = split_tf32(b0p[c]);
                Bs2[bN4 + 64 + c][bK] = split_tf32(b1p[c]);
            }
            __syncthreads();
        }
    }

    // Epilogue: bias (+ReLU), float2 stores
#pragma unroll
    for (int j = 0; j < 4; j++) {
        const int cc = bn + n0 + j * 8 + 2 * lc;
        float2 bb = *(const float2*)(bias + cc);
#pragma unroll
        for (int i = 0; i < 4; i++) {
            const int r0 = bm + m0 + i * 16 + lr;
            float v0 = acc[i][j][0] + bb.x;
            float v1 = acc[i][j][1] + bb.y;
            float v2 = acc[i][j][2] + bb.x;
            float v3 = acc[i][j][3] + bb.y;
            if (doRelu) {
                v0 = fmaxf(v0, 0.f); v1 = fmaxf(v1, 0.f);
                v2 = fmaxf(v2, 0.f); v3 = fmaxf(v3, 0.f);
            }
            *(float2*)(C + (size_t)r0 * N + cc)       = make_float2(v0, v1);
            *(float2*)(C + (size_t)(r0 + 8) * N + cc) = make_float2(v2, v3);
        }
    }
}

// ---------------------------------------------------------------------------
// Flash-style attention (unchanged from round 1 — validated).
// ---------------------------------------------------------------------------
__global__ __launch_bounds__(128) void attention_kernel(
    const float* __restrict__ Q, const float* __restrict__ K,
    const float* __restrict__ V, const int* __restrict__ mask,
    float* __restrict__ O)
{
    __shared__ float Ks[64][64];
    __shared__ float Vs[64][64];
    __shared__ int   ms[64];

    const int b  = blockIdx.z;
    const int h  = blockIdx.y;
    const int qt = blockIdx.x;
    const int t  = threadIdx.x;
    const int qrow = qt * 128 + t;

    const float* qp = Q + ((size_t)(b * Sq + qrow)) * Dq + h * DKq;
    float qreg[DKq];
#pragma unroll
    for (int d = 0; d < DKq; d += 4) {
        float4 t4 = *(const float4*)(qp + d);
        qreg[d + 0] = t4.x * 0.125f;
        qreg[d + 1] = t4.y * 0.125f;
        qreg[d + 2] = t4.z * 0.125f;
        qreg[d + 3] = t4.w * 0.125f;
    }

    float acc[DKq];
#pragma unroll
    for (int d = 0; d < DKq; d++) acc[d] = 0.f;
    float l = 0.f;

    for (int kt = 0; kt < Sq; kt += 64) {
        for (int i = t; i < 64 * 16; i += 128) {
            int r = i >> 4;
            int c = (i & 15) << 2;
            size_t gidx = ((size_t)(b * Sq + kt + r)) * Dq + h * DKq + c;
            *(float4*)&Ks[r][c] = *(const float4*)(K + gidx);
            *(float4*)&Vs[r][c] = *(const float4*)(V + gidx);
        }
        if (t < 64) ms[t] = mask[b * Sq + kt + t];
        __syncthreads();

        for (int j = 0; j < 64; ++j) {
            float s = 0.f;
#pragma unroll
            for (int d = 0; d < DKq; d += 4) {
                float4 kk = *(const float4*)&Ks[j][d];
                s += qreg[d]     * kk.x;
                s += qreg[d + 1] * kk.y;
                s += qreg[d + 2] * kk.z;
                s += qreg[d + 3] * kk.w;
            }
            float p = ms[j] ? __expf(s) : 0.f;
            l += p;
#pragma unroll
            for (int d = 0; d < DKq; d += 4) {
                float4 vv = *(const float4*)&Vs[j][d];
                acc[d + 0] += p * vv.x;
                acc[d + 1] += p * vv.y;
                acc[d + 2] += p * vv.z;
                acc[d + 3] += p * vv.w;
            }
        }
        __syncthreads();
    }

    const float inv = 1.f / l;
    float* op = O + ((size_t)(b * Sq + qrow)) * Dq + h * DKq;
#pragma unroll
    for (int d = 0; d < DKq; d += 4) {
        float4 o4 = make_float4(acc[d] * inv, acc[d + 1] * inv,
                                acc[d + 2] * inv, acc[d + 3] * inv);
        *(float4*)(op + d) = o4;
    }
}

// ---------------------------------------------------------------------------
// Fused residual + LayerNorm over last dim (D=1024). One block per row.
// ---------------------------------------------------------------------------
__global__ __launch_bounds__(256) void residual_ln(
    const float* __restrict__ X, const float* __restrict__ Y,
    const float* __restrict__ Aw, const float* __restrict__ Bw,
    float* __restrict__ out)
{
    const int row = blockIdx.x;
    const int tid = threadIdx.x;
    const size_t base = (size_t)row * Dq + tid * 4;

    float4 xv = *(const float4*)(X + base);
    float4 yv = *(const float4*)(Y + base);
    float4 v  = make_float4(xv.x + yv.x, xv.y + yv.y, xv.z + yv.z, xv.w + yv.w);

    float s  = v.x + v.y + v.z + v.w;
    float ss = v.x * v.x + v.y * v.y + v.z * v.z + v.w * v.w;

#pragma unroll
    for (int o = 16; o > 0; o >>= 1) {
        s  += __shfl_xor_sync(0xffffffffu, s,  o);
        ss += __shfl_xor_sync(0xffffffffu, ss, o);
    }

    __shared__ float rs[8], rss[8];
    const int w = tid >> 5, lane = tid & 31;
    if (lane == 0) { rs[w] = s; rss[w] = ss; }
    __syncthreads();
    if (tid == 0) {
        float S = 0.f, SS = 0.f;
#pragma unroll
        for (int i = 0; i < 8; i++) { S += rs[i]; SS += rss[i]; }
        rs[0] = S; rss[0] = SS;
    }
    __syncthreads();

    const float mean = rs[0]  * (1.f / Dq);
    const float var  = rss[0] * (1.f / Dq) - mean * mean;
    const float rstd = rsqrtf(var + 1e-6f);

    float4 a4 = *(const float4*)(Aw + tid * 4);
    float4 b4 = *(const float4*)(Bw + tid * 4);
    float4 o4;
    o4.x = a4.x * (v.x - mean) * rstd + b4.x;
    o4.y = a4.y * (v.y - mean) * rstd + b4.y;
    o4.z = a4.z * (v.z - mean) * rstd + b4.z;
    o4.w = a4.w * (v.w - mean) * rstd + b4.w;
    *(float4*)(out + base) = o4;
}

// ---------------------------------------------------------------------------
// kernel_launch
// ---------------------------------------------------------------------------
extern "C" void kernel_launch(void* const* d_in, const int* in_sizes, int n_in,
                              void* d_out, int out_size)
{
    const float* x    = (const float*)d_in[0];
    const int*   mask = (const int*)  d_in[1];
    const float* wq   = (const float*)d_in[2];
    const float* bq   = (const float*)d_in[3];
    const float* wk   = (const float*)d_in[4];
    const float* bk   = (const float*)d_in[5];
    const float* wv   = (const float*)d_in[6];
    const float* bv   = (const float*)d_in[7];
    const float* wo   = (const float*)d_in[8];
    const float* bo   = (const float*)d_in[9];
    const float* l1a  = (const float*)d_in[10];
    const float* l1b  = (const float*)d_in[11];
    const float* l2a  = (const float*)d_in[12];
    const float* l2b  = (const float*)d_in[13];
    const float* w1   = (const float*)d_in[14];
    const float* b1   = (const float*)d_in[15];
    const float* w2   = (const float*)d_in[16];
    const float* b2   = (const float*)d_in[17];
    float* out = (float*)d_out;

    float *q, *k, *v, *attn, *tmp, *x1, *ff;
    cudaGetSymbolAddress((void**)&q,    g_q);
    cudaGetSymbolAddress((void**)&k,    g_k);
    cudaGetSymbolAddress((void**)&v,    g_v);
    cudaGetSymbolAddress((void**)&attn, g_attn);
    cudaGetSymbolAddress((void**)&tmp,  g_tmp);
    cudaGetSymbolAddress((void**)&x1,   g_x1);
    cudaGetSymbolAddress((void**)&ff,   g_ff);

    const dim3 gD(Dq / 128, MROWS / 128);      // (8, 64)
    const dim3 gF(DFFq / 128, MROWS / 128);    // (32, 64)

    // QKV projections (tensor cores, 3xTF32)
    tf32gemm_bias<<<gD, 256>>>(x, wq, bq, q, MROWS, Dq, Dq, 0);
    tf32gemm_bias<<<gD, 256>>>(x, wk, bk, k, MROWS, Dq, Dq, 0);
    tf32gemm_bias<<<gD, 256>>>(x, wv, bv, v, MROWS, Dq, Dq, 0);

    // Attention
    attention_kernel<<<dim3(Sq / 128, Hq, Bq), 128>>>(q, k, v, mask, attn);

    // O projection + residual + LN1
    tf32gemm_bias<<<gD, 256>>>(attn, wo, bo, tmp, MROWS, Dq, Dq, 0);
    residual_ln<<<MROWS, 256>>>(x, tmp, l1a, l1b, x1);

    // FFN
    tf32gemm_bias<<<gF, 256>>>(x1, w1, b1, ff, MROWS, DFFq, Dq, 1);
    tf32gemm_bias<<<gD, 256>>>(ff, w2, b2, tmp, MROWS, Dq, DFFq, 0);
    residual_ln<<<MROWS, 256>>>(x1, tmp, l2a, l2b, out);
}

// round 5
// speedup vs baseline: 2.4765x; 2.4681x over previous
#include <cuda_runtime.h>
#include <cuda_fp16.h>
#include <math.h>
#include <stdint.h>

#define Bq   8
#define Sq   1024
#define Dq   1024
#define Hq   16
#define DKq  64
#define DFFq 4096
#define MROWS (Bq * Sq)

typedef __half h16;

// ---------------- scratch ----------------
__device__ float g_q  [MROWS * Dq];
__device__ float g_k  [MROWS * Dq];
__device__ float g_v  [MROWS * Dq];
__device__ float g_tmp[MROWS * Dq];
__device__ float g_x1 [MROWS * Dq];
__device__ h16 g_xh [MROWS * Dq],  g_xl [MROWS * Dq];
__device__ h16 g_ah [MROWS * Dq],  g_al [MROWS * Dq];
__device__ h16 g_x1h[MROWS * Dq],  g_x1l[MROWS * Dq];
__device__ h16 g_fh [MROWS * DFFq], g_fl[MROWS * DFFq];
__device__ h16 g_wqh[Dq * Dq],  g_wql[Dq * Dq];
__device__ h16 g_wkh[Dq * Dq],  g_wkl[Dq * Dq];
__device__ h16 g_wvh[Dq * Dq],  g_wvl[Dq * Dq];
__device__ h16 g_woh[Dq * Dq],  g_wol[Dq * Dq];
__device__ h16 g_w1h[Dq * DFFq], g_w1l[Dq * DFFq];
__device__ h16 g_w2h[DFFq * Dq], g_w2l[DFFq * Dq];

// ---------------- helpers ----------------
__device__ __forceinline__ uint32_t smem_u32(const void* p) {
    uint32_t a;
    asm("{ .reg .u64 t; cvta.to.shared.u64 t, %1; cvt.u32.u64 %0, t; }" : "=r"(a) : "l"(p));
    return a;
}
__device__ __forceinline__ void cpa16(uint32_t s, const void* g) {
    asm volatile("cp.async.cg.shared.global [%0], [%1], 16;" :: "r"(s), "l"(g));
}
#define CP_COMMIT() asm volatile("cp.async.commit_group;" ::: "memory")
#define CP_WAIT1()  asm volatile("cp.async.wait_group 1;" ::: "memory")
#define CP_WAIT0()  asm volatile("cp.async.wait_group 0;" ::: "memory")
#define LDMX4(r0,r1,r2,r3,addr)                                               \
    asm volatile("ldmatrix.sync.aligned.m8n8.x4.shared.b16 {%0,%1,%2,%3},[%4];" \
        : "=r"(r0), "=r"(r1), "=r"(r2), "=r"(r3) : "r"(addr))
#define HMMA(d,a,b)                                                           \
    asm volatile("mma.sync.aligned.m16n8k16.row.col.f32.f16.f16.f32 "         \
        "{%0,%1,%2,%3},{%4,%5,%6,%7},{%8,%9},{%0,%1,%2,%3};"                  \
        : "+f"((d)[0]), "+f"((d)[1]), "+f"((d)[2]), "+f"((d)[3])              \
        : "r"((a)[0]), "r"((a)[1]), "r"((a)[2]), "r"((a)[3]),                 \
          "r"((b)[0]), "r"((b)[1]))

__device__ __forceinline__ void hsplit(float x, h16& h, h16& l) {
    h = __float2half_rn(x);
    l = __float2half_rn(x - __half2float(h));
}

// ---------------- fp16 2-limb (3-term) HMMA GEMM ----------------
// C[M,N] = (Ah+Al)[M,K] @ (Bh+Bl)^T[N,K] + bias, opt ReLU, opt split out.
// BM=BN=128, BK=64, 256 threads, warp tile 64x32, cp.async double buffer.
#define BM 128
#define BN 128
#define BK 64
#define TILE_B16 16384                 // one 128x64 fp16 tile
#define OFF_AH 0
#define OFF_AL 16384
#define OFF_BH 32768
#define OFF_BL 49152
#define BUFB   65536
#define SMEM_REQ (2 * BUFB)            // 131072

__global__ __launch_bounds__(256, 1) void hgemm3(
    const h16* __restrict__ Ahb, const h16* __restrict__ Alb,
    const h16* __restrict__ Bhb, const h16* __restrict__ Blb,
    const float* __restrict__ bias, float* __restrict__ C,
    h16* __restrict__ Ch, h16* __restrict__ Cl,
    int M, int N, int K, int doRelu)
{
    extern __shared__ char smem[];
    const uint32_t sb = smem_u32(smem);
    const int tid  = threadIdx.x;
    const int warp = tid >> 5, lane = tid & 31;
    const int bm = blockIdx.y * BM, bn = blockIdx.x * BN;
    const int m0w = (warp & 1) * 64, n0w = (warp >> 1) * 32;

    // global->smem load mapping: thread -> (row rL, 16B-chunk cL)
    const int rL = tid >> 3, cL = tid & 7;
    const uint32_t sRowOff = (uint32_t)rL * 128 + (((uint32_t)(cL ^ (rL & 7))) << 4);
    const h16* gAh = Ahb + (size_t)(bm + rL) * K + cL * 8;
    const h16* gAl = Alb + (size_t)(bm + rL) * K + cL * 8;
    const h16* gBh = Bhb + (size_t)(bn + rL) * K + cL * 8;
    const h16* gBl = Blb + (size_t)(bn + rL) * K + cL * 8;
    const size_t rstep = (size_t)32 * K;

    float acc[4][4][4];
#pragma unroll
    for (int i = 0; i < 4; i++)
#pragma unroll
        for (int j = 0; j < 4; j++)
#pragma unroll
            for (int r = 0; r < 4; r++) acc[i][j][r] = 0.f;

    // ldmatrix lane mappings
    const int arow0 = m0w + (lane & 15);                      // +16*mt
    const int akc   = lane >> 4;                              // 0/1
    const int brow0 = n0w + ((lane >> 4) << 3) + (lane & 7);  // +16*bt
    const int bkc   = (lane >> 3) & 1;

    auto LOAD = [&](int c, int buf) {
        const uint32_t s = sb + (uint32_t)buf * BUFB;
        const size_t k0 = (size_t)c * BK;
#pragma unroll
        for (int i = 0; i < 4; i++) {
            const uint32_t so = sRowOff + (uint32_t)i * 4096;
            const size_t go = (size_t)i * rstep + k0;
            cpa16(s + OFF_AH + so, gAh + go);
            cpa16(s + OFF_AL + so, gAl + go);
            cpa16(s + OFF_BH + so, gBh + go);
            cpa16(s + OFF_BL + so, gBl + go);
        }
    };

    auto COMPUTE = [&](int buf) {
        const uint32_t s = sb + (uint32_t)buf * BUFB;
#pragma unroll
        for (int ks = 0; ks < 4; ks++) {
            uint32_t bh[4][2], bl[4][2];
#pragma unroll
            for (int bt = 0; bt < 2; bt++) {
                const int row = brow0 + bt * 16;
                const int kc  = ks * 2 + bkc;
                const uint32_t off = (uint32_t)row * 128 + (((uint32_t)(kc ^ (row & 7))) << 4);
                LDMX4(bh[2*bt][0], bh[2*bt][1], bh[2*bt+1][0], bh[2*bt+1][1], s + OFF_BH + off);
                LDMX4(bl[2*bt][0], bl[2*bt][1], bl[2*bt+1][0], bl[2*bt+1][1], s + OFF_BL + off);
            }
#pragma unroll
            for (int mt = 0; mt < 4; mt++) {
                const int row = arow0 + mt * 16;
                const int kc  = ks * 2 + akc;
                const uint32_t off = (uint32_t)row * 128 + (((uint32_t)(kc ^ (row & 7))) << 4);
                uint32_t a[4];
                LDMX4(a[0], a[1], a[2], a[3], s + OFF_AH + off);
#pragma unroll
                for (int nt = 0; nt < 4; nt++) HMMA(acc[mt][nt], a, bh[nt]);
#pragma unroll
                for (int nt = 0; nt < 4; nt++) HMMA(acc[mt][nt], a, bl[nt]);
                LDMX4(a[0], a[1], a[2], a[3], s + OFF_AL + off);
#pragma unroll
                for (int nt = 0; nt < 4; nt++) HMMA(acc[mt][nt], a, bh[nt]);
            }
        }
    };

    const int chunks = K / BK;
    LOAD(0, 0);
    CP_COMMIT();
    for (int c = 0; c < chunks; c++) {
        if (c + 1 < chunks) {
            LOAD(c + 1, (c + 1) & 1);
            CP_COMMIT();
            CP_WAIT1();
        } else {
            CP_WAIT0();
        }
        __syncthreads();
        COMPUTE(c & 1);
        __syncthreads();
    }

    // epilogue
#pragma unroll
    for (int mt = 0; mt < 4; mt++) {
        const int mr = bm + m0w + mt * 16 + (lane >> 2);
#pragma unroll
        for (int nt = 0; nt < 4; nt++) {
            const int col = bn + n0w + nt * 8 + 2 * (lane & 3);
            const float b0 = bias[col], b1 = bias[col + 1];
            float v0 = acc[mt][nt][0] + b0, v1 = acc[mt][nt][1] + b1;
            float v2 = acc[mt][nt][2] + b0, v3 = acc[mt][nt][3] + b1;
            if (doRelu) {
                v0 = fmaxf(v0, 0.f); v1 = fmaxf(v1, 0.f);
                v2 = fmaxf(v2, 0.f); v3 = fmaxf(v3, 0.f);
            }
            if (C) {
                *(float2*)(C + (size_t)mr * N + col)       = make_float2(v0, v1);
                *(float2*)(C + (size_t)(mr + 8) * N + col) = make_float2(v2, v3);
            }
            if (Ch) {
                h16 h0, l0, h1, l1;
                hsplit(v0, h0, l0); hsplit(v1, h1, l1);
                *(__half2*)(Ch + (size_t)mr * N + col) = __halves2half2(h0, h1);
                *(__half2*)(Cl + (size_t)mr * N + col) = __halves2half2(l0, l1);
                hsplit(v2, h0, l0); hsplit(v3, h1, l1);
                *(__half2*)(Ch + (size_t)(mr + 8) * N + col) = __halves2half2(h0, h1);
                *(__half2*)(Cl + (size_t)(mr + 8) * N + col) = __halves2half2(l0, l1);
            }
        }
    }
}

// ---------------- pre-pass kernels ----------------
__global__ __launch_bounds__(256) void vsplit_kernel(
    const float* __restrict__ s, h16* __restrict__ h, h16* __restrict__ l, int n)
{
    int i = (blockIdx.x * 256 + threadIdx.x) * 4;
    if (i >= n) return;
    float4 v = *(const float4*)(s + i);
    h16 h0,l0,h1,l1,h2,l2,h3,l3;
    hsplit(v.x,h0,l0); hsplit(v.y,h1,l1); hsplit(v.z,h2,l2); hsplit(v.w,h3,l3);
    *(__half2*)(h+i)   = __halves2half2(h0,h1);
    *(__half2*)(h+i+2) = __halves2half2(h2,h3);
    *(__half2*)(l+i)   = __halves2half2(l0,l1);
    *(__half2*)(l+i+2) = __halves2half2(l2,l3);
}

__global__ __launch_bounds__(256) void tsplit_kernel(
    const float* __restrict__ W, h16* __restrict__ Th, h16* __restrict__ Tl,
    int K, int N)
{
    __shared__ float t[32][33];
    const int n0 = blockIdx.x * 32, k0 = blockIdx.y * 32;
    const int tx = threadIdx.x & 31, ty = threadIdx.x >> 5;
#pragma unroll
    for (int i = ty; i < 32; i += 8)
        t[i][tx] = W[(size_t)(k0 + i) * N + n0 + tx];
    __syncthreads();
#pragma unroll
    for (int i = ty; i < 32; i += 8) {
        h16 h, l;
        hsplit(t[tx][i], h, l);
        Th[(size_t)(n0 + i) * K + k0 + tx] = h;
        Tl[(size_t)(n0 + i) * K + k0 + tx] = l;
    }
}

// ---------------- attention (fp32 compute, fp16 split output) ----------------
__global__ __launch_bounds__(128) void attention_kernel(
    const float* __restrict__ Q, const float* __restrict__ K,
    const float* __restrict__ V, const int* __restrict__ mask,
    h16* __restrict__ OH, h16* __restrict__ OL)
{
    __shared__ float Ks[64][64];
    __shared__ float Vs[64][64];
    __shared__ int ms[64];

    const int b = blockIdx.z, h = blockIdx.y, qt = blockIdx.x, t = threadIdx.x;
    const int qrow = qt * 128 + t;

    const float* qp = Q + ((size_t)(b * Sq + qrow)) * Dq + h * DKq;
    float qreg[DKq];
#pragma unroll
    for (int d = 0; d < DKq; d += 4) {
        float4 t4 = *(const float4*)(qp + d);
        qreg[d]   = t4.x * 0.125f;
        qreg[d+1] = t4.y * 0.125f;
        qreg[d+2] = t4.z * 0.125f;
        qreg[d+3] = t4.w * 0.125f;
    }
    float acc[DKq];
#pragma unroll
    for (int d = 0; d < DKq; d++) acc[d] = 0.f;
    float l = 0.f;

    for (int kt = 0; kt < Sq; kt += 64) {
        for (int i = t; i < 64 * 16; i += 128) {
            int r = i >> 4, c = (i & 15) << 2;
            size_t g = ((size_t)(b * Sq + kt + r)) * Dq + h * DKq + c;
            *(float4*)&Ks[r][c] = *(const float4*)(K + g);
            *(float4*)&Vs[r][c] = *(const float4*)(V + g);
        }
        if (t < 64) ms[t] = mask[b * Sq + kt + t];
        __syncthreads();
        for (int j = 0; j < 64; ++j) {
            float s = 0.f;
#pragma unroll
            for (int d = 0; d < DKq; d += 4) {
                float4 kk = *(const float4*)&Ks[j][d];
                s += qreg[d]*kk.x + qreg[d+1]*kk.y + qreg[d+2]*kk.z + qreg[d+3]*kk.w;
            }
            float p = ms[j] ? __expf(s) : 0.f;
            l += p;
#pragma unroll
            for (int d = 0; d < DKq; d += 4) {
                float4 vv = *(const float4*)&Vs[j][d];
                acc[d]   += p * vv.x;
                acc[d+1] += p * vv.y;
                acc[d+2] += p * vv.z;
                acc[d+3] += p * vv.w;
            }
        }
        __syncthreads();
    }
    const float inv = 1.f / l;
    size_t ob = ((size_t)(b * Sq + qrow)) * Dq + h * DKq;
#pragma unroll
    for (int d = 0; d < DKq; d += 2) {
        h16 h0, l0, h1, l1;
        hsplit(acc[d] * inv, h0, l0);
        hsplit(acc[d+1] * inv, h1, l1);
        *(__half2*)(OH + ob + d) = __halves2half2(h0, h1);
        *(__half2*)(OL + ob + d) = __halves2half2(l0, l1);
    }
}

// ---------------- residual + LayerNorm (opt split out) ----------------
__global__ __launch_bounds__(256) void residual_ln(
    const float* __restrict__ X, const float* __restrict__ Y,
    const float* __restrict__ Aw, const float* __restrict__ Bw,
    float* __restrict__ out, h16* __restrict__ oh, h16* __restrict__ ol)
{
    const int row = blockIdx.x, tid = threadIdx.x;
    const size_t base = (size_t)row * Dq + tid * 4;
    float4 xv = *(const float4*)(X + base);
    float4 yv = *(const float4*)(Y + base);
    float4 v = make_float4(xv.x+yv.x, xv.y+yv.y, xv.z+yv.z, xv.w+yv.w);

    float s = v.x+v.y+v.z+v.w;
    float ss = v.x*v.x+v.y*v.y+v.z*v.z+v.w*v.w;
#pragma unroll
    for (int o = 16; o > 0; o >>= 1) {
        s  += __shfl_xor_sync(0xffffffffu, s, o);
        ss += __shfl_xor_sync(0xffffffffu, ss, o);
    }
    __shared__ float rs[8], rss[8];
    const int w = tid >> 5, lane = tid & 31;
    if (lane == 0) { rs[w] = s; rss[w] = ss; }
    __syncthreads();
    if (tid == 0) {
        float S = 0.f, SS = 0.f;
#pragma unroll
        for (int i = 0; i < 8; i++) { S += rs[i]; SS += rss[i]; }
        rs[0] = S; rss[0] = SS;
    }
    __syncthreads();
    const float mean = rs[0] * (1.f / Dq);
    const float var  = rss[0] * (1.f / Dq) - mean * mean;
    const float rstd = rsqrtf(var + 1e-6f);

    float4 a4 = *(const float4*)(Aw + tid * 4);
    float4 b4 = *(const float4*)(Bw + tid * 4);
    float4 o4;
    o4.x = a4.x * (v.x - mean) * rstd + b4.x;
    o4.y = a4.y * (v.y - mean) * rstd + b4.y;
    o4.z = a4.z * (v.z - mean) * rstd + b4.z;
    o4.w = a4.w * (v.w - mean) * rstd + b4.w;
    *(float4*)(out + base) = o4;
    if (oh) {
        h16 h0,l0,h1,l1,h2,l2,h3,l3;
        hsplit(o4.x,h0,l0); hsplit(o4.y,h1,l1); hsplit(o4.z,h2,l2); hsplit(o4.w,h3,l3);
        *(__half2*)(oh+base)   = __halves2half2(h0,h1);
        *(__half2*)(oh+base+2) = __halves2half2(h2,h3);
        *(__half2*)(ol+base)   = __halves2half2(l0,l1);
        *(__half2*)(ol+base+2) = __halves2half2(l2,l3);
    }
}

// ---------------- kernel_launch ----------------
extern "C" void kernel_launch(void* const* d_in, const int* in_sizes, int n_in,
                              void* d_out, int out_size)
{
    const float* x   = (const float*)d_in[0];
    const int* mask  = (const int*)d_in[1];
    const float* wq  = (const float*)d_in[2];
    const float* bq  = (const float*)d_in[3];
    const float* wk  = (const float*)d_in[4];
    const float* bk  = (const float*)d_in[5];
    const float* wv  = (const float*)d_in[6];
    const float* bv  = (const float*)d_in[7];
    const float* wo  = (const float*)d_in[8];
    const float* bo  = (const float*)d_in[9];
    const float* l1a = (const float*)d_in[10];
    const float* l1b = (const float*)d_in[11];
    const float* l2a = (const float*)d_in[12];
    const float* l2b = (const float*)d_in[13];
    const float* w1  = (const float*)d_in[14];
    const float* b1  = (const float*)d_in[15];
    const float* w2  = (const float*)d_in[16];
    const float* b2  = (const float*)d_in[17];
    float* out = (float*)d_out;

    float *q, *k, *v, *tmp, *x1;
    h16 *xh,*xl,*ah,*al,*x1h,*x1l,*fh,*fl;
    h16 *wqh,*wql,*wkh,*wkl,*wvh,*wvl,*woh,*wol,*w1h,*w1l,*w2h,*w2l;
    cudaGetSymbolAddress((void**)&q, g_q);
    cudaGetSymbolAddress((void**)&k, g_k);
    cudaGetSymbolAddress((void**)&v, g_v);
    cudaGetSymbolAddress((void**)&tmp, g_tmp);
    cudaGetSymbolAddress((void**)&x1, g_x1);
    cudaGetSymbolAddress((void**)&xh, g_xh);   cudaGetSymbolAddress((void**)&xl, g_xl);
    cudaGetSymbolAddress((void**)&ah, g_ah);   cudaGetSymbolAddress((void**)&al, g_al);
    cudaGetSymbolAddress((void**)&x1h, g_x1h); cudaGetSymbolAddress((void**)&x1l, g_x1l);
    cudaGetSymbolAddress((void**)&fh, g_fh);   cudaGetSymbolAddress((void**)&fl, g_fl);
    cudaGetSymbolAddress((void**)&wqh, g_wqh); cudaGetSymbolAddress((void**)&wql, g_wql);
    cudaGetSymbolAddress((void**)&wkh, g_wkh); cudaGetSymbolAddress((void**)&wkl, g_wkl);
    cudaGetSymbolAddress((void**)&wvh, g_wvh); cudaGetSymbolAddress((void**)&wvl, g_wvl);
    cudaGetSymbolAddress((void**)&woh, g_woh); cudaGetSymbolAddress((void**)&wol, g_wol);
    cudaGetSymbolAddress((void**)&w1h, g_w1h); cudaGetSymbolAddress((void**)&w1l, g_w1l);
    cudaGetSymbolAddress((void**)&w2h, g_w2h); cudaGetSymbolAddress((void**)&w2l, g_w2l);

    cudaFuncSetAttribute(hgemm3, cudaFuncAttributeMaxDynamicSharedMemorySize, SMEM_REQ);

    // Pre-pass: split x and weights
    vsplit_kernel<<<MROWS * Dq / 1024, 256>>>(x, xh, xl, MROWS * Dq);
    tsplit_kernel<<<dim3(Dq/32, Dq/32), 256>>>(wq, wqh, wql, Dq, Dq);
    tsplit_kernel<<<dim3(Dq/32, Dq/32), 256>>>(wk, wkh, wkl, Dq, Dq);
    tsplit_kernel<<<dim3(Dq/32, Dq/32), 256>>>(wv, wvh, wvl, Dq, Dq);
    tsplit_kernel<<<dim3(Dq/32, Dq/32), 256>>>(wo, woh, wol, Dq, Dq);
    tsplit_kernel<<<dim3(DFFq/32, Dq/32), 256>>>(w1, w1h, w1l, Dq, DFFq);
    tsplit_kernel<<<dim3(Dq/32, DFFq/32), 256>>>(w2, w2h, w2l, DFFq, Dq);

    const dim3 gD(Dq / BN, MROWS / BM);    // (8, 64)
    const dim3 gF(DFFq / BN, MROWS / BM);  // (32, 64)

    hgemm3<<<gD, 256, SMEM_REQ>>>(xh, xl, wqh, wql, bq, q, nullptr, nullptr, MROWS, Dq, Dq, 0);
    hgemm3<<<gD, 256, SMEM_REQ>>>(xh, xl, wkh, wkl, bk, k, nullptr, nullptr, MROWS, Dq, Dq, 0);
    hgemm3<<<gD, 256, SMEM_REQ>>>(xh, xl, wvh, wvl, bv, v, nullptr, nullptr, MROWS, Dq, Dq, 0);

    attention_kernel<<<dim3(Sq/128, Hq, Bq), 128>>>(q, k, v, mask, ah, al);

    hgemm3<<<gD, 256, SMEM_REQ>>>(ah, al, woh, wol, bo, tmp, nullptr, nullptr, MROWS, Dq, Dq, 0);
    residual_ln<<<MROWS, 256>>>(x, tmp, l1a, l1b, x1, x1h, x1l);

    hgemm3<<<gF, 256, SMEM_REQ>>>(x1h, x1l, w1h, w1l, b1, nullptr, fh, fl, MROWS, DFFq, Dq, 1);
    hgemm3<<<gD, 256, SMEM_REQ>>>(fh, fl, w2h, w2l, b2, tmp, nullptr, nullptr, MROWS, Dq, DFFq, 0);
    residual_ln<<<MROWS, 256>>>(x1, tmp, l2a, l2b, out, nullptr, nullptr);
}

// round 8
// speedup vs baseline: 4.1868x; 1.6906x over previous
#include <cuda_runtime.h>
#include <cuda_fp16.h>
#include <math.h>
#include <stdint.h>

#define Bq   8
#define Sq   1024
#define Dq   1024
#define Hq   16
#define DKq  64
#define DFFq 4096
#define MROWS (Bq * Sq)

typedef __half h16;

// ---------------- scratch ----------------
__device__ float g_tmp[MROWS * Dq];
__device__ float g_x1 [MROWS * Dq];
__device__ h16 g_qh [MROWS * Dq], g_kh [MROWS * Dq], g_vh [MROWS * Dq];
__device__ h16 g_xh [MROWS * Dq],  g_xl [MROWS * Dq];
__device__ h16 g_ah [MROWS * Dq],  g_al [MROWS * Dq];
__device__ h16 g_x1h[MROWS * Dq],  g_x1l[MROWS * Dq];
__device__ h16 g_fh [MROWS * DFFq], g_fl[MROWS * DFFq];
__device__ h16 g_wqh[Dq * Dq],  g_wql[Dq * Dq];
__device__ h16 g_wkh[Dq * Dq],  g_wkl[Dq * Dq];
__device__ h16 g_wvh[Dq * Dq],  g_wvl[Dq * Dq];
__device__ h16 g_woh[Dq * Dq],  g_wol[Dq * Dq];
__device__ h16 g_w1h[Dq * DFFq], g_w1l[Dq * DFFq];
__device__ h16 g_w2h[DFFq * Dq], g_w2l[DFFq * Dq];

// ---------------- helpers ----------------
__device__ __forceinline__ uint32_t smem_u32(const void* p) {
    uint32_t a;
    asm("{ .reg .u64 t; cvta.to.shared.u64 t, %1; cvt.u32.u64 %0, t; }" : "=r"(a) : "l"(p));
    return a;
}
__device__ __forceinline__ void cpa16(uint32_t s, const void* g) {
    asm volatile("cp.async.cg.shared.global [%0], [%1], 16;" :: "r"(s), "l"(g));
}
#define CP_COMMIT() asm volatile("cp.async.commit_group;" ::: "memory")
#define CP_WAIT1()  asm volatile("cp.async.wait_group 1;" ::: "memory")
#define CP_WAIT0()  asm volatile("cp.async.wait_group 0;" ::: "memory")
#define LDMX4(r0,r1,r2,r3,addr)                                               \
    asm volatile("ldmatrix.sync.aligned.m8n8.x4.shared.b16 {%0,%1,%2,%3},[%4];" \
        : "=r"(r0), "=r"(r1), "=r"(r2), "=r"(r3) : "r"(addr))
#define LDMX4T(r0,r1,r2,r3,addr)                                              \
    asm volatile("ldmatrix.sync.aligned.m8n8.x4.trans.shared.b16 {%0,%1,%2,%3},[%4];" \
        : "=r"(r0), "=r"(r1), "=r"(r2), "=r"(r3) : "r"(addr))
#define HMMA(d,a,b)                                                           \
    asm volatile("mma.sync.aligned.m16n8k16.row.col.f32.f16.f16.f32 "         \
        "{%0,%1,%2,%3},{%4,%5,%6,%7},{%8,%9},{%0,%1,%2,%3};"                  \
        : "+f"((d)[0]), "+f"((d)[1]), "+f"((d)[2]), "+f"((d)[3])              \
        : "r"((a)[0]), "r"((a)[1]), "r"((a)[2]), "r"((a)[3]),                 \
          "r"((b)[0]), "r"((b)[1]))

__device__ __forceinline__ void hsplit(float x, h16& h, h16& l) {
    h = __float2half_rn(x);
    l = __float2half_rn(x - __half2float(h));
}

// ---------------- fp16 2-limb (3-term) HMMA GEMM ----------------
#define BM 128
#define BN 128
#define BK 64
#define OFF_AH 0
#define OFF_AL 16384
#define OFF_BH 32768
#define OFF_BL 49152
#define BUFB   65536
#define SMEM_REQ (2 * BUFB)

__global__ __launch_bounds__(256, 1) void hgemm3(
    const h16* __restrict__ Ahb, const h16* __restrict__ Alb,
    const h16* __restrict__ Bhb, const h16* __restrict__ Blb,
    const float* __restrict__ bias, float* __restrict__ C,
    h16* __restrict__ Ch, h16* __restrict__ Cl,
    int M, int N, int K, int doRelu)
{
    extern __shared__ char smem[];
    const uint32_t sb = smem_u32(smem);
    const int tid  = threadIdx.x;
    const int warp = tid >> 5, lane = tid & 31;
    const int bm = blockIdx.y * BM, bn = blockIdx.x * BN;
    const int m0w = (warp & 1) * 64, n0w = (warp >> 1) * 32;

    const int rL = tid >> 3, cL = tid & 7;
    const uint32_t sRowOff = (uint32_t)rL * 128 + (((uint32_t)(cL ^ (rL & 7))) << 4);
    const h16* gAh = Ahb + (size_t)(bm + rL) * K + cL * 8;
    const h16* gAl = Alb + (size_t)(bm + rL) * K + cL * 8;
    const h16* gBh = Bhb + (size_t)(bn + rL) * K + cL * 8;
    const h16* gBl = Blb + (size_t)(bn + rL) * K + cL * 8;
    const size_t rstep = (size_t)32 * K;

    float acc[4][4][4];
#pragma unroll
    for (int i = 0; i < 4; i++)
#pragma unroll
        for (int j = 0; j < 4; j++)
#pragma unroll
            for (int r = 0; r < 4; r++) acc[i][j][r] = 0.f;

    const int arow0 = m0w + (lane & 15);
    const int akc   = lane >> 4;
    const int brow0 = n0w + ((lane >> 4) << 3) + (lane & 7);
    const int bkc   = (lane >> 3) & 1;

    auto LOAD = [&](int c, int buf) {
        const uint32_t s = sb + (uint32_t)buf * BUFB;
        const size_t k0 = (size_t)c * BK;
#pragma unroll
        for (int i = 0; i < 4; i++) {
            const uint32_t so = sRowOff + (uint32_t)i * 4096;
            const size_t go = (size_t)i * rstep + k0;
            cpa16(s + OFF_AH + so, gAh + go);
            cpa16(s + OFF_AL + so, gAl + go);
            cpa16(s + OFF_BH + so, gBh + go);
            cpa16(s + OFF_BL + so, gBl + go);
        }
    };

    auto COMPUTE = [&](int buf) {
        const uint32_t s = sb + (uint32_t)buf * BUFB;
#pragma unroll
        for (int ks = 0; ks < 4; ks++) {
            uint32_t bh[4][2], bl[4][2];
#pragma unroll
            for (int bt = 0; bt < 2; bt++) {
                const int row = brow0 + bt * 16;
                const int kc  = ks * 2 + bkc;
                const uint32_t off = (uint32_t)row * 128 + (((uint32_t)(kc ^ (row & 7))) << 4);
                LDMX4(bh[2*bt][0], bh[2*bt][1], bh[2*bt+1][0], bh[2*bt+1][1], s + OFF_BH + off);
                LDMX4(bl[2*bt][0], bl[2*bt][1], bl[2*bt+1][0], bl[2*bt+1][1], s + OFF_BL + off);
            }
#pragma unroll
            for (int mt = 0; mt < 4; mt++) {
                const int row = arow0 + mt * 16;
                const int kc  = ks * 2 + akc;
                const uint32_t off = (uint32_t)row * 128 + (((uint32_t)(kc ^ (row & 7))) << 4);
                uint32_t a[4];
                LDMX4(a[0], a[1], a[2], a[3], s + OFF_AH + off);
#pragma unroll
                for (int nt = 0; nt < 4; nt++) HMMA(acc[mt][nt], a, bh[nt]);
#pragma unroll
                for (int nt = 0; nt < 4; nt++) HMMA(acc[mt][nt], a, bl[nt]);
                LDMX4(a[0], a[1], a[2], a[3], s + OFF_AL + off);
#pragma unroll
                for (int nt = 0; nt < 4; nt++) HMMA(acc[mt][nt], a, bh[nt]);
            }
        }
    };

    const int chunks = K / BK;
    LOAD(0, 0);
    CP_COMMIT();
#pragma unroll 1
    for (int c = 0; c < chunks; c++) {
        if (c + 1 < chunks) {
            LOAD(c + 1, (c + 1) & 1);
            CP_COMMIT();
            CP_WAIT1();
        } else {
            CP_WAIT0();
        }
        __syncthreads();
        COMPUTE(c & 1);
        __syncthreads();
    }

#pragma unroll
    for (int mt = 0; mt < 4; mt++) {
        const int mr = bm + m0w + mt * 16 + (lane >> 2);
#pragma unroll
        for (int nt = 0; nt < 4; nt++) {
            const int col = bn + n0w + nt * 8 + 2 * (lane & 3);
            const float b0 = bias[col], b1 = bias[col + 1];
            float v0 = acc[mt][nt][0] + b0, v1 = acc[mt][nt][1] + b1;
            float v2 = acc[mt][nt][2] + b0, v3 = acc[mt][nt][3] + b1;
            if (doRelu) {
                v0 = fmaxf(v0, 0.f); v1 = fmaxf(v1, 0.f);
                v2 = fmaxf(v2, 0.f); v3 = fmaxf(v3, 0.f);
            }
            if (C) {
                *(float2*)(C + (size_t)mr * N + col)       = make_float2(v0, v1);
                *(float2*)(C + (size_t)(mr + 8) * N + col) = make_float2(v2, v3);
            }
            if (Ch) {
                if (Cl) {
                    h16 h0, l0, h1, l1;
                    hsplit(v0, h0, l0); hsplit(v1, h1, l1);
                    *(__half2*)(Ch + (size_t)mr * N + col) = __halves2half2(h0, h1);
                    *(__half2*)(Cl + (size_t)mr * N + col) = __halves2half2(l0, l1);
                    hsplit(v2, h0, l0); hsplit(v3, h1, l1);
                    *(__half2*)(Ch + (size_t)(mr + 8) * N + col) = __halves2half2(h0, h1);
                    *(__half2*)(Cl + (size_t)(mr + 8) * N + col) = __halves2half2(l0, l1);
                } else {
                    *(__half2*)(Ch + (size_t)mr * N + col)       = __floats2half2_rn(v0, v1);
                    *(__half2*)(Ch + (size_t)(mr + 8) * N + col) = __floats2half2_rn(v2, v3);
                }
            }
        }
    }
}

// ---------------- pre-pass kernels ----------------
__global__ __launch_bounds__(256) void vsplit_kernel(
    const float* __restrict__ s, h16* __restrict__ h, h16* __restrict__ l, int n)
{
    int i = (blockIdx.x * 256 + threadIdx.x) * 4;
    if (i >= n) return;
    float4 v = *(const float4*)(s + i);
    h16 h0,l0,h1,l1,h2,l2,h3,l3;
    hsplit(v.x,h0,l0); hsplit(v.y,h1,l1); hsplit(v.z,h2,l2); hsplit(v.w,h3,l3);
    *(__half2*)(h+i)   = __halves2half2(h0,h1);
    *(__half2*)(h+i+2) = __halves2half2(h2,h3);
    *(__half2*)(l+i)   = __halves2half2(l0,l1);
    *(__half2*)(l+i+2) = __halves2half2(l2,l3);
}

__global__ __launch_bounds__(256) void tsplit_kernel(
    const float* __restrict__ W, h16* __restrict__ Th, h16* __restrict__ Tl,
    int K, int N)
{
    __shared__ float t[32][33];
    const int n0 = blockIdx.x * 32, k0 = blockIdx.y * 32;
    const int tx = threadIdx.x & 31, ty = threadIdx.x >> 5;
#pragma unroll
    for (int i = ty; i < 32; i += 8)
        t[i][tx] = W[(size_t)(k0 + i) * N + n0 + tx];
    __syncthreads();
#pragma unroll
    for (int i = ty; i < 32; i += 8) {
        h16 h, l;
        hsplit(t[tx][i], h, l);
        Th[(size_t)(n0 + i) * K + k0 + tx] = h;
        Tl[(size_t)(n0 + i) * K + k0 + tx] = l;
    }
}

// ---------------- HMMA flash attention ----------------
// grid (Sq/64, Hq, Bq), 128 threads (4 warps); warp owns 16 q-rows.
// KV loop kept at unroll 1 to bound code size / ptxas time.
__global__ __launch_bounds__(128) void attention_hmma(
    const h16* __restrict__ Qg, const h16* __restrict__ Kg,
    const h16* __restrict__ Vg, const int* __restrict__ mask,
    h16* __restrict__ OH, h16* __restrict__ OL)
{
    __shared__ h16 Qs[64 * 64];
    __shared__ h16 Ks[64 * 64];
    __shared__ h16 Vs[64 * 64];
    __shared__ int ms[64];

    const int b = blockIdx.z, h = blockIdx.y, qt = blockIdx.x;
    const int tid = threadIdx.x, warp = tid >> 5, lane = tid & 31;
    const uint32_t qsb = smem_u32(Qs), ksb = smem_u32(Ks), vsb = smem_u32(Vs);

    const int lr = tid >> 1, lc0 = (tid & 1) * 4;
    const h16* qg = Qg + (size_t)(b * Sq + qt * 64 + lr) * Dq + h * 64;
    const h16* kgb = Kg + (size_t)(b * Sq + lr) * Dq + h * 64;
    const h16* vgb = Vg + (size_t)(b * Sq + lr) * Dq + h * 64;

#pragma unroll
    for (int c = 0; c < 4; c++) {
        const int ch = lc0 + c;
        const uint32_t sw = (uint32_t)lr * 128 + (((uint32_t)(ch ^ (lr & 7))) << 4);
        cpa16(qsb + sw, qg + ch * 8);
        cpa16(ksb + sw, kgb + ch * 8);
        cpa16(vsb + sw, vgb + ch * 8);
    }
    if (tid < 64) ms[tid] = mask[b * Sq + tid];
    CP_COMMIT();
    CP_WAIT0();
    __syncthreads();

    uint32_t qf[4][4];
    {
        const int row = warp * 16 + (lane & 15);
        const int kb = lane >> 4;
#pragma unroll
        for (int kf = 0; kf < 4; kf++) {
            const int kc = kf * 2 + kb;
            const uint32_t off = (uint32_t)row * 128 + (((uint32_t)(kc ^ (row & 7))) << 4);
            LDMX4(qf[kf][0], qf[kf][1], qf[kf][2], qf[kf][3], qsb + off);
        }
    }

    float oacc[8][4];
#pragma unroll
    for (int t = 0; t < 8; t++)
#pragma unroll
        for (int r = 0; r < 4; r++) oacc[t][r] = 0.f;
    float lsum0 = 0.f, lsum1 = 0.f;

    const int sb_row = ((lane >> 4) << 3) + (lane & 7);
    const int sb_kc  = (lane >> 3) & 1;
    const int vrow   = ((lane >> 3) & 1) * 8 + (lane & 7);
    const int vchb   = lane >> 4;
    const int mcol   = 2 * (lane & 3);

#pragma unroll 1
    for (int c = 0; c < 16; c++) {
        float sacc[8][4];
#pragma unroll
        for (int t = 0; t < 8; t++)
#pragma unroll
            for (int r = 0; r < 4; r++) sacc[t][r] = 0.f;
#pragma unroll
        for (int jt = 0; jt < 4; jt++) {
            const int row = jt * 16 + sb_row;
#pragma unroll
            for (int kf = 0; kf < 4; kf++) {
                const int kc = kf * 2 + sb_kc;
                const uint32_t off = (uint32_t)row * 128 + (((uint32_t)(kc ^ (row & 7))) << 4);
                uint32_t bb[4];
                LDMX4(bb[0], bb[1], bb[2], bb[3], ksb + off);
                HMMA(sacc[2*jt],   qf[kf], (bb));
                HMMA(sacc[2*jt+1], qf[kf], (bb + 2));
            }
        }

        uint32_t pf[4][4];
#pragma unroll
        for (int t = 0; t < 8; t++) {
            const int col = t * 8 + mcol;
            const int m0 = ms[col], m1 = ms[col + 1];
            float p0 = m0 ? __expf(0.125f * sacc[t][0]) : 0.f;
            float p1 = m1 ? __expf(0.125f * sacc[t][1]) : 0.f;
            float p2 = m0 ? __expf(0.125f * sacc[t][2]) : 0.f;
            float p3 = m1 ? __expf(0.125f * sacc[t][3]) : 0.f;
            lsum0 += p0 + p1;
            lsum1 += p2 + p3;
            __half2 a01 = __floats2half2_rn(p0, p1);
            __half2 a23 = __floats2half2_rn(p2, p3);
            pf[t >> 1][(t & 1) * 2 + 0] = *(uint32_t*)&a01;
            pf[t >> 1][(t & 1) * 2 + 1] = *(uint32_t*)&a23;
        }

#pragma unroll
        for (int np = 0; np < 4; np++) {
            const int chunk = np * 2 + vchb;
#pragma unroll
            for (int kt = 0; kt < 4; kt++) {
                const int r = kt * 16 + vrow;
                const uint32_t off = (uint32_t)r * 128 + (((uint32_t)(chunk ^ (r & 7))) << 4);
                uint32_t vb[4];
                LDMX4T(vb[0], vb[1], vb[2], vb[3], vsb + off);
                HMMA(oacc[2*np],   pf[kt], (vb));
                HMMA(oacc[2*np+1], pf[kt], (vb + 2));
            }
        }

        if (c < 15) {
            __syncthreads();
            const size_t gofs = (size_t)(c + 1) * 64 * Dq;
#pragma unroll
            for (int cc = 0; cc < 4; cc++) {
                const int ch = lc0 + cc;
                const uint32_t sw = (uint32_t)lr * 128 + (((uint32_t)(ch ^ (lr & 7))) << 4);
                cpa16(ksb + sw, kgb + gofs + ch * 8);
                cpa16(vsb + sw, vgb + gofs + ch * 8);
            }
            if (tid < 64) ms[tid] = mask[b * Sq + (c + 1) * 64 + tid];
            CP_COMMIT();
            CP_WAIT0();
            __syncthreads();
        }
    }

    lsum0 += __shfl_xor_sync(0xffffffffu, lsum0, 1);
    lsum0 += __shfl_xor_sync(0xffffffffu, lsum0, 2);
    lsum1 += __shfl_xor_sync(0xffffffffu, lsum1, 1);
    lsum1 += __shfl_xor_sync(0xffffffffu, lsum1, 2);
    const float inv0 = 1.f / lsum0, inv1 = 1.f / lsum1;

    const int qr0 = qt * 64 + warp * 16 + (lane >> 2);
    const size_t gr0 = (size_t)(b * Sq + qr0) * Dq;
    const size_t gr1 = gr0 + (size_t)8 * Dq;
#pragma unroll
    for (int t = 0; t < 8; t++) {
        const int col = h * 64 + t * 8 + mcol;
        float v0 = oacc[t][0] * inv0, v1 = oacc[t][1] * inv0;
        float v2 = oacc[t][2] * inv1, v3 = oacc[t][3] * inv1;
        h16 h0, l0, h1, l1;
        hsplit(v0, h0, l0); hsplit(v1, h1, l1);
        *(__half2*)(OH + gr0 + col) = __halves2half2(h0, h1);
        *(__half2*)(OL + gr0 + col) = __halves2half2(l0, l1);
        hsplit(v2, h0, l0); hsplit(v3, h1, l1);
        *(__half2*)(OH + gr1 + col) = __halves2half2(h0, h1);
        *(__half2*)(OL + gr1 + col) = __halves2half2(l0, l1);
    }
}

// ---------------- residual + LayerNorm (opt split out) ----------------
__global__ __launch_bounds__(256) void residual_ln(
    const float* __restrict__ X, const float* __restrict__ Y,
    const float* __restrict__ Aw, const float* __restrict__ Bw,
    float* __restrict__ out, h16* __restrict__ oh, h16* __restrict__ ol)
{
    const int row = blockIdx.x, tid = threadIdx.x;
    const size_t base = (size_t)row * Dq + tid * 4;
    float4 xv = *(const float4*)(X + base);
    float4 yv = *(const float4*)(Y + base);
    float4 v = make_float4(xv.x+yv.x, xv.y+yv.y, xv.z+yv.z, xv.w+yv.w);

    float s = v.x+v.y+v.z+v.w;
    float ss = v.x*v.x+v.y*v.y+v.z*v.z+v.w*v.w;
#pragma unroll
    for (int o = 16; o > 0; o >>= 1) {
        s  += __shfl_xor_sync(0xffffffffu, s, o);
        ss += __shfl_xor_sync(0xffffffffu, ss, o);
    }
    __shared__ float rs[8], rss[8];
    const int w = tid >> 5, lane = tid & 31;
    if (lane == 0) { rs[w] = s; rss[w] = ss; }
    __syncthreads();
    if (tid == 0) {
        float S = 0.f, SS = 0.f;
#pragma unroll
        for (int i = 0; i < 8; i++) { S += rs[i]; SS += rss[i]; }
        rs[0] = S; rss[0] = SS;
    }
    __syncthreads();
    const float mean = rs[0] * (1.f / Dq);
    const float var  = rss[0] * (1.f / Dq) - mean * mean;
    const float rstd = rsqrtf(var + 1e-6f);

    float4 a4 = *(const float4*)(Aw + tid * 4);
    float4 b4 = *(const float4*)(Bw + tid * 4);
    float4 o4;
    o4.x = a4.x * (v.x - mean) * rstd + b4.x;
    o4.y = a4.y * (v.y - mean) * rstd + b4.y;
    o4.z = a4.z * (v.z - mean) * rstd + b4.z;
    o4.w = a4.w * (v.w - mean) * rstd + b4.w;
    *(float4*)(out + base) = o4;
    if (oh) {
        h16 h0,l0,h1,l1,h2,l2,h3,l3;
        hsplit(o4.x,h0,l0); hsplit(o4.y,h1,l1); hsplit(o4.z,h2,l2); hsplit(o4.w,h3,l3);
        *(__half2*)(oh+base)   = __halves2half2(h0,h1);
        *(__half2*)(oh+base+2) = __halves2half2(h2,h3);
        *(__half2*)(ol+base)   = __halves2half2(l0,l1);
        *(__half2*)(ol+base+2) = __halves2half2(l2,l3);
    }
}

// ---------------- kernel_launch ----------------
extern "C" void kernel_launch(void* const* d_in, const int* in_sizes, int n_in,
                              void* d_out, int out_size)
{
    const float* x   = (const float*)d_in[0];
    const int* mask  = (const int*)d_in[1];
    const float* wq  = (const float*)d_in[2];
    const float* bq  = (const float*)d_in[3];
    const float* wk  = (const float*)d_in[4];
    const float* bk  = (const float*)d_in[5];
    const float* wv  = (const float*)d_in[6];
    const float* bv  = (const float*)d_in[7];
    const float* wo  = (const float*)d_in[8];
    const float* bo  = (const float*)d_in[9];
    const float* l1a = (const float*)d_in[10];
    const float* l1b = (const float*)d_in[11];
    const float* l2a = (const float*)d_in[12];
    const float* l2b = (const float*)d_in[13];
    const float* w1  = (const float*)d_in[14];
    const float* b1  = (const float*)d_in[15];
    const float* w2  = (const float*)d_in[16];
    const float* b2  = (const float*)d_in[17];
    float* out = (float*)d_out;

    float *tmp, *x1;
    h16 *qh,*kh,*vh,*xh,*xl,*ah,*al,*x1h,*x1l,*fh,*fl;
    h16 *wqh,*wql,*wkh,*wkl,*wvh,*wvl,*woh,*wol,*w1h,*w1l,*w2h,*w2l;
    cudaGetSymbolAddress((void**)&tmp, g_tmp);
    cudaGetSymbolAddress((void**)&x1, g_x1);
    cudaGetSymbolAddress((void**)&qh, g_qh);
    cudaGetSymbolAddress((void**)&kh, g_kh);
    cudaGetSymbolAddress((void**)&vh, g_vh);
    cudaGetSymbolAddress((void**)&xh, g_xh);   cudaGetSymbolAddress((void**)&xl, g_xl);
    cudaGetSymbolAddress((void**)&ah, g_ah);   cudaGetSymbolAddress((void**)&al, g_al);
    cudaGetSymbolAddress((void**)&x1h, g_x1h); cudaGetSymbolAddress((void**)&x1l, g_x1l);
    cudaGetSymbolAddress((void**)&fh, g_fh);   cudaGetSymbolAddress((void**)&fl, g_fl);
    cudaGetSymbolAddress((void**)&wqh, g_wqh); cudaGetSymbolAddress((void**)&wql, g_wql);
    cudaGetSymbolAddress((void**)&wkh, g_wkh); cudaGetSymbolAddress((void**)&wkl, g_wkl);
    cudaGetSymbolAddress((void**)&wvh, g_wvh); cudaGetSymbolAddress((void**)&wvl, g_wvl);
    cudaGetSymbolAddress((void**)&woh, g_woh); cudaGetSymbolAddress((void**)&wol, g_wol);
    cudaGetSymbolAddress((void**)&w1h, g_w1h); cudaGetSymbolAddress((void**)&w1l, g_w1l);
    cudaGetSymbolAddress((void**)&w2h, g_w2h); cudaGetSymbolAddress((void**)&w2l, g_w2l);

    cudaFuncSetAttribute(hgemm3, cudaFuncAttributeMaxDynamicSharedMemorySize, SMEM_REQ);

    vsplit_kernel<<<MROWS * Dq / 1024, 256>>>(x, xh, xl, MROWS * Dq);
    tsplit_kernel<<<dim3(Dq/32, Dq/32), 256>>>(wq, wqh, wql, Dq, Dq);
    tsplit_kernel<<<dim3(Dq/32, Dq/32), 256>>>(wk, wkh, wkl, Dq, Dq);
    tsplit_kernel<<<dim3(Dq/32, Dq/32), 256>>>(wv, wvh, wvl, Dq, Dq);
    tsplit_kernel<<<dim3(Dq/32, Dq/32), 256>>>(wo, woh, wol, Dq, Dq);
    tsplit_kernel<<<dim3(DFFq/32, Dq/32), 256>>>(w1, w1h, w1l, Dq, DFFq);
    tsplit_kernel<<<dim3(Dq/32, DFFq/32), 256>>>(w2, w2h, w2l, DFFq, Dq);

    const dim3 gD(Dq / BN, MROWS / BM);
    const dim3 gF(DFFq / BN, MROWS / BM);

    hgemm3<<<gD, 256, SMEM_REQ>>>(xh, xl, wqh, wql, bq, nullptr, qh, nullptr, MROWS, Dq, Dq, 0);
    hgemm3<<<gD, 256, SMEM_REQ>>>(xh, xl, wkh, wkl, bk, nullptr, kh, nullptr, MROWS, Dq, Dq, 0);
    hgemm3<<<gD, 256, SMEM_REQ>>>(xh, xl, wvh, wvl, bv, nullptr, vh, nullptr, MROWS, Dq, Dq, 0);

    attention_hmma<<<dim3(Sq/64, Hq, Bq), 128>>>(qh, kh, vh, mask, ah, al);

    hgemm3<<<gD, 256, SMEM_REQ>>>(ah, al, woh, wol, bo, tmp, nullptr, nullptr, MROWS, Dq, Dq, 0);
    residual_ln<<<MROWS, 256>>>(x, tmp, l1a, l1b, x1, x1h, x1l);

    hgemm3<<<gF, 256, SMEM_REQ>>>(x1h, x1l, w1h, w1l, b1, nullptr, fh, fl, MROWS, DFFq, Dq, 1);
    hgemm3<<<gD, 256, SMEM_REQ>>>(fh, fl, w2h, w2l, b2, tmp, nullptr, nullptr, MROWS, Dq, DFFq, 0);
    residual_ln<<<MROWS, 256>>>(x1, tmp, l2a, l2b, out, nullptr, nullptr);
}

// round 9
// speedup vs baseline: 5.5435x; 1.3240x over previous
#include <cuda_runtime.h>
#include <cuda_fp16.h>
#include <math.h>
#include <stdint.h>

#define Bq   8
#define Sq   1024
#define Dq   1024
#define Hq   16
#define DKq  64
#define DFFq 4096
#define MROWS (Bq * Sq)

typedef __half h16;

// ---------------- scratch ----------------
__device__ float g_tmp[MROWS * Dq];
__device__ float g_x1 [MROWS * Dq];
__device__ h16 g_qh [MROWS * Dq], g_kh [MROWS * Dq], g_vh [MROWS * Dq];
__device__ h16 g_xh [MROWS * Dq];
__device__ h16 g_ah [MROWS * Dq],  g_al [MROWS * Dq];
__device__ h16 g_x1h[MROWS * Dq],  g_x1l[MROWS * Dq];
__device__ h16 g_fh [MROWS * DFFq], g_fl[MROWS * DFFq];
__device__ h16 g_wqh[Dq * Dq];
__device__ h16 g_wkh[Dq * Dq];
__device__ h16 g_wvh[Dq * Dq];
__device__ h16 g_woh[Dq * Dq];
__device__ h16 g_w1h[Dq * DFFq];
__device__ h16 g_w2h[DFFq * Dq];

// ---------------- helpers ----------------
__device__ __forceinline__ uint32_t smem_u32(const void* p) {
    uint32_t a;
    asm("{ .reg .u64 t; cvta.to.shared.u64 t, %1; cvt.u32.u64 %0, t; }" : "=r"(a) : "l"(p));
    return a;
}
__device__ __forceinline__ void cpa16(uint32_t s, const void* g) {
    asm volatile("cp.async.cg.shared.global [%0], [%1], 16;" :: "r"(s), "l"(g));
}
#define CP_COMMIT() asm volatile("cp.async.commit_group;" ::: "memory")
#define CP_WAIT1()  asm volatile("cp.async.wait_group 1;" ::: "memory")
#define CP_WAIT0()  asm volatile("cp.async.wait_group 0;" ::: "memory")
#define LDMX4(r0,r1,r2,r3,addr)                                               \
    asm volatile("ldmatrix.sync.aligned.m8n8.x4.shared.b16 {%0,%1,%2,%3},[%4];" \
        : "=r"(r0), "=r"(r1), "=r"(r2), "=r"(r3) : "r"(addr))
#define LDMX4T(r0,r1,r2,r3,addr)                                              \
    asm volatile("ldmatrix.sync.aligned.m8n8.x4.trans.shared.b16 {%0,%1,%2,%3},[%4];" \
        : "=r"(r0), "=r"(r1), "=r"(r2), "=r"(r3) : "r"(addr))
#define HMMA(d,a,b)                                                           \
    asm volatile("mma.sync.aligned.m16n8k16.row.col.f32.f16.f16.f32 "         \
        "{%0,%1,%2,%3},{%4,%5,%6,%7},{%8,%9},{%0,%1,%2,%3};"                  \
        : "+f"((d)[0]), "+f"((d)[1]), "+f"((d)[2]), "+f"((d)[3])              \
        : "r"((a)[0]), "r"((a)[1]), "r"((a)[2]), "r"((a)[3]),                 \
          "r"((b)[0]), "r"((b)[1]))

__device__ __forceinline__ void hsplit(float x, h16& h, h16& l) {
    h = __float2half_rn(x);
    l = __float2half_rn(x - __half2float(h));
}

// ---------------- fp16 HMMA GEMM: C = (Ah [+ Al]) @ Bh^T + bias ------------
// Alb == nullptr -> 1-term (A = Ah). Else 2-term (A = Ah + Al exactly).
// Weights pre-rounded to fp16 (Bh only). BM=BN=128, BK=64, 256 threads.
#define BM 128
#define BN 128
#define BK 64
#define OFF_AH 0
#define OFF_AL 16384
#define OFF_BH 32768
#define BUFB   49152
#define SMEM_REQ (2 * BUFB)            // 98304

__global__ __launch_bounds__(256, 1) void hgemm(
    const h16* __restrict__ Ahb, const h16* __restrict__ Alb,
    const h16* __restrict__ Bhb,
    const float* __restrict__ bias, float* __restrict__ C,
    h16* __restrict__ Ch, h16* __restrict__ Cl,
    int M, int N, int K, int doRelu)
{
    extern __shared__ char smem[];
    const uint32_t sb = smem_u32(smem);
    const int tid  = threadIdx.x;
    const int warp = tid >> 5, lane = tid & 31;
    const int bm = blockIdx.y * BM, bn = blockIdx.x * BN;
    const int m0w = (warp & 1) * 64, n0w = (warp >> 1) * 32;
    const bool twoTerm = (Alb != nullptr);

    const int rL = tid >> 3, cL = tid & 7;
    const uint32_t sRowOff = (uint32_t)rL * 128 + (((uint32_t)(cL ^ (rL & 7))) << 4);
    const h16* gAh = Ahb + (size_t)(bm + rL) * K + cL * 8;
    const h16* gAl = twoTerm ? (Alb + (size_t)(bm + rL) * K + cL * 8) : nullptr;
    const h16* gBh = Bhb + (size_t)(bn + rL) * K + cL * 8;
    const size_t rstep = (size_t)32 * K;

    float acc[4][4][4];
#pragma unroll
    for (int i = 0; i < 4; i++)
#pragma unroll
        for (int j = 0; j < 4; j++)
#pragma unroll
            for (int r = 0; r < 4; r++) acc[i][j][r] = 0.f;

    const int arow0 = m0w + (lane & 15);
    const int akc   = lane >> 4;
    const int brow0 = n0w + ((lane >> 4) << 3) + (lane & 7);
    const int bkc   = (lane >> 3) & 1;

    auto LOAD = [&](int c, int buf) {
        const uint32_t s = sb + (uint32_t)buf * BUFB;
        const size_t k0 = (size_t)c * BK;
#pragma unroll
        for (int i = 0; i < 4; i++) {
            const uint32_t so = sRowOff + (uint32_t)i * 4096;
            const size_t go = (size_t)i * rstep + k0;
            cpa16(s + OFF_AH + so, gAh + go);
            if (twoTerm) cpa16(s + OFF_AL + so, gAl + go);
            cpa16(s + OFF_BH + so, gBh + go);
        }
    };

    auto COMPUTE = [&](int buf) {
        const uint32_t s = sb + (uint32_t)buf * BUFB;
#pragma unroll
        for (int ks = 0; ks < 4; ks++) {
            uint32_t bh[4][2];
#pragma unroll
            for (int bt = 0; bt < 2; bt++) {
                const int row = brow0 + bt * 16;
                const int kc  = ks * 2 + bkc;
                const uint32_t off = (uint32_t)row * 128 + (((uint32_t)(kc ^ (row & 7))) << 4);
                LDMX4(bh[2*bt][0], bh[2*bt][1], bh[2*bt+1][0], bh[2*bt+1][1], s + OFF_BH + off);
            }
#pragma unroll
            for (int mt = 0; mt < 4; mt++) {
                const int row = arow0 + mt * 16;
                const int kc  = ks * 2 + akc;
                const uint32_t off = (uint32_t)row * 128 + (((uint32_t)(kc ^ (row & 7))) << 4);
                uint32_t a[4];
                LDMX4(a[0], a[1], a[2], a[3], s + OFF_AH + off);
#pragma unroll
                for (int nt = 0; nt < 4; nt++) HMMA(acc[mt][nt], a, bh[nt]);
                if (twoTerm) {
                    LDMX4(a[0], a[1], a[2], a[3], s + OFF_AL + off);
#pragma unroll
                    for (int nt = 0; nt < 4; nt++) HMMA(acc[mt][nt], a, bh[nt]);
                }
            }
        }
    };

    const int chunks = K / BK;
    LOAD(0, 0);
    CP_COMMIT();
#pragma unroll 1
    for (int c = 0; c < chunks; c++) {
        if (c + 1 < chunks) {
            LOAD(c + 1, (c + 1) & 1);
            CP_COMMIT();
            CP_WAIT1();
        } else {
            CP_WAIT0();
        }
        __syncthreads();
        COMPUTE(c & 1);
        __syncthreads();
    }

#pragma unroll
    for (int mt = 0; mt < 4; mt++) {
        const int mr = bm + m0w + mt * 16 + (lane >> 2);
#pragma unroll
        for (int nt = 0; nt < 4; nt++) {
            const int col = bn + n0w + nt * 8 + 2 * (lane & 3);
            const float b0 = bias[col], b1 = bias[col + 1];
            float v0 = acc[mt][nt][0] + b0, v1 = acc[mt][nt][1] + b1;
            float v2 = acc[mt][nt][2] + b0, v3 = acc[mt][nt][3] + b1;
            if (doRelu) {
                v0 = fmaxf(v0, 0.f); v1 = fmaxf(v1, 0.f);
                v2 = fmaxf(v2, 0.f); v3 = fmaxf(v3, 0.f);
            }
            if (C) {
                *(float2*)(C + (size_t)mr * N + col)       = make_float2(v0, v1);
                *(float2*)(C + (size_t)(mr + 8) * N + col) = make_float2(v2, v3);
            }
            if (Ch) {
                if (Cl) {
                    h16 h0, l0, h1, l1;
                    hsplit(v0, h0, l0); hsplit(v1, h1, l1);
                    *(__half2*)(Ch + (size_t)mr * N + col) = __halves2half2(h0, h1);
                    *(__half2*)(Cl + (size_t)mr * N + col) = __halves2half2(l0, l1);
                    hsplit(v2, h0, l0); hsplit(v3, h1, l1);
                    *(__half2*)(Ch + (size_t)(mr + 8) * N + col) = __halves2half2(h0, h1);
                    *(__half2*)(Cl + (size_t)(mr + 8) * N + col) = __halves2half2(l0, l1);
                } else {
                    *(__half2*)(Ch + (size_t)mr * N + col)       = __floats2half2_rn(v0, v1);
                    *(__half2*)(Ch + (size_t)(mr + 8) * N + col) = __floats2half2_rn(v2, v3);
                }
            }
        }
    }
}

// ---------------- pre-pass kernels ----------------
__global__ __launch_bounds__(256) void vsplit_kernel(
    const float* __restrict__ s, h16* __restrict__ h, h16* __restrict__ l, int n)
{
    int i = (blockIdx.x * 256 + threadIdx.x) * 4;
    if (i >= n) return;
    float4 v = *(const float4*)(s + i);
    h16 h0,l0,h1,l1,h2,l2,h3,l3;
    hsplit(v.x,h0,l0); hsplit(v.y,h1,l1); hsplit(v.z,h2,l2); hsplit(v.w,h3,l3);
    *(__half2*)(h+i)   = __halves2half2(h0,h1);
    *(__half2*)(h+i+2) = __halves2half2(h2,h3);
    if (l) {
        *(__half2*)(l+i)   = __halves2half2(l0,l1);
        *(__half2*)(l+i+2) = __halves2half2(l2,l3);
    }
}

// transpose + round: W[K,N] fp32 -> Th[N,K] fp16
__global__ __launch_bounds__(256) void ttrans_kernel(
    const float* __restrict__ W, h16* __restrict__ Th, int K, int N)
{
    __shared__ float t[32][33];
    const int n0 = blockIdx.x * 32, k0 = blockIdx.y * 32;
    const int tx = threadIdx.x & 31, ty = threadIdx.x >> 5;
#pragma unroll
    for (int i = ty; i < 32; i += 8)
        t[i][tx] = W[(size_t)(k0 + i) * N + n0 + tx];
    __syncthreads();
#pragma unroll
    for (int i = ty; i < 32; i += 8)
        Th[(size_t)(n0 + i) * K + k0 + tx] = __float2half_rn(t[tx][i]);
}

// ---------------- HMMA flash attention (round-8, unchanged) ----------------
__global__ __launch_bounds__(128) void attention_hmma(
    const h16* __restrict__ Qg, const h16* __restrict__ Kg,
    const h16* __restrict__ Vg, const int* __restrict__ mask,
    h16* __restrict__ OH, h16* __restrict__ OL)
{
    __shared__ h16 Qs[64 * 64];
    __shared__ h16 Ks[64 * 64];
    __shared__ h16 Vs[64 * 64];
    __shared__ int ms[64];

    const int b = blockIdx.z, h = blockIdx.y, qt = blockIdx.x;
    const int tid = threadIdx.x, warp = tid >> 5, lane = tid & 31;
    const uint32_t qsb = smem_u32(Qs), ksb = smem_u32(Ks), vsb = smem_u32(Vs);

    const int lr = tid >> 1, lc0 = (tid & 1) * 4;
    const h16* qg = Qg + (size_t)(b * Sq + qt * 64 + lr) * Dq + h * 64;
    const h16* kgb = Kg + (size_t)(b * Sq + lr) * Dq + h * 64;
    const h16* vgb = Vg + (size_t)(b * Sq + lr) * Dq + h * 64;

#pragma unroll
    for (int c = 0; c < 4; c++) {
        const int ch = lc0 + c;
        const uint32_t sw = (uint32_t)lr * 128 + (((uint32_t)(ch ^ (lr & 7))) << 4);
        cpa16(qsb + sw, qg + ch * 8);
        cpa16(ksb + sw, kgb + ch * 8);
        cpa16(vsb + sw, vgb + ch * 8);
    }
    if (tid < 64) ms[tid] = mask[b * Sq + tid];
    CP_COMMIT();
    CP_WAIT0();
    __syncthreads();

    uint32_t qf[4][4];
    {
        const int row = warp * 16 + (lane & 15);
        const int kb = lane >> 4;
#pragma unroll
        for (int kf = 0; kf < 4; kf++) {
            const int kc = kf * 2 + kb;
            const uint32_t off = (uint32_t)row * 128 + (((uint32_t)(kc ^ (row & 7))) << 4);
            LDMX4(qf[kf][0], qf[kf][1], qf[kf][2], qf[kf][3], qsb + off);
        }
    }

    float oacc[8][4];
#pragma unroll
    for (int t = 0; t < 8; t++)
#pragma unroll
        for (int r = 0; r < 4; r++) oacc[t][r] = 0.f;
    float lsum0 = 0.f, lsum1 = 0.f;

    const int sb_row = ((lane >> 4) << 3) + (lane & 7);
    const int sb_kc  = (lane >> 3) & 1;
    const int vrow   = ((lane >> 3) & 1) * 8 + (lane & 7);
    const int vchb   = lane >> 4;
    const int mcol   = 2 * (lane & 3);

#pragma unroll 1
    for (int c = 0; c < 16; c++) {
        float sacc[8][4];
#pragma unroll
        for (int t = 0; t < 8; t++)
#pragma unroll
            for (int r = 0; r < 4; r++) sacc[t][r] = 0.f;
#pragma unroll
        for (int jt = 0; jt < 4; jt++) {
            const int row = jt * 16 + sb_row;
#pragma unroll
            for (int kf = 0; kf < 4; kf++) {
                const int kc = kf * 2 + sb_kc;
                const uint32_t off = (uint32_t)row * 128 + (((uint32_t)(kc ^ (row & 7))) << 4);
                uint32_t bb[4];
                LDMX4(bb[0], bb[1], bb[2], bb[3], ksb + off);
                HMMA(sacc[2*jt],   qf[kf], (bb));
                HMMA(sacc[2*jt+1], qf[kf], (bb + 2));
            }
        }

        uint32_t pf[4][4];
#pragma unroll
        for (int t = 0; t < 8; t++) {
            const int col = t * 8 + mcol;
            const int m0 = ms[col], m1 = ms[col + 1];
            float p0 = m0 ? __expf(0.125f * sacc[t][0]) : 0.f;
            float p1 = m1 ? __expf(0.125f * sacc[t][1]) : 0.f;
            float p2 = m0 ? __expf(0.125f * sacc[t][2]) : 0.f;
            float p3 = m1 ? __expf(0.125f * sacc[t][3]) : 0.f;
            lsum0 += p0 + p1;
            lsum1 += p2 + p3;
            __half2 a01 = __floats2half2_rn(p0, p1);
            __half2 a23 = __floats2half2_rn(p2, p3);
            pf[t >> 1][(t & 1) * 2 + 0] = *(uint32_t*)&a01;
            pf[t >> 1][(t & 1) * 2 + 1] = *(uint32_t*)&a23;
        }

#pragma unroll
        for (int np = 0; np < 4; np++) {
            const int chunk = np * 2 + vchb;
#pragma unroll
            for (int kt = 0; kt < 4; kt++) {
                const int r = kt * 16 + vrow;
                const uint32_t off = (uint32_t)r * 128 + (((uint32_t)(chunk ^ (r & 7))) << 4);
                uint32_t vb[4];
                LDMX4T(vb[0], vb[1], vb[2], vb[3], vsb + off);
                HMMA(oacc[2*np],   pf[kt], (vb));
                HMMA(oacc[2*np+1], pf[kt], (vb + 2));
            }
        }

        if (c < 15) {
            __syncthreads();
            const size_t gofs = (size_t)(c + 1) * 64 * Dq;
#pragma unroll
            for (int cc = 0; cc < 4; cc++) {
                const int ch = lc0 + cc;
                const uint32_t sw = (uint32_t)lr * 128 + (((uint32_t)(ch ^ (lr & 7))) << 4);
                cpa16(ksb + sw, kgb + gofs + ch * 8);
                cpa16(vsb + sw, vgb + gofs + ch * 8);
            }
            if (tid < 64) ms[tid] = mask[b * Sq + (c + 1) * 64 + tid];
            CP_COMMIT();
            CP_WAIT0();
            __syncthreads();
        }
    }

    lsum0 += __shfl_xor_sync(0xffffffffu, lsum0, 1);
    lsum0 += __shfl_xor_sync(0xffffffffu, lsum0, 2);
    lsum1 += __shfl_xor_sync(0xffffffffu, lsum1, 1);
    lsum1 += __shfl_xor_sync(0xffffffffu, lsum1, 2);
    const float inv0 = 1.f / lsum0, inv1 = 1.f / lsum1;

    const int qr0 = qt * 64 + warp * 16 + (lane >> 2);
    const size_t gr0 = (size_t)(b * Sq + qr0) * Dq;
    const size_t gr1 = gr0 + (size_t)8 * Dq;
#pragma unroll
    for (int t = 0; t < 8; t++) {
        const int col = h * 64 + t * 8 + mcol;
        float v0 = oacc[t][0] * inv0, v1 = oacc[t][1] * inv0;
        float v2 = oacc[t][2] * inv1, v3 = oacc[t][3] * inv1;
        h16 h0, l0, h1, l1;
        hsplit(v0, h0, l0); hsplit(v1, h1, l1);
        *(__half2*)(OH + gr0 + col) = __halves2half2(h0, h1);
        *(__half2*)(OL + gr0 + col) = __halves2half2(l0, l1);
        hsplit(v2, h0, l0); hsplit(v3, h1, l1);
        *(__half2*)(OH + gr1 + col) = __halves2half2(h0, h1);
        *(__half2*)(OL + gr1 + col) = __halves2half2(l0, l1);
    }
}

// ---------------- residual + LayerNorm (opt split out) ----------------
__global__ __launch_bounds__(256) void residual_ln(
    const float* __restrict__ X, const float* __restrict__ Y,
    const float* __restrict__ Aw, const float* __restrict__ Bw,
    float* __restrict__ out, h16* __restrict__ oh, h16* __restrict__ ol)
{
    const int row = blockIdx.x, tid = threadIdx.x;
    const size_t base = (size_t)row * Dq + tid * 4;
    float4 xv = *(const float4*)(X + base);
    float4 yv = *(const float4*)(Y + base);
    float4 v = make_float4(xv.x+yv.x, xv.y+yv.y, xv.z+yv.z, xv.w+yv.w);

    float s = v.x+v.y+v.z+v.w;
    float ss = v.x*v.x+v.y*v.y+v.z*v.z+v.w*v.w;
#pragma unroll
    for (int o = 16; o > 0; o >>= 1) {
        s  += __shfl_xor_sync(0xffffffffu, s, o);
        ss += __shfl_xor_sync(0xffffffffu, ss, o);
    }
    __shared__ float rs[8], rss[8];
    const int w = tid >> 5, lane = tid & 31;
    if (lane == 0) { rs[w] = s; rss[w] = ss; }
    __syncthreads();
    if (tid == 0) {
        float S = 0.f, SS = 0.f;
#pragma unroll
        for (int i = 0; i < 8; i++) { S += rs[i]; SS += rss[i]; }
        rs[0] = S; rss[0] = SS;
    }
    __syncthreads();
    const float mean = rs[0] * (1.f / Dq);
    const float var  = rss[0] * (1.f / Dq) - mean * mean;
    const float rstd = rsqrtf(var + 1e-6f);

    float4 a4 = *(const float4*)(Aw + tid * 4);
    float4 b4 = *(const float4*)(Bw + tid * 4);
    float4 o4;
    o4.x = a4.x * (v.x - mean) * rstd + b4.x;
    o4.y = a4.y * (v.y - mean) * rstd + b4.y;
    o4.z = a4.z * (v.z - mean) * rstd + b4.z;
    o4.w = a4.w * (v.w - mean) * rstd + b4.w;
    *(float4*)(out + base) = o4;
    if (oh) {
        h16 h0,l0,h1,l1,h2,l2,h3,l3;
        hsplit(o4.x,h0,l0); hsplit(o4.y,h1,l1); hsplit(o4.z,h2,l2); hsplit(o4.w,h3,l3);
        *(__half2*)(oh+base)   = __halves2half2(h0,h1);
        *(__half2*)(oh+base+2) = __halves2half2(h2,h3);
        *(__half2*)(ol+base)   = __halves2half2(l0,l1);
        *(__half2*)(ol+base+2) = __halves2half2(l2,l3);
    }
}

// ---------------- kernel_launch ----------------
extern "C" void kernel_launch(void* const* d_in, const int* in_sizes, int n_in,
                              void* d_out, int out_size)
{
    const float* x   = (const float*)d_in[0];
    const int* mask  = (const int*)d_in[1];
    const float* wq  = (const float*)d_in[2];
    const float* bq  = (const float*)d_in[3];
    const float* wk  = (const float*)d_in[4];
    const float* bk  = (const float*)d_in[5];
    const float* wv  = (const float*)d_in[6];
    const float* bv  = (const float*)d_in[7];
    const float* wo  = (const float*)d_in[8];
    const float* bo  = (const float*)d_in[9];
    const float* l1a = (const float*)d_in[10];
    const float* l1b = (const float*)d_in[11];
    const float* l2a = (const float*)d_in[12];
    const float* l2b = (const float*)d_in[13];
    const float* w1  = (const float*)d_in[14];
    const float* b1  = (const float*)d_in[15];
    const float* w2  = (const float*)d_in[16];
    const float* b2  = (const float*)d_in[17];
    float* out = (float*)d_out;

    float *tmp, *x1;
    h16 *qh,*kh,*vh,*xh,*ah,*al,*x1h,*x1l,*fh,*fl;
    h16 *wqh,*wkh,*wvh,*woh,*w1h,*w2h;
    cudaGetSymbolAddress((void**)&tmp, g_tmp);
    cudaGetSymbolAddress((void**)&x1, g_x1);
    cudaGetSymbolAddress((void**)&qh, g_qh);
    cudaGetSymbolAddress((void**)&kh, g_kh);
    cudaGetSymbolAddress((void**)&vh, g_vh);
    cudaGetSymbolAddress((void**)&xh, g_xh);
    cudaGetSymbolAddress((void**)&ah, g_ah);   cudaGetSymbolAddress((void**)&al, g_al);
    cudaGetSymbolAddress((void**)&x1h, g_x1h); cudaGetSymbolAddress((void**)&x1l, g_x1l);
    cudaGetSymbolAddress((void**)&fh, g_fh);   cudaGetSymbolAddress((void**)&fl, g_fl);
    cudaGetSymbolAddress((void**)&wqh, g_wqh);
    cudaGetSymbolAddress((void**)&wkh, g_wkh);
    cudaGetSymbolAddress((void**)&wvh, g_wvh);
    cudaGetSymbolAddress((void**)&woh, g_woh);
    cudaGetSymbolAddress((void**)&w1h, g_w1h);
    cudaGetSymbolAddress((void**)&w2h, g_w2h);

    cudaFuncSetAttribute(hgemm, cudaFuncAttributeMaxDynamicSharedMemorySize, SMEM_REQ);

    // Pre-pass: split x (2 limbs); transpose+round weights (1 limb)
    vsplit_kernel<<<MROWS * Dq / 1024, 256>>>(x, xh, nullptr, MROWS * Dq);
    ttrans_kernel<<<dim3(Dq/32, Dq/32), 256>>>(wq, wqh, Dq, Dq);
    ttrans_kernel<<<dim3(Dq/32, Dq/32), 256>>>(wk, wkh, Dq, Dq);
    ttrans_kernel<<<dim3(Dq/32, Dq/32), 256>>>(wv, wvh, Dq, Dq);
    ttrans_kernel<<<dim3(Dq/32, Dq/32), 256>>>(wo, woh, Dq, Dq);
    ttrans_kernel<<<dim3(DFFq/32, Dq/32), 256>>>(w1, w1h, Dq, DFFq);
    ttrans_kernel<<<dim3(Dq/32, DFFq/32), 256>>>(w2, w2h, DFFq, Dq);

    const dim3 gD(Dq / BN, MROWS / BM);
    const dim3 gF(DFFq / BN, MROWS / BM);

    // QKV: 1-term (A = xh), fp16 out
    hgemm<<<gD, 256, SMEM_REQ>>>(xh, nullptr, wqh, bq, nullptr, qh, nullptr, MROWS, Dq, Dq, 0);
    hgemm<<<gD, 256, SMEM_REQ>>>(xh, nullptr, wkh, bk, nullptr, kh, nullptr, MROWS, Dq, Dq, 0);
    hgemm<<<gD, 256, SMEM_REQ>>>(xh, nullptr, wvh, bv, nullptr, vh, nullptr, MROWS, Dq, Dq, 0);

    attention_hmma<<<dim3(Sq/64, Hq, Bq), 128>>>(qh, kh, vh, mask, ah, al);

    // O-proj: 2-term (A = ah+al), fp32 out
    hgemm<<<gD, 256, SMEM_REQ>>>(ah, al, woh, bo, tmp, nullptr, nullptr, MROWS, Dq, Dq, 0);
    residual_ln<<<MROWS, 256>>>(x, tmp, l1a, l1b, x1, x1h, x1l);

    // FFN: 2-term both
    hgemm<<<gF, 256, SMEM_REQ>>>(x1h, x1l, w1h, b1, nullptr, fh, fl, MROWS, DFFq, Dq, 1);
    hgemm<<<gD, 256, SMEM_REQ>>>(fh, fl, w2h, b2, tmp, nullptr, nullptr, MROWS, Dq, DFFq, 0);
    residual_ln<<<MROWS, 256>>>(x1, tmp, l2a, l2b, out, nullptr, nullptr);
}

// round 12
// speedup vs baseline: 8.2318x; 1.4849x over previous
// r11: 1-term fp16 HMMA everywhere (resubmission c; hash-bump + launch_bounds(256,1))
#include <cuda_runtime.h>
#include <cuda_fp16.h>
#include <math.h>
#include <stdint.h>

#define Bq   8
#define Sq   1024
#define Dq   1024
#define Hq   16
#define DKq  64
#define DFFq 4096
#define MROWS (Bq * Sq)

typedef __half h16;

// ---------------- scratch ----------------
__device__ float g_tmp[MROWS * Dq];
__device__ float g_x1 [MROWS * Dq];
__device__ h16 g_qh [MROWS * Dq], g_kh [MROWS * Dq], g_vh [MROWS * Dq];
__device__ h16 g_xh [MROWS * Dq];
__device__ h16 g_ah [MROWS * Dq];
__device__ h16 g_x1h[MROWS * Dq];
__device__ h16 g_fh [MROWS * DFFq];
__device__ h16 g_wqh[Dq * Dq];
__device__ h16 g_wkh[Dq * Dq];
__device__ h16 g_wvh[Dq * Dq];
__device__ h16 g_woh[Dq * Dq];
__device__ h16 g_w1h[Dq * DFFq];
__device__ h16 g_w2h[DFFq * Dq];

// ---------------- helpers ----------------
__device__ __forceinline__ uint32_t smem_u32(const void* p) {
    uint32_t a;
    asm("{ .reg .u64 t; cvta.to.shared.u64 t, %1; cvt.u32.u64 %0, t; }" : "=r"(a) : "l"(p));
    return a;
}
__device__ __forceinline__ void cpa16(uint32_t s, const void* g) {
    asm volatile("cp.async.cg.shared.global [%0], [%1], 16;" :: "r"(s), "l"(g));
}
#define CP_COMMIT() asm volatile("cp.async.commit_group;" ::: "memory")
#define CP_WAIT1()  asm volatile("cp.async.wait_group 1;" ::: "memory")
#define CP_WAIT0()  asm volatile("cp.async.wait_group 0;" ::: "memory")
#define LDMX4(r0,r1,r2,r3,addr)                                               \
    asm volatile("ldmatrix.sync.aligned.m8n8.x4.shared.b16 {%0,%1,%2,%3},[%4];" \
        : "=r"(r0), "=r"(r1), "=r"(r2), "=r"(r3) : "r"(addr))
#define LDMX4T(r0,r1,r2,r3,addr)                                              \
    asm volatile("ldmatrix.sync.aligned.m8n8.x4.trans.shared.b16 {%0,%1,%2,%3},[%4];" \
        : "=r"(r0), "=r"(r1), "=r"(r2), "=r"(r3) : "r"(addr))
#define HMMA(d,a,b)                                                           \
    asm volatile("mma.sync.aligned.m16n8k16.row.col.f32.f16.f16.f32 "         \
        "{%0,%1,%2,%3},{%4,%5,%6,%7},{%8,%9},{%0,%1,%2,%3};"                  \
        : "+f"((d)[0]), "+f"((d)[1]), "+f"((d)[2]), "+f"((d)[3])              \
        : "r"((a)[0]), "r"((a)[1]), "r"((a)[2]), "r"((a)[3]),                 \
          "r"((b)[0]), "r"((b)[1]))

// ---------------- fp16 HMMA GEMM: C = Ah @ Bh^T + bias ---------------------
// 1-term. BM=BN=128, BK=64, 256 threads, warp tile 64x32, double buffer.
#define BM 128
#define BN 128
#define BK 64
#define OFF_A 0
#define OFF_B 16384
#define BUFB  32768
#define SMEM_REQ (2 * BUFB)            // 65536

__global__ __launch_bounds__(256, 1) void hgemm(
    const h16* __restrict__ Ahb, const h16* __restrict__ Bhb,
    const float* __restrict__ bias, float* __restrict__ C,
    h16* __restrict__ Ch,
    int M, int N, int K, int doRelu)
{
    extern __shared__ char smem[];
    const uint32_t sb = smem_u32(smem);
    const int tid  = threadIdx.x;
    const int warp = tid >> 5, lane = tid & 31;
    const int bm = blockIdx.y * BM, bn = blockIdx.x * BN;
    const int m0w = (warp & 1) * 64, n0w = (warp >> 1) * 32;

    const int rL = tid >> 3, cL = tid & 7;
    const uint32_t sRowOff = (uint32_t)rL * 128 + (((uint32_t)(cL ^ (rL & 7))) << 4);
    const h16* gA = Ahb + (size_t)(bm + rL) * K + cL * 8;
    const h16* gB = Bhb + (size_t)(bn + rL) * K + cL * 8;
    const size_t rstep = (size_t)32 * K;

    float acc[4][4][4];
#pragma unroll
    for (int i = 0; i < 4; i++)
#pragma unroll
        for (int j = 0; j < 4; j++)
#pragma unroll
            for (int r = 0; r < 4; r++) acc[i][j][r] = 0.f;

    const int arow0 = m0w + (lane & 15);
    const int akc   = lane >> 4;
    const int brow0 = n0w + ((lane >> 4) << 3) + (lane & 7);
    const int bkc   = (lane >> 3) & 1;

    auto LOAD = [&](int c, int buf) {
        const uint32_t s = sb + (uint32_t)buf * BUFB;
        const size_t k0 = (size_t)c * BK;
#pragma unroll
        for (int i = 0; i < 4; i++) {
            const uint32_t so = sRowOff + (uint32_t)i * 4096;
            const size_t go = (size_t)i * rstep + k0;
            cpa16(s + OFF_A + so, gA + go);
            cpa16(s + OFF_B + so, gB + go);
        }
    };

    auto COMPUTE = [&](int buf) {
        const uint32_t s = sb + (uint32_t)buf * BUFB;
#pragma unroll
        for (int ks = 0; ks < 4; ks++) {
            uint32_t bh[4][2];
#pragma unroll
            for (int bt = 0; bt < 2; bt++) {
                const int row = brow0 + bt * 16;
                const int kc  = ks * 2 + bkc;
                const uint32_t off = (uint32_t)row * 128 + (((uint32_t)(kc ^ (row & 7))) << 4);
                LDMX4(bh[2*bt][0], bh[2*bt][1], bh[2*bt+1][0], bh[2*bt+1][1], s + OFF_B + off);
            }
#pragma unroll
            for (int mt = 0; mt < 4; mt++) {
                const int row = arow0 + mt * 16;
                const int kc  = ks * 2 + akc;
                const uint32_t off = (uint32_t)row * 128 + (((uint32_t)(kc ^ (row & 7))) << 4);
                uint32_t a[4];
                LDMX4(a[0], a[1], a[2], a[3], s + OFF_A + off);
#pragma unroll
                for (int nt = 0; nt < 4; nt++) HMMA(acc[mt][nt], a, bh[nt]);
            }
        }
    };

    const int chunks = K / BK;
    LOAD(0, 0);
    CP_COMMIT();
#pragma unroll 1
    for (int c = 0; c < chunks; c++) {
        if (c + 1 < chunks) {
            LOAD(c + 1, (c + 1) & 1);
            CP_COMMIT();
            CP_WAIT1();
        } else {
            CP_WAIT0();
        }
        __syncthreads();
        COMPUTE(c & 1);
        __syncthreads();
    }

#pragma unroll
    for (int mt = 0; mt < 4; mt++) {
        const int mr = bm + m0w + mt * 16 + (lane >> 2);
#pragma unroll
        for (int nt = 0; nt < 4; nt++) {
            const int col = bn + n0w + nt * 8 + 2 * (lane & 3);
            const float b0 = bias[col], b1 = bias[col + 1];
            float v0 = acc[mt][nt][0] + b0, v1 = acc[mt][nt][1] + b1;
            float v2 = acc[mt][nt][2] + b0, v3 = acc[mt][nt][3] + b1;
            if (doRelu) {
                v0 = fmaxf(v0, 0.f); v1 = fmaxf(v1, 0.f);
                v2 = fmaxf(v2, 0.f); v3 = fmaxf(v3, 0.f);
            }
            if (C) {
                *(float2*)(C + (size_t)mr * N + col)       = make_float2(v0, v1);
                *(float2*)(C + (size_t)(mr + 8) * N + col) = make_float2(v2, v3);
            }
            if (Ch) {
                *(__half2*)(Ch + (size_t)mr * N + col)       = __floats2half2_rn(v0, v1);
                *(__half2*)(Ch + (size_t)(mr + 8) * N + col) = __floats2half2_rn(v2, v3);
            }
        }
    }
}

// ---------------- pre-pass kernels ----------------
__global__ __launch_bounds__(256) void vround_kernel(
    const float* __restrict__ s, h16* __restrict__ h, int n)
{
    int i = (blockIdx.x * 256 + threadIdx.x) * 4;
    if (i >= n) return;
    float4 v = *(const float4*)(s + i);
    *(__half2*)(h+i)   = __floats2half2_rn(v.x, v.y);
    *(__half2*)(h+i+2) = __floats2half2_rn(v.z, v.w);
}

// transpose + round: W[K,N] fp32 -> Th[N,K] fp16
__global__ __launch_bounds__(256) void ttrans_kernel(
    const float* __restrict__ W, h16* __restrict__ Th, int K, int N)
{
    __shared__ float t[32][33];
    const int n0 = blockIdx.x * 32, k0 = blockIdx.y * 32;
    const int tx = threadIdx.x & 31, ty = threadIdx.x >> 5;
#pragma unroll
    for (int i = ty; i < 32; i += 8)
        t[i][tx] = W[(size_t)(k0 + i) * N + n0 + tx];
    __syncthreads();
#pragma unroll
    for (int i = ty; i < 32; i += 8)
        Th[(size_t)(n0 + i) * K + k0 + tx] = __float2half_rn(t[tx][i]);
}

// ---------------- HMMA flash attention (single-limb output) ----------------
__global__ __launch_bounds__(128) void attention_hmma(
    const h16* __restrict__ Qg, const h16* __restrict__ Kg,
    const h16* __restrict__ Vg, const int* __restrict__ mask,
    h16* __restrict__ OH)
{
    __shared__ h16 Qs[64 * 64];
    __shared__ h16 Ks[64 * 64];
    __shared__ h16 Vs[64 * 64];
    __shared__ int ms[64];

    const int b = blockIdx.z, h = blockIdx.y, qt = blockIdx.x;
    const int tid = threadIdx.x, warp = tid >> 5, lane = tid & 31;
    const uint32_t qsb = smem_u32(Qs), ksb = smem_u32(Ks), vsb = smem_u32(Vs);

    const int lr = tid >> 1, lc0 = (tid & 1) * 4;
    const h16* qg = Qg + (size_t)(b * Sq + qt * 64 + lr) * Dq + h * 64;
    const h16* kgb = Kg + (size_t)(b * Sq + lr) * Dq + h * 64;
    const h16* vgb = Vg + (size_t)(b * Sq + lr) * Dq + h * 64;

#pragma unroll
    for (int c = 0; c < 4; c++) {
        const int ch = lc0 + c;
        const uint32_t sw = (uint32_t)lr * 128 + (((uint32_t)(ch ^ (lr & 7))) << 4);
        cpa16(qsb + sw, qg + ch * 8);
        cpa16(ksb + sw, kgb + ch * 8);
        cpa16(vsb + sw, vgb + ch * 8);
    }
    if (tid < 64) ms[tid] = mask[b * Sq + tid];
    CP_COMMIT();
    CP_WAIT0();
    __syncthreads();

    uint32_t qf[4][4];
    {
        const int row = warp * 16 + (lane & 15);
        const int kb = lane >> 4;
#pragma unroll
        for (int kf = 0; kf < 4; kf++) {
            const int kc = kf * 2 + kb;
            const uint32_t off = (uint32_t)row * 128 + (((uint32_t)(kc ^ (row & 7))) << 4);
            LDMX4(qf[kf][0], qf[kf][1], qf[kf][2], qf[kf][3], qsb + off);
        }
    }

    float oacc[8][4];
#pragma unroll
    for (int t = 0; t < 8; t++)
#pragma unroll
        for (int r = 0; r < 4; r++) oacc[t][r] = 0.f;
    float lsum0 = 0.f, lsum1 = 0.f;

    const int sb_row = ((lane >> 4) << 3) + (lane & 7);
    const int sb_kc  = (lane >> 3) & 1;
    const int vrow   = ((lane >> 3) & 1) * 8 + (lane & 7);
    const int vchb   = lane >> 4;
    const int mcol   = 2 * (lane & 3);

#pragma unroll 1
    for (int c = 0; c < 16; c++) {
        float sacc[8][4];
#pragma unroll
        for (int t = 0; t < 8; t++)
#pragma unroll
            for (int r = 0; r < 4; r++) sacc[t][r] = 0.f;
#pragma unroll
        for (int jt = 0; jt < 4; jt++) {
            const int row = jt * 16 + sb_row;
#pragma unroll
            for (int kf = 0; kf < 4; kf++) {
                const int kc = kf * 2 + sb_kc;
                const uint32_t off = (uint32_t)row * 128 + (((uint32_t)(kc ^ (row & 7))) << 4);
                uint32_t bb[4];
                LDMX4(bb[0], bb[1], bb[2], bb[3], ksb + off);
                HMMA(sacc[2*jt],   qf[kf], (bb));
                HMMA(sacc[2*jt+1], qf[kf], (bb + 2));
            }
        }

        uint32_t pf[4][4];
#pragma unroll
        for (int t = 0; t < 8; t++) {
            const int col = t * 8 + mcol;
            const int m0 = ms[col], m1 = ms[col + 1];
            float p0 = m0 ? __expf(0.125f * sacc[t][0]) : 0.f;
            float p1 = m1 ? __expf(0.125f * sacc[t][1]) : 0.f;
            float p2 = m0 ? __expf(0.125f * sacc[t][2]) : 0.f;
            float p3 = m1 ? __expf(0.125f * sacc[t][3]) : 0.f;
            lsum0 += p0 + p1;
            lsum1 += p2 + p3;
            __half2 a01 = __floats2half2_rn(p0, p1);
            __half2 a23 = __floats2half2_rn(p2, p3);
            pf[t >> 1][(t & 1) * 2 + 0] = *(uint32_t*)&a01;
            pf[t >> 1][(t & 1) * 2 + 1] = *(uint32_t*)&a23;
        }

#pragma unroll
        for (int np = 0; np < 4; np++) {
            const int chunk = np * 2 + vchb;
#pragma unroll
            for (int kt = 0; kt < 4; kt++) {
                const int r = kt * 16 + vrow;
                const uint32_t off = (uint32_t)r * 128 + (((uint32_t)(chunk ^ (r & 7))) << 4);
                uint32_t vb[4];
                LDMX4T(vb[0], vb[1], vb[2], vb[3], vsb + off);
                HMMA(oacc[2*np],   pf[kt], (vb));
                HMMA(oacc[2*np+1], pf[kt], (vb + 2));
            }
        }

        if (c < 15) {
            __syncthreads();
            const size_t gofs = (size_t)(c + 1) * 64 * Dq;
#pragma unroll
            for (int cc = 0; cc < 4; cc++) {
                const int ch = lc0 + cc;
                const uint32_t sw = (uint32_t)lr * 128 + (((uint32_t)(ch ^ (lr & 7))) << 4);
                cpa16(ksb + sw, kgb + gofs + ch * 8);
                cpa16(vsb + sw, vgb + gofs + ch * 8);
            }
            if (tid < 64) ms[tid] = mask[b * Sq + (c + 1) * 64 + tid];
            CP_COMMIT();
            CP_WAIT0();
            __syncthreads();
        }
    }

    lsum0 += __shfl_xor_sync(0xffffffffu, lsum0, 1);
    lsum0 += __shfl_xor_sync(0xffffffffu, lsum0, 2);
    lsum1 += __shfl_xor_sync(0xffffffffu, lsum1, 1);
    lsum1 += __shfl_xor_sync(0xffffffffu, lsum1, 2);
    const float inv0 = 1.f / lsum0, inv1 = 1.f / lsum1;

    const int qr0 = qt * 64 + warp * 16 + (lane >> 2);
    const size_t gr0 = (size_t)(b * Sq + qr0) * Dq;
    const size_t gr1 = gr0 + (size_t)8 * Dq;
#pragma unroll
    for (int t = 0; t < 8; t++) {
        const int col = h * 64 + t * 8 + mcol;
        *(__half2*)(OH + gr0 + col) = __floats2half2_rn(oacc[t][0] * inv0, oacc[t][1] * inv0);
        *(__half2*)(OH + gr1 + col) = __floats2half2_rn(oacc[t][2] * inv1, oacc[t][3] * inv1);
    }
}

// ---------------- residual + LayerNorm (opt fp16 out) ----------------
__global__ __launch_bounds__(256) void residual_ln(
    const float* __restrict__ X, const float* __restrict__ Y,
    const float* __restrict__ Aw, const float* __restrict__ Bw,
    float* __restrict__ out, h16* __restrict__ oh)
{
    const int row = blockIdx.x, tid = threadIdx.x;
    const size_t base = (size_t)row * Dq + tid * 4;
    float4 xv = *(const float4*)(X + base);
    float4 yv = *(const float4*)(Y + base);
    float4 v = make_float4(xv.x+yv.x, xv.y+yv.y, xv.z+yv.z, xv.w+yv.w);

    float s = v.x+v.y+v.z+v.w;
    float ss = v.x*v.x+v.y*v.y+v.z*v.z+v.w*v.w;
#pragma unroll
    for (int o = 16; o > 0; o >>= 1) {
        s  += __shfl_xor_sync(0xffffffffu, s, o);
        ss += __shfl_xor_sync(0xffffffffu, ss, o);
    }
    __shared__ float rs[8], rss[8];
    const int w = tid >> 5, lane = tid & 31;
    if (lane == 0) { rs[w] = s; rss[w] = ss; }
    __syncthreads();
    if (tid == 0) {
        float S = 0.f, SS = 0.f;
#pragma unroll
        for (int i = 0; i < 8; i++) { S += rs[i]; SS += rss[i]; }
        rs[0] = S; rss[0] = SS;
    }
    __syncthreads();
    const float mean = rs[0] * (1.f / Dq);
    const float var  = rss[0] * (1.f / Dq) - mean * mean;
    const float rstd = rsqrtf(var + 1e-6f);

    float4 a4 = *(const float4*)(Aw + tid * 4);
    float4 b4 = *(const float4*)(Bw + tid * 4);
    float4 o4;
    o4.x = a4.x * (v.x - mean) * rstd + b4.x;
    o4.y = a4.y * (v.y - mean) * rstd + b4.y;
    o4.z = a4.z * (v.z - mean) * rstd + b4.z;
    o4.w = a4.w * (v.w - mean) * rstd + b4.w;
    *(float4*)(out + base) = o4;
    if (oh) {
        *(__half2*)(oh+base)   = __floats2half2_rn(o4.x, o4.y);
        *(__half2*)(oh+base+2) = __floats2half2_rn(o4.z, o4.w);
    }
}

// ---------------- kernel_launch ----------------
extern "C" void kernel_launch(void* const* d_in, const int* in_sizes, int n_in,
                              void* d_out, int out_size)
{
    const float* x   = (const float*)d_in[0];
    const int* mask  = (const int*)d_in[1];
    const float* wq  = (const float*)d_in[2];
    const float* bq  = (const float*)d_in[3];
    const float* wk  = (const float*)d_in[4];
    const float* bk  = (const float*)d_in[5];
    const float* wv  = (const float*)d_in[6];
    const float* bv  = (const float*)d_in[7];
    const float* wo  = (const float*)d_in[8];
    const float* bo  = (const float*)d_in[9];
    const float* l1a = (const float*)d_in[10];
    const float* l1b = (const float*)d_in[11];
    const float* l2a = (const float*)d_in[12];
    const float* l2b = (const float*)d_in[13];
    const float* w1  = (const float*)d_in[14];
    const float* b1  = (const float*)d_in[15];
    const float* w2  = (const float*)d_in[16];
    const float* b2  = (const float*)d_in[17];
    float* out = (float*)d_out;

    float *tmp, *x1;
    h16 *qh,*kh,*vh,*xh,*ah,*x1h,*fh;
    h16 *wqh,*wkh,*wvh,*woh,*w1h,*w2h;
    cudaGetSymbolAddress((void**)&tmp, g_tmp);
    cudaGetSymbolAddress((void**)&x1, g_x1);
    cudaGetSymbolAddress((void**)&qh, g_qh);
    cudaGetSymbolAddress((void**)&kh, g_kh);
    cudaGetSymbolAddress((void**)&vh, g_vh);
    cudaGetSymbolAddress((void**)&xh, g_xh);
    cudaGetSymbolAddress((void**)&ah, g_ah);
    cudaGetSymbolAddress((void**)&x1h, g_x1h);
    cudaGetSymbolAddress((void**)&fh, g_fh);
    cudaGetSymbolAddress((void**)&wqh, g_wqh);
    cudaGetSymbolAddress((void**)&wkh, g_wkh);
    cudaGetSymbolAddress((void**)&wvh, g_wvh);
    cudaGetSymbolAddress((void**)&woh, g_woh);
    cudaGetSymbolAddress((void**)&w1h, g_w1h);
    cudaGetSymbolAddress((void**)&w2h, g_w2h);

    cudaFuncSetAttribute(hgemm, cudaFuncAttributeMaxDynamicSharedMemorySize, SMEM_REQ);

    // Pre-pass: round x; transpose+round weights
    vround_kernel<<<MROWS * Dq / 1024, 256>>>(x, xh, MROWS * Dq);
    ttrans_kernel<<<dim3(Dq/32, Dq/32), 256>>>(wq, wqh, Dq, Dq);
    ttrans_kernel<<<dim3(Dq/32, Dq/32), 256>>>(wk, wkh, Dq, Dq);
    ttrans_kernel<<<dim3(Dq/32, Dq/32), 256>>>(wv, wvh, Dq, Dq);
    ttrans_kernel<<<dim3(Dq/32, Dq/32), 256>>>(wo, woh, Dq, Dq);
    ttrans_kernel<<<dim3(DFFq/32, Dq/32), 256>>>(w1, w1h, Dq, DFFq);
    ttrans_kernel<<<dim3(Dq/32, DFFq/32), 256>>>(w2, w2h, DFFq, Dq);

    const dim3 gD(Dq / BN, MROWS / BM);
    const dim3 gF(DFFq / BN, MROWS / BM);

    // QKV: fp16 out
    hgemm<<<gD, 256, SMEM_REQ>>>(xh, wqh, bq, nullptr, qh, MROWS, Dq, Dq, 0);
    hgemm<<<gD, 256, SMEM_REQ>>>(xh, wkh, bk, nullptr, kh, MROWS, Dq, Dq, 0);
    hgemm<<<gD, 256, SMEM_REQ>>>(xh, wvh, bv, nullptr, vh, MROWS, Dq, Dq, 0);

    attention_hmma<<<dim3(Sq/64, Hq, Bq), 128>>>(qh, kh, vh, mask, ah);

    // O-proj -> fp32 tmp; LN1 -> x1 fp32 + x1h fp16
    hgemm<<<gD, 256, SMEM_REQ>>>(ah, woh, bo, tmp, nullptr, MROWS, Dq, Dq, 0);
    residual_ln<<<MROWS, 256>>>(x, tmp, l1a, l1b, x1, x1h);

    // FFN
    hgemm<<<gF, 256, SMEM_REQ>>>(x1h, w1h, b1, nullptr, fh, MROWS, DFFq, Dq, 1);
    hgemm<<<gD, 256, SMEM_REQ>>>(fh, w2h, b2, tmp, nullptr, MROWS, Dq, DFFq, 0);
    residual_ln<<<MROWS, 256>>>(x1, tmp, l2a, l2b, out, nullptr);
}

// round 13
// speedup vs baseline: 9.0505x; 1.0995x over previous
// r13: hgemm widened to BM128xBN256 (warp tile 64x64, 4:1 HMMA:ldmatrix)
#include <cuda_runtime.h>
#include <cuda_fp16.h>
#include <math.h>
#include <stdint.h>

#define Bq   8
#define Sq   1024
#define Dq   1024
#define Hq   16
#define DKq  64
#define DFFq 4096
#define MROWS (Bq * Sq)

typedef __half h16;

// ---------------- scratch ----------------
__device__ float g_tmp[MROWS * Dq];
__device__ float g_x1 [MROWS * Dq];
__device__ h16 g_qh [MROWS * Dq], g_kh [MROWS * Dq], g_vh [MROWS * Dq];
__device__ h16 g_xh [MROWS * Dq];
__device__ h16 g_ah [MROWS * Dq];
__device__ h16 g_x1h[MROWS * Dq];
__device__ h16 g_fh [MROWS * DFFq];
__device__ h16 g_wqh[Dq * Dq];
__device__ h16 g_wkh[Dq * Dq];
__device__ h16 g_wvh[Dq * Dq];
__device__ h16 g_woh[Dq * Dq];
__device__ h16 g_w1h[Dq * DFFq];
__device__ h16 g_w2h[DFFq * Dq];

// ---------------- helpers ----------------
__device__ __forceinline__ uint32_t smem_u32(const void* p) {
    uint32_t a;
    asm("{ .reg .u64 t; cvta.to.shared.u64 t, %1; cvt.u32.u64 %0, t; }" : "=r"(a) : "l"(p));
    return a;
}
__device__ __forceinline__ void cpa16(uint32_t s, const void* g) {
    asm volatile("cp.async.cg.shared.global [%0], [%1], 16;" :: "r"(s), "l"(g));
}
#define CP_COMMIT() asm volatile("cp.async.commit_group;" ::: "memory")
#define CP_WAIT1()  asm volatile("cp.async.wait_group 1;" ::: "memory")
#define CP_WAIT0()  asm volatile("cp.async.wait_group 0;" ::: "memory")
#define LDMX4(r0,r1,r2,r3,addr)                                               \
    asm volatile("ldmatrix.sync.aligned.m8n8.x4.shared.b16 {%0,%1,%2,%3},[%4];" \
        : "=r"(r0), "=r"(r1), "=r"(r2), "=r"(r3) : "r"(addr))
#define LDMX4T(r0,r1,r2,r3,addr)                                              \
    asm volatile("ldmatrix.sync.aligned.m8n8.x4.trans.shared.b16 {%0,%1,%2,%3},[%4];" \
        : "=r"(r0), "=r"(r1), "=r"(r2), "=r"(r3) : "r"(addr))
#define HMMA(d,a,b)                                                           \
    asm volatile("mma.sync.aligned.m16n8k16.row.col.f32.f16.f16.f32 "         \
        "{%0,%1,%2,%3},{%4,%5,%6,%7},{%8,%9},{%0,%1,%2,%3};"                  \
        : "+f"((d)[0]), "+f"((d)[1]), "+f"((d)[2]), "+f"((d)[3])              \
        : "r"((a)[0]), "r"((a)[1]), "r"((a)[2]), "r"((a)[3]),                 \
          "r"((b)[0]), "r"((b)[1]))

// ---------------- fp16 HMMA GEMM: C = Ah @ Bh^T + bias ---------------------
// 1-term. BM=128, BN=256, BK=64, 256 threads, warp tile 64x64, double buffer.
#define BM 128
#define BN 256
#define BK 64
#define OFF_A 0
#define OFF_B 16384
#define BUFB  49152                    // 16KB A + 32KB B
#define SMEM_REQ (2 * BUFB)            // 98304

__global__ __launch_bounds__(256) void hgemm(
    const h16* __restrict__ Ahb, const h16* __restrict__ Bhb,
    const float* __restrict__ bias, float* __restrict__ C,
    h16* __restrict__ Ch,
    int M, int N, int K, int doRelu)
{
    extern __shared__ char smem[];
    const uint32_t sb = smem_u32(smem);
    const int tid  = threadIdx.x;
    const int warp = tid >> 5, lane = tid & 31;
    const int bm = blockIdx.y * BM, bn = blockIdx.x * BN;
    const int m0w = (warp & 1) * 64, n0w = (warp >> 1) * 64;

    const int rL = tid >> 3, cL = tid & 7;
    const uint32_t sRowOff = (uint32_t)rL * 128 + (((uint32_t)(cL ^ (rL & 7))) << 4);
    const h16* gA = Ahb + (size_t)(bm + rL) * K + cL * 8;
    const h16* gB = Bhb + (size_t)(bn + rL) * K + cL * 8;
    const size_t rstep = (size_t)32 * K;

    float acc[4][8][4];
#pragma unroll
    for (int i = 0; i < 4; i++)
#pragma unroll
        for (int j = 0; j < 8; j++)
#pragma unroll
            for (int r = 0; r < 4; r++) acc[i][j][r] = 0.f;

    const int arow0 = m0w + (lane & 15);
    const int akc   = lane >> 4;
    const int brow0 = n0w + ((lane >> 4) << 3) + (lane & 7);
    const int bkc   = (lane >> 3) & 1;

    auto LOAD = [&](int c, int buf) {
        const uint32_t s = sb + (uint32_t)buf * BUFB;
        const size_t k0 = (size_t)c * BK;
#pragma unroll
        for (int i = 0; i < 4; i++) {               // A: 128 rows
            const uint32_t so = sRowOff + (uint32_t)i * 4096;
            cpa16(s + OFF_A + so, gA + (size_t)i * rstep + k0);
        }
#pragma unroll
        for (int i = 0; i < 8; i++) {               // B: 256 rows
            const uint32_t so = sRowOff + (uint32_t)i * 4096;
            cpa16(s + OFF_B + so, gB + (size_t)i * rstep + k0);
        }
    };

    auto COMPUTE = [&](int buf) {
        const uint32_t s = sb + (uint32_t)buf * BUFB;
#pragma unroll
        for (int ks = 0; ks < 4; ks++) {
            uint32_t bh[8][2];
#pragma unroll
            for (int bt = 0; bt < 4; bt++) {        // 64 B-rows (cols of C)
                const int row = brow0 + bt * 16;
                const int kc  = ks * 2 + bkc;
                const uint32_t off = (uint32_t)row * 128 + (((uint32_t)(kc ^ (row & 7))) << 4);
                LDMX4(bh[2*bt][0], bh[2*bt][1], bh[2*bt+1][0], bh[2*bt+1][1], s + OFF_B + off);
            }
#pragma unroll
            for (int mt = 0; mt < 4; mt++) {
                const int row = arow0 + mt * 16;
                const int kc  = ks * 2 + akc;
                const uint32_t off = (uint32_t)row * 128 + (((uint32_t)(kc ^ (row & 7))) << 4);
                uint32_t a[4];
                LDMX4(a[0], a[1], a[2], a[3], s + OFF_A + off);
#pragma unroll
                for (int nt = 0; nt < 8; nt++) HMMA(acc[mt][nt], a, bh[nt]);
            }
        }
    };

    const int chunks = K / BK;
    LOAD(0, 0);
    CP_COMMIT();
#pragma unroll 1
    for (int c = 0; c < chunks; c++) {
        if (c + 1 < chunks) {
            LOAD(c + 1, (c + 1) & 1);
            CP_COMMIT();
            CP_WAIT1();
        } else {
            CP_WAIT0();
        }
        __syncthreads();
        COMPUTE(c & 1);
        __syncthreads();
    }

#pragma unroll
    for (int mt = 0; mt < 4; mt++) {
        const int mr = bm + m0w + mt * 16 + (lane >> 2);
#pragma unroll
        for (int nt = 0; nt < 8; nt++) {
            const int col = bn + n0w + nt * 8 + 2 * (lane & 3);
            const float b0 = bias[col], b1 = bias[col + 1];
            float v0 = acc[mt][nt][0] + b0, v1 = acc[mt][nt][1] + b1;
            float v2 = acc[mt][nt][2] + b0, v3 = acc[mt][nt][3] + b1;
            if (doRelu) {
                v0 = fmaxf(v0, 0.f); v1 = fmaxf(v1, 0.f);
                v2 = fmaxf(v2, 0.f); v3 = fmaxf(v3, 0.f);
            }
            if (C) {
                *(float2*)(C + (size_t)mr * N + col)       = make_float2(v0, v1);
                *(float2*)(C + (size_t)(mr + 8) * N + col) = make_float2(v2, v3);
            }
            if (Ch) {
                *(__half2*)(Ch + (size_t)mr * N + col)       = __floats2half2_rn(v0, v1);
                *(__half2*)(Ch + (size_t)(mr + 8) * N + col) = __floats2half2_rn(v2, v3);
            }
        }
    }
}

// ---------------- pre-pass kernels ----------------
__global__ __launch_bounds__(256) void vround_kernel(
    const float* __restrict__ s, h16* __restrict__ h, int n)
{
    int i = (blockIdx.x * 256 + threadIdx.x) * 4;
    if (i >= n) return;
    float4 v = *(const float4*)(s + i);
    *(__half2*)(h+i)   = __floats2half2_rn(v.x, v.y);
    *(__half2*)(h+i+2) = __floats2half2_rn(v.z, v.w);
}

// transpose + round: W[K,N] fp32 -> Th[N,K] fp16
__global__ __launch_bounds__(256) void ttrans_kernel(
    const float* __restrict__ W, h16* __restrict__ Th, int K, int N)
{
    __shared__ float t[32][33];
    const int n0 = blockIdx.x * 32, k0 = blockIdx.y * 32;
    const int tx = threadIdx.x & 31, ty = threadIdx.x >> 5;
#pragma unroll
    for (int i = ty; i < 32; i += 8)
        t[i][tx] = W[(size_t)(k0 + i) * N + n0 + tx];
    __syncthreads();
#pragma unroll
    for (int i = ty; i < 32; i += 8)
        Th[(size_t)(n0 + i) * K + k0 + tx] = __float2half_rn(t[tx][i]);
}

// ---------------- HMMA flash attention (single-limb output) ----------------
__global__ __launch_bounds__(128) void attention_hmma(
    const h16* __restrict__ Qg, const h16* __restrict__ Kg,
    const h16* __restrict__ Vg, const int* __restrict__ mask,
    h16* __restrict__ OH)
{
    __shared__ h16 Qs[64 * 64];
    __shared__ h16 Ks[64 * 64];
    __shared__ h16 Vs[64 * 64];
    __shared__ int ms[64];

    const int b = blockIdx.z, h = blockIdx.y, qt = blockIdx.x;
    const int tid = threadIdx.x, warp = tid >> 5, lane = tid & 31;
    const uint32_t qsb = smem_u32(Qs), ksb = smem_u32(Ks), vsb = smem_u32(Vs);

    const int lr = tid >> 1, lc0 = (tid & 1) * 4;
    const h16* qg = Qg + (size_t)(b * Sq + qt * 64 + lr) * Dq + h * 64;
    const h16* kgb = Kg + (size_t)(b * Sq + lr) * Dq + h * 64;
    const h16* vgb = Vg + (size_t)(b * Sq + lr) * Dq + h * 64;

#pragma unroll
    for (int c = 0; c < 4; c++) {
        const int ch = lc0 + c;
        const uint32_t sw = (uint32_t)lr * 128 + (((uint32_t)(ch ^ (lr & 7))) << 4);
        cpa16(qsb + sw, qg + ch * 8);
        cpa16(ksb + sw, kgb + ch * 8);
        cpa16(vsb + sw, vgb + ch * 8);
    }
    if (tid < 64) ms[tid] = mask[b * Sq + tid];
    CP_COMMIT();
    CP_WAIT0();
    __syncthreads();

    uint32_t qf[4][4];
    {
        const int row = warp * 16 + (lane & 15);
        const int kb = lane >> 4;
#pragma unroll
        for (int kf = 0; kf < 4; kf++) {
            const int kc = kf * 2 + kb;
            const uint32_t off = (uint32_t)row * 128 + (((uint32_t)(kc ^ (row & 7))) << 4);
            LDMX4(qf[kf][0], qf[kf][1], qf[kf][2], qf[kf][3], qsb + off);
        }
    }

    float oacc[8][4];
#pragma unroll
    for (int t = 0; t < 8; t++)
#pragma unroll
        for (int r = 0; r < 4; r++) oacc[t][r] = 0.f;
    float lsum0 = 0.f, lsum1 = 0.f;

    const int sb_row = ((lane >> 4) << 3) + (lane & 7);
    const int sb_kc  = (lane >> 3) & 1;
    const int vrow   = ((lane >> 3) & 1) * 8 + (lane & 7);
    const int vchb   = lane >> 4;
    const int mcol   = 2 * (lane & 3);

#pragma unroll 1
    for (int c = 0; c < 16; c++) {
        float sacc[8][4];
#pragma unroll
        for (int t = 0; t < 8; t++)
#pragma unroll
            for (int r = 0; r < 4; r++) sacc[t][r] = 0.f;
#pragma unroll
        for (int jt = 0; jt < 4; jt++) {
            const int row = jt * 16 + sb_row;
#pragma unroll
            for (int kf = 0; kf < 4; kf++) {
                const int kc = kf * 2 + sb_kc;
                const uint32_t off = (uint32_t)row * 128 + (((uint32_t)(kc ^ (row & 7))) << 4);
                uint32_t bb[4];
                LDMX4(bb[0], bb[1], bb[2], bb[3], ksb + off);
                HMMA(sacc[2*jt],   qf[kf], (bb));
                HMMA(sacc[2*jt+1], qf[kf], (bb + 2));
            }
        }

        uint32_t pf[4][4];
#pragma unroll
        for (int t = 0; t < 8; t++) {
            const int col = t * 8 + mcol;
            const int m0 = ms[col], m1 = ms[col + 1];
            float p0 = m0 ? __expf(0.125f * sacc[t][0]) : 0.f;
            float p1 = m1 ? __expf(0.125f * sacc[t][1]) : 0.f;
            float p2 = m0 ? __expf(0.125f * sacc[t][2]) : 0.f;
            float p3 = m1 ? __expf(0.125f * sacc[t][3]) : 0.f;
            lsum0 += p0 + p1;
            lsum1 += p2 + p3;
            __half2 a01 = __floats2half2_rn(p0, p1);
            __half2 a23 = __floats2half2_rn(p2, p3);
            pf[t >> 1][(t & 1) * 2 + 0] = *(uint32_t*)&a01;
            pf[t >> 1][(t & 1) * 2 + 1] = *(uint32_t*)&a23;
        }

#pragma unroll
        for (int np = 0; np < 4; np++) {
            const int chunk = np * 2 + vchb;
#pragma unroll
            for (int kt = 0; kt < 4; kt++) {
                const int r = kt * 16 + vrow;
                const uint32_t off = (uint32_t)r * 128 + (((uint32_t)(chunk ^ (r & 7))) << 4);
                uint32_t vb[4];
                LDMX4T(vb[0], vb[1], vb[2], vb[3], vsb + off);
                HMMA(oacc[2*np],   pf[kt], (vb));
                HMMA(oacc[2*np+1], pf[kt], (vb + 2));
            }
        }

        if (c < 15) {
            __syncthreads();
            const size_t gofs = (size_t)(c + 1) * 64 * Dq;
#pragma unroll
            for (int cc = 0; cc < 4; cc++) {
                const int ch = lc0 + cc;
                const uint32_t sw = (uint32_t)lr * 128 + (((uint32_t)(ch ^ (lr & 7))) << 4);
                cpa16(ksb + sw, kgb + gofs + ch * 8);
                cpa16(vsb + sw, vgb + gofs + ch * 8);
            }
            if (tid < 64) ms[tid] = mask[b * Sq + (c + 1) * 64 + tid];
            CP_COMMIT();
            CP_WAIT0();
            __syncthreads();
        }
    }

    lsum0 += __shfl_xor_sync(0xffffffffu, lsum0, 1);
    lsum0 += __shfl_xor_sync(0xffffffffu, lsum0, 2);
    lsum1 += __shfl_xor_sync(0xffffffffu, lsum1, 1);
    lsum1 += __shfl_xor_sync(0xffffffffu, lsum1, 2);
    const float inv0 = 1.f / lsum0, inv1 = 1.f / lsum1;

    const int qr0 = qt * 64 + warp * 16 + (lane >> 2);
    const size_t gr0 = (size_t)(b * Sq + qr0) * Dq;
    const size_t gr1 = gr0 + (size_t)8 * Dq;
#pragma unroll
    for (int t = 0; t < 8; t++) {
        const int col = h * 64 + t * 8 + mcol;
        *(__half2*)(OH + gr0 + col) = __floats2half2_rn(oacc[t][0] * inv0, oacc[t][1] * inv0);
        *(__half2*)(OH + gr1 + col) = __floats2half2_rn(oacc[t][2] * inv1, oacc[t][3] * inv1);
    }
}

// ---------------- residual + LayerNorm (opt fp16 out) ----------------
__global__ __launch_bounds__(256) void residual_ln(
    const float* __restrict__ X, const float* __restrict__ Y,
    const float* __restrict__ Aw, const float* __restrict__ Bw,
    float* __restrict__ out, h16* __restrict__ oh)
{
    const int row = blockIdx.x, tid = threadIdx.x;
    const size_t base = (size_t)row * Dq + tid * 4;
    float4 xv = *(const float4*)(X + base);
    float4 yv = *(const float4*)(Y + base);
    float4 v = make_float4(xv.x+yv.x, xv.y+yv.y, xv.z+yv.z, xv.w+yv.w);

    float s = v.x+v.y+v.z+v.w;
    float ss = v.x*v.x+v.y*v.y+v.z*v.z+v.w*v.w;
#pragma unroll
    for (int o = 16; o > 0; o >>= 1) {
        s  += __shfl_xor_sync(0xffffffffu, s, o);
        ss += __shfl_xor_sync(0xffffffffu, ss, o);
    }
    __shared__ float rs[8], rss[8];
    const int w = tid >> 5, lane = tid & 31;
    if (lane == 0) { rs[w] = s; rss[w] = ss; }
    __syncthreads();
    if (tid == 0) {
        float S = 0.f, SS = 0.f;
#pragma unroll
        for (int i = 0; i < 8; i++) { S += rs[i]; SS += rss[i]; }
        rs[0] = S; rss[0] = SS;
    }
    __syncthreads();
    const float mean = rs[0] * (1.f / Dq);
    const float var  = rss[0] * (1.f / Dq) - mean * mean;
    const float rstd = rsqrtf(var + 1e-6f);

    float4 a4 = *(const float4*)(Aw + tid * 4);
    float4 b4 = *(const float4*)(Bw + tid * 4);
    float4 o4;
    o4.x = a4.x * (v.x - mean) * rstd + b4.x;
    o4.y = a4.y * (v.y - mean) * rstd + b4.y;
    o4.z = a4.z * (v.z - mean) * rstd + b4.z;
    o4.w = a4.w * (v.w - mean) * rstd + b4.w;
    *(float4*)(out + base) = o4;
    if (oh) {
        *(__half2*)(oh+base)   = __floats2half2_rn(o4.x, o4.y);
        *(__half2*)(oh+base+2) = __floats2half2_rn(o4.z, o4.w);
    }
}

// ---------------- kernel_launch ----------------
extern "C" void kernel_launch(void* const* d_in, const int* in_sizes, int n_in,
                              void* d_out, int out_size)
{
    const float* x   = (const float*)d_in[0];
    const int* mask  = (const int*)d_in[1];
    const float* wq  = (const float*)d_in[2];
    const float* bq  = (const float*)d_in[3];
    const float* wk  = (const float*)d_in[4];
    const float* bk  = (const float*)d_in[5];
    const float* wv  = (const float*)d_in[6];
    const float* bv  = (const float*)d_in[7];
    const float* wo  = (const float*)d_in[8];
    const float* bo  = (const float*)d_in[9];
    const float* l1a = (const float*)d_in[10];
    const float* l1b = (const float*)d_in[11];
    const float* l2a = (const float*)d_in[12];
    const float* l2b = (const float*)d_in[13];
    const float* w1  = (const float*)d_in[14];
    const float* b1  = (const float*)d_in[15];
    const float* w2  = (const float*)d_in[16];
    const float* b2  = (const float*)d_in[17];
    float* out = (float*)d_out;

    float *tmp, *x1;
    h16 *qh,*kh,*vh,*xh,*ah,*x1h,*fh;
    h16 *wqh,*wkh,*wvh,*woh,*w1h,*w2h;
    cudaGetSymbolAddress((void**)&tmp, g_tmp);
    cudaGetSymbolAddress((void**)&x1, g_x1);
    cudaGetSymbolAddress((void**)&qh, g_qh);
    cudaGetSymbolAddress((void**)&kh, g_kh);
    cudaGetSymbolAddress((void**)&vh, g_vh);
    cudaGetSymbolAddress((void**)&xh, g_xh);
    cudaGetSymbolAddress((void**)&ah, g_ah);
    cudaGetSymbolAddress((void**)&x1h, g_x1h);
    cudaGetSymbolAddress((void**)&fh, g_fh);
    cudaGetSymbolAddress((void**)&wqh, g_wqh);
    cudaGetSymbolAddress((void**)&wkh, g_wkh);
    cudaGetSymbolAddress((void**)&wvh, g_wvh);
    cudaGetSymbolAddress((void**)&woh, g_woh);
    cudaGetSymbolAddress((void**)&w1h, g_w1h);
    cudaGetSymbolAddress((void**)&w2h, g_w2h);

    cudaFuncSetAttribute(hgemm, cudaFuncAttributeMaxDynamicSharedMemorySize, SMEM_REQ);

    // Pre-pass: round x; transpose+round weights
    vround_kernel<<<MROWS * Dq / 1024, 256>>>(x, xh, MROWS * Dq);
    ttrans_kernel<<<dim3(Dq/32, Dq/32), 256>>>(wq, wqh, Dq, Dq);
    ttrans_kernel<<<dim3(Dq/32, Dq/32), 256>>>(wk, wkh, Dq, Dq);
    ttrans_kernel<<<dim3(Dq/32, Dq/32), 256>>>(wv, wvh, Dq, Dq);
    ttrans_kernel<<<dim3(Dq/32, Dq/32), 256>>>(wo, woh, Dq, Dq);
    ttrans_kernel<<<dim3(DFFq/32, Dq/32), 256>>>(w1, w1h, Dq, DFFq);
    ttrans_kernel<<<dim3(Dq/32, DFFq/32), 256>>>(w2, w2h, DFFq, Dq);

    const dim3 gD(Dq / BN, MROWS / BM);    // (4, 64)
    const dim3 gF(DFFq / BN, MROWS / BM);  // (16, 64)

    // QKV: fp16 out
    hgemm<<<gD, 256, SMEM_REQ>>>(xh, wqh, bq, nullptr, qh, MROWS, Dq, Dq, 0);
    hgemm<<<gD, 256, SMEM_REQ>>>(xh, wkh, bk, nullptr, kh, MROWS, Dq, Dq, 0);
    hgemm<<<gD, 256, SMEM_REQ>>>(xh, wvh, bv, nullptr, vh, MROWS, Dq, Dq, 0);

    attention_hmma<<<dim3(Sq/64, Hq, Bq), 128>>>(qh, kh, vh, mask, ah);

    // O-proj -> fp32 tmp; LN1 -> x1 fp32 + x1h fp16
    hgemm<<<gD, 256, SMEM_REQ>>>(ah, woh, bo, tmp, nullptr, MROWS, Dq, Dq, 0);
    residual_ln<<<MROWS, 256>>>(x, tmp, l1a, l1b, x1, x1h);

    // FFN
    hgemm<<<gF, 256, SMEM_REQ>>>(x1h, w1h, b1, nullptr, fh, MROWS, DFFq, Dq, 1);
    hgemm<<<gD, 256, SMEM_REQ>>>(fh, w2h, b2, tmp, nullptr, MROWS, Dq, DFFq, 0);
    residual_ln<<<MROWS, 256>>>(x1, tmp, l2a, l2b, out, nullptr);
}

// round 14
// speedup vs baseline: 9.2434x; 1.0213x over previous
// r14: multi-stream fork/join overlap (prepass + QKV concurrency); kernels = r13
#include <cuda_runtime.h>
#include <cuda_fp16.h>
#include <math.h>
#include <stdint.h>

#define Bq   8
#define Sq   1024
#define Dq   1024
#define Hq   16
#define DKq  64
#define DFFq 4096
#define MROWS (Bq * Sq)

typedef __half h16;

// ---------------- scratch ----------------
__device__ float g_tmp[MROWS * Dq];
__device__ float g_x1 [MROWS * Dq];
__device__ h16 g_qh [MROWS * Dq], g_kh [MROWS * Dq], g_vh [MROWS * Dq];
__device__ h16 g_xh [MROWS * Dq];
__device__ h16 g_ah [MROWS * Dq];
__device__ h16 g_x1h[MROWS * Dq];
__device__ h16 g_fh [MROWS * DFFq];
__device__ h16 g_wqh[Dq * Dq];
__device__ h16 g_wkh[Dq * Dq];
__device__ h16 g_wvh[Dq * Dq];
__device__ h16 g_woh[Dq * Dq];
__device__ h16 g_w1h[Dq * DFFq];
__device__ h16 g_w2h[DFFq * Dq];

// ---------------- helpers ----------------
__device__ __forceinline__ uint32_t smem_u32(const void* p) {
    uint32_t a;
    asm("{ .reg .u64 t; cvta.to.shared.u64 t, %1; cvt.u32.u64 %0, t; }" : "=r"(a) : "l"(p));
    return a;
}
__device__ __forceinline__ void cpa16(uint32_t s, const void* g) {
    asm volatile("cp.async.cg.shared.global [%0], [%1], 16;" :: "r"(s), "l"(g));
}
#define CP_COMMIT() asm volatile("cp.async.commit_group;" ::: "memory")
#define CP_WAIT1()  asm volatile("cp.async.wait_group 1;" ::: "memory")
#define CP_WAIT0()  asm volatile("cp.async.wait_group 0;" ::: "memory")
#define LDMX4(r0,r1,r2,r3,addr)                                               \
    asm volatile("ldmatrix.sync.aligned.m8n8.x4.shared.b16 {%0,%1,%2,%3},[%4];" \
        : "=r"(r0), "=r"(r1), "=r"(r2), "=r"(r3) : "r"(addr))
#define LDMX4T(r0,r1,r2,r3,addr)                                              \
    asm volatile("ldmatrix.sync.aligned.m8n8.x4.trans.shared.b16 {%0,%1,%2,%3},[%4];" \
        : "=r"(r0), "=r"(r1), "=r"(r2), "=r"(r3) : "r"(addr))
#define HMMA(d,a,b)                                                           \
    asm volatile("mma.sync.aligned.m16n8k16.row.col.f32.f16.f16.f32 "         \
        "{%0,%1,%2,%3},{%4,%5,%6,%7},{%8,%9},{%0,%1,%2,%3};"                  \
        : "+f"((d)[0]), "+f"((d)[1]), "+f"((d)[2]), "+f"((d)[3])              \
        : "r"((a)[0]), "r"((a)[1]), "r"((a)[2]), "r"((a)[3]),                 \
          "r"((b)[0]), "r"((b)[1]))

// ---------------- fp16 HMMA GEMM: C = Ah @ Bh^T + bias ---------------------
// 1-term. BM=128, BN=256, BK=64, 256 threads, warp tile 64x64, double buffer.
#define BM 128
#define BN 256
#define BK 64
#define OFF_A 0
#define OFF_B 16384
#define BUFB  49152
#define SMEM_REQ (2 * BUFB)            // 98304

__global__ __launch_bounds__(256) void hgemm(
    const h16* __restrict__ Ahb, const h16* __restrict__ Bhb,
    const float* __restrict__ bias, float* __restrict__ C,
    h16* __restrict__ Ch,
    int M, int N, int K, int doRelu)
{
    extern __shared__ char smem[];
    const uint32_t sb = smem_u32(smem);
    const int tid  = threadIdx.x;
    const int warp = tid >> 5, lane = tid & 31;
    const int bm = blockIdx.y * BM, bn = blockIdx.x * BN;
    const int m0w = (warp & 1) * 64, n0w = (warp >> 1) * 64;

    const int rL = tid >> 3, cL = tid & 7;
    const uint32_t sRowOff = (uint32_t)rL * 128 + (((uint32_t)(cL ^ (rL & 7))) << 4);
    const h16* gA = Ahb + (size_t)(bm + rL) * K + cL * 8;
    const h16* gB = Bhb + (size_t)(bn + rL) * K + cL * 8;
    const size_t rstep = (size_t)32 * K;

    float acc[4][8][4];
#pragma unroll
    for (int i = 0; i < 4; i++)
#pragma unroll
        for (int j = 0; j < 8; j++)
#pragma unroll
            for (int r = 0; r < 4; r++) acc[i][j][r] = 0.f;

    const int arow0 = m0w + (lane & 15);
    const int akc   = lane >> 4;
    const int brow0 = n0w + ((lane >> 4) << 3) + (lane & 7);
    const int bkc   = (lane >> 3) & 1;

    auto LOAD = [&](int c, int buf) {
        const uint32_t s = sb + (uint32_t)buf * BUFB;
        const size_t k0 = (size_t)c * BK;
#pragma unroll
        for (int i = 0; i < 4; i++) {
            const uint32_t so = sRowOff + (uint32_t)i * 4096;
            cpa16(s + OFF_A + so, gA + (size_t)i * rstep + k0);
        }
#pragma unroll
        for (int i = 0; i < 8; i++) {
            const uint32_t so = sRowOff + (uint32_t)i * 4096;
            cpa16(s + OFF_B + so, gB + (size_t)i * rstep + k0);
        }
    };

    auto COMPUTE = [&](int buf) {
        const uint32_t s = sb + (uint32_t)buf * BUFB;
#pragma unroll
        for (int ks = 0; ks < 4; ks++) {
            uint32_t bh[8][2];
#pragma unroll
            for (int bt = 0; bt < 4; bt++) {
                const int row = brow0 + bt * 16;
                const int kc  = ks * 2 + bkc;
                const uint32_t off = (uint32_t)row * 128 + (((uint32_t)(kc ^ (row & 7))) << 4);
                LDMX4(bh[2*bt][0], bh[2*bt][1], bh[2*bt+1][0], bh[2*bt+1][1], s + OFF_B + off);
            }
#pragma unroll
            for (int mt = 0; mt < 4; mt++) {
                const int row = arow0 + mt * 16;
                const int kc  = ks * 2 + akc;
                const uint32_t off = (uint32_t)row * 128 + (((uint32_t)(kc ^ (row & 7))) << 4);
                uint32_t a[4];
                LDMX4(a[0], a[1], a[2], a[3], s + OFF_A + off);
#pragma unroll
                for (int nt = 0; nt < 8; nt++) HMMA(acc[mt][nt], a, bh[nt]);
            }
        }
    };

    const int chunks = K / BK;
    LOAD(0, 0);
    CP_COMMIT();
#pragma unroll 1
    for (int c = 0; c < chunks; c++) {
        if (c + 1 < chunks) {
            LOAD(c + 1, (c + 1) & 1);
            CP_COMMIT();
            CP_WAIT1();
        } else {
            CP_WAIT0();
        }
        __syncthreads();
        COMPUTE(c & 1);
        __syncthreads();
    }

#pragma unroll
    for (int mt = 0; mt < 4; mt++) {
        const int mr = bm + m0w + mt * 16 + (lane >> 2);
#pragma unroll
        for (int nt = 0; nt < 8; nt++) {
            const int col = bn + n0w + nt * 8 + 2 * (lane & 3);
            const float b0 = bias[col], b1 = bias[col + 1];
            float v0 = acc[mt][nt][0] + b0, v1 = acc[mt][nt][1] + b1;
            float v2 = acc[mt][nt][2] + b0, v3 = acc[mt][nt][3] + b1;
            if (doRelu) {
                v0 = fmaxf(v0, 0.f); v1 = fmaxf(v1, 0.f);
                v2 = fmaxf(v2, 0.f); v3 = fmaxf(v3, 0.f);
            }
            if (C) {
                *(float2*)(C + (size_t)mr * N + col)       = make_float2(v0, v1);
                *(float2*)(C + (size_t)(mr + 8) * N + col) = make_float2(v2, v3);
            }
            if (Ch) {
                *(__half2*)(Ch + (size_t)mr * N + col)       = __floats2half2_rn(v0, v1);
                *(__half2*)(Ch + (size_t)(mr + 8) * N + col) = __floats2half2_rn(v2, v3);
            }
        }
    }
}

// ---------------- pre-pass kernels ----------------
__global__ __launch_bounds__(256) void vround_kernel(
    const float* __restrict__ s, h16* __restrict__ h, int n)
{
    int i = (blockIdx.x * 256 + threadIdx.x) * 4;
    if (i >= n) return;
    float4 v = *(const float4*)(s + i);
    *(__half2*)(h+i)   = __floats2half2_rn(v.x, v.y);
    *(__half2*)(h+i+2) = __floats2half2_rn(v.z, v.w);
}

__global__ __launch_bounds__(256) void ttrans_kernel(
    const float* __restrict__ W, h16* __restrict__ Th, int K, int N)
{
    __shared__ float t[32][33];
    const int n0 = blockIdx.x * 32, k0 = blockIdx.y * 32;
    const int tx = threadIdx.x & 31, ty = threadIdx.x >> 5;
#pragma unroll
    for (int i = ty; i < 32; i += 8)
        t[i][tx] = W[(size_t)(k0 + i) * N + n0 + tx];
    __syncthreads();
#pragma unroll
    for (int i = ty; i < 32; i += 8)
        Th[(size_t)(n0 + i) * K + k0 + tx] = __float2half_rn(t[tx][i]);
}

// ---------------- HMMA flash attention (single-limb output) ----------------
__global__ __launch_bounds__(128) void attention_hmma(
    const h16* __restrict__ Qg, const h16* __restrict__ Kg,
    const h16* __restrict__ Vg, const int* __restrict__ mask,
    h16* __restrict__ OH)
{
    __shared__ h16 Qs[64 * 64];
    __shared__ h16 Ks[64 * 64];
    __shared__ h16 Vs[64 * 64];
    __shared__ int ms[64];

    const int b = blockIdx.z, h = blockIdx.y, qt = blockIdx.x;
    const int tid = threadIdx.x, warp = tid >> 5, lane = tid & 31;
    const uint32_t qsb = smem_u32(Qs), ksb = smem_u32(Ks), vsb = smem_u32(Vs);

    const int lr = tid >> 1, lc0 = (tid & 1) * 4;
    const h16* qg = Qg + (size_t)(b * Sq + qt * 64 + lr) * Dq + h * 64;
    const h16* kgb = Kg + (size_t)(b * Sq + lr) * Dq + h * 64;
    const h16* vgb = Vg + (size_t)(b * Sq + lr) * Dq + h * 64;

#pragma unroll
    for (int c = 0; c < 4; c++) {
        const int ch = lc0 + c;
        const uint32_t sw = (uint32_t)lr * 128 + (((uint32_t)(ch ^ (lr & 7))) << 4);
        cpa16(qsb + sw, qg + ch * 8);
        cpa16(ksb + sw, kgb + ch * 8);
        cpa16(vsb + sw, vgb + ch * 8);
    }
    if (tid < 64) ms[tid] = mask[b * Sq + tid];
    CP_COMMIT();
    CP_WAIT0();
    __syncthreads();

    uint32_t qf[4][4];
    {
        const int row = warp * 16 + (lane & 15);
        const int kb = lane >> 4;
#pragma unroll
        for (int kf = 0; kf < 4; kf++) {
            const int kc = kf * 2 + kb;
            const uint32_t off = (uint32_t)row * 128 + (((uint32_t)(kc ^ (row & 7))) << 4);
            LDMX4(qf[kf][0], qf[kf][1], qf[kf][2], qf[kf][3], qsb + off);
        }
    }

    float oacc[8][4];
#pragma unroll
    for (int t = 0; t < 8; t++)
#pragma unroll
        for (int r = 0; r < 4; r++) oacc[t][r] = 0.f;
    float lsum0 = 0.f, lsum1 = 0.f;

    const int sb_row = ((lane >> 4) << 3) + (lane & 7);
    const int sb_kc  = (lane >> 3) & 1;
    const int vrow   = ((lane >> 3) & 1) * 8 + (lane & 7);
    const int vchb   = lane >> 4;
    const int mcol   = 2 * (lane & 3);

#pragma unroll 1
    for (int c = 0; c < 16; c++) {
        float sacc[8][4];
#pragma unroll
        for (int t = 0; t < 8; t++)
#pragma unroll
            for (int r = 0; r < 4; r++) sacc[t][r] = 0.f;
#pragma unroll
        for (int jt = 0; jt < 4; jt++) {
            const int row = jt * 16 + sb_row;
#pragma unroll
            for (int kf = 0; kf < 4; kf++) {
                const int kc = kf * 2 + sb_kc;
                const uint32_t off = (uint32_t)row * 128 + (((uint32_t)(kc ^ (row & 7))) << 4);
                uint32_t bb[4];
                LDMX4(bb[0], bb[1], bb[2], bb[3], ksb + off);
                HMMA(sacc[2*jt],   qf[kf], (bb));
                HMMA(sacc[2*jt+1], qf[kf], (bb + 2));
            }
        }

        uint32_t pf[4][4];
#pragma unroll
        for (int t = 0; t < 8; t++) {
            const int col = t * 8 + mcol;
            const int m0 = ms[col], m1 = ms[col + 1];
            float p0 = m0 ? __expf(0.125f * sacc[t][0]) : 0.f;
            float p1 = m1 ? __expf(0.125f * sacc[t][1]) : 0.f;
            float p2 = m0 ? __expf(0.125f * sacc[t][2]) : 0.f;
            float p3 = m1 ? __expf(0.125f * sacc[t][3]) : 0.f;
            lsum0 += p0 + p1;
            lsum1 += p2 + p3;
            __half2 a01 = __floats2half2_rn(p0, p1);
            __half2 a23 = __floats2half2_rn(p2, p3);
            pf[t >> 1][(t & 1) * 2 + 0] = *(uint32_t*)&a01;
            pf[t >> 1][(t & 1) * 2 + 1] = *(uint32_t*)&a23;
        }

#pragma unroll
        for (int np = 0; np < 4; np++) {
            const int chunk = np * 2 + vchb;
#pragma unroll
            for (int kt = 0; kt < 4; kt++) {
                const int r = kt * 16 + vrow;
                const uint32_t off = (uint32_t)r * 128 + (((uint32_t)(chunk ^ (r & 7))) << 4);
                uint32_t vb[4];
                LDMX4T(vb[0], vb[1], vb[2], vb[3], vsb + off);
                HMMA(oacc[2*np],   pf[kt], (vb));
                HMMA(oacc[2*np+1], pf[kt], (vb + 2));
            }
        }

        if (c < 15) {
            __syncthreads();
            const size_t gofs = (size_t)(c + 1) * 64 * Dq;
#pragma unroll
            for (int cc = 0; cc < 4; cc++) {
                const int ch = lc0 + cc;
                const uint32_t sw = (uint32_t)lr * 128 + (((uint32_t)(ch ^ (lr & 7))) << 4);
                cpa16(ksb + sw, kgb + gofs + ch * 8);
                cpa16(vsb + sw, vgb + gofs + ch * 8);
            }
            if (tid < 64) ms[tid] = mask[b * Sq + (c + 1) * 64 + tid];
            CP_COMMIT();
            CP_WAIT0();
            __syncthreads();
        }
    }

    lsum0 += __shfl_xor_sync(0xffffffffu, lsum0, 1);
    lsum0 += __shfl_xor_sync(0xffffffffu, lsum0, 2);
    lsum1 += __shfl_xor_sync(0xffffffffu, lsum1, 1);
    lsum1 += __shfl_xor_sync(0xffffffffu, lsum1, 2);
    const float inv0 = 1.f / lsum0, inv1 = 1.f / lsum1;

    const int qr0 = qt * 64 + warp * 16 + (lane >> 2);
    const size_t gr0 = (size_t)(b * Sq + qr0) * Dq;
    const size_t gr1 = gr0 + (size_t)8 * Dq;
#pragma unroll
    for (int t = 0; t < 8; t++) {
        const int col = h * 64 + t * 8 + mcol;
        *(__half2*)(OH + gr0 + col) = __floats2half2_rn(oacc[t][0] * inv0, oacc[t][1] * inv0);
        *(__half2*)(OH + gr1 + col) = __floats2half2_rn(oacc[t][2] * inv1, oacc[t][3] * inv1);
    }
}

// ---------------- residual + LayerNorm (opt fp16 out) ----------------
__global__ __launch_bounds__(256) void residual_ln(
    const float* __restrict__ X, const float* __restrict__ Y,
    const float* __restrict__ Aw, const float* __restrict__ Bw,
    float* __restrict__ out, h16* __restrict__ oh)
{
    const int row = blockIdx.x, tid = threadIdx.x;
    const size_t base = (size_t)row * Dq + tid * 4;
    float4 xv = *(const float4*)(X + base);
    float4 yv = *(const float4*)(Y + base);
    float4 v = make_float4(xv.x+yv.x, xv.y+yv.y, xv.z+yv.z, xv.w+yv.w);

    float s = v.x+v.y+v.z+v.w;
    float ss = v.x*v.x+v.y*v.y+v.z*v.z+v.w*v.w;
#pragma unroll
    for (int o = 16; o > 0; o >>= 1) {
        s  += __shfl_xor_sync(0xffffffffu, s, o);
        ss += __shfl_xor_sync(0xffffffffu, ss, o);
    }
    __shared__ float rs[8], rss[8];
    const int w = tid >> 5, lane = tid & 31;
    if (lane == 0) { rs[w] = s; rss[w] = ss; }
    __syncthreads();
    if (tid == 0) {
        float S = 0.f, SS = 0.f;
#pragma unroll
        for (int i = 0; i < 8; i++) { S += rs[i]; SS += rss[i]; }
        rs[0] = S; rss[0] = SS;
    }
    __syncthreads();
    const float mean = rs[0] * (1.f / Dq);
    const float var  = rss[0] * (1.f / Dq) - mean * mean;
    const float rstd = rsqrtf(var + 1e-6f);

    float4 a4 = *(const float4*)(Aw + tid * 4);
    float4 b4 = *(const float4*)(Bw + tid * 4);
    float4 o4;
    o4.x = a4.x * (v.x - mean) * rstd + b4.x;
    o4.y = a4.y * (v.y - mean) * rstd + b4.y;
    o4.z = a4.z * (v.z - mean) * rstd + b4.z;
    o4.w = a4.w * (v.w - mean) * rstd + b4.w;
    *(float4*)(out + base) = o4;
    if (oh) {
        *(__half2*)(oh+base)   = __floats2half2_rn(o4.x, o4.y);
        *(__half2*)(oh+base+2) = __floats2half2_rn(o4.z, o4.w);
    }
}

// ---------------- kernel_launch (multi-stream fork/join) ----------------
extern "C" void kernel_launch(void* const* d_in, const int* in_sizes, int n_in,
                              void* d_out, int out_size)
{
    const float* x   = (const float*)d_in[0];
    const int* mask  = (const int*)d_in[1];
    const float* wq  = (const float*)d_in[2];
    const float* bq  = (const float*)d_in[3];
    const float* wk  = (const float*)d_in[4];
    const float* bk  = (const float*)d_in[5];
    const float* wv  = (const float*)d_in[6];
    const float* bv  = (const float*)d_in[7];
    const float* wo  = (const float*)d_in[8];
    const float* bo  = (const float*)d_in[9];
    const float* l1a = (const float*)d_in[10];
    const float* l1b = (const float*)d_in[11];
    const float* l2a = (const float*)d_in[12];
    const float* l2b = (const float*)d_in[13];
    const float* w1  = (const float*)d_in[14];
    const float* b1  = (const float*)d_in[15];
    const float* w2  = (const float*)d_in[16];
    const float* b2  = (const float*)d_in[17];
    float* out = (float*)d_out;

    float *tmp, *x1;
    h16 *qh,*kh,*vh,*xh,*ah,*x1h,*fh;
    h16 *wqh,*wkh,*wvh,*woh,*w1h,*w2h;
    cudaGetSymbolAddress((void**)&tmp, g_tmp);
    cudaGetSymbolAddress((void**)&x1, g_x1);
    cudaGetSymbolAddress((void**)&qh, g_qh);
    cudaGetSymbolAddress((void**)&kh, g_kh);
    cudaGetSymbolAddress((void**)&vh, g_vh);
    cudaGetSymbolAddress((void**)&xh, g_xh);
    cudaGetSymbolAddress((void**)&ah, g_ah);
    cudaGetSymbolAddress((void**)&x1h, g_x1h);
    cudaGetSymbolAddress((void**)&fh, g_fh);
    cudaGetSymbolAddress((void**)&wqh, g_wqh);
    cudaGetSymbolAddress((void**)&wkh, g_wkh);
    cudaGetSymbolAddress((void**)&wvh, g_wvh);
    cudaGetSymbolAddress((void**)&woh, g_woh);
    cudaGetSymbolAddress((void**)&w1h, g_w1h);
    cudaGetSymbolAddress((void**)&w2h, g_w2h);

    static int inited = 0;
    static cudaStream_t s1, s2, s3;
    static cudaEvent_t eFork, eVr, eK, eV, eW;
    if (!inited) {
        cudaFuncSetAttribute(hgemm, cudaFuncAttributeMaxDynamicSharedMemorySize, SMEM_REQ);
        cudaStreamCreateWithFlags(&s1, cudaStreamNonBlocking);
        cudaStreamCreateWithFlags(&s2, cudaStreamNonBlocking);
        cudaStreamCreateWithFlags(&s3, cudaStreamNonBlocking);
        cudaEventCreateWithFlags(&eFork, cudaEventDisableTiming);
        cudaEventCreateWithFlags(&eVr,   cudaEventDisableTiming);
        cudaEventCreateWithFlags(&eK,    cudaEventDisableTiming);
        cudaEventCreateWithFlags(&eV,    cudaEventDisableTiming);
        cudaEventCreateWithFlags(&eW,    cudaEventDisableTiming);
        inited = 1;
    }

    const dim3 gD(Dq / BN, MROWS / BM);    // (4, 64)
    const dim3 gF(DFFq / BN, MROWS / BM);  // (16, 64)

    // fork: s1/s2/s3 branch off the capture (default) stream
    cudaEventRecord(eFork, 0);
    cudaStreamWaitEvent(s1, eFork, 0);
    cudaStreamWaitEvent(s2, eFork, 0);
    cudaStreamWaitEvent(s3, eFork, 0);

    // s3: weight transposes not needed until O-proj/FFN
    ttrans_kernel<<<dim3(Dq/32, Dq/32), 256, 0, s3>>>(wo, woh, Dq, Dq);
    ttrans_kernel<<<dim3(DFFq/32, Dq/32), 256, 0, s3>>>(w1, w1h, Dq, DFFq);
    ttrans_kernel<<<dim3(Dq/32, DFFq/32), 256, 0, s3>>>(w2, w2h, DFFq, Dq);
    cudaEventRecord(eW, s3);

    // default: round x, then Q chain
    vround_kernel<<<MROWS * Dq / 1024, 256>>>(x, xh, MROWS * Dq);
    cudaEventRecord(eVr, 0);
    cudaStreamWaitEvent(s1, eVr, 0);
    cudaStreamWaitEvent(s2, eVr, 0);

    ttrans_kernel<<<dim3(Dq/32, Dq/32), 256>>>(wq, wqh, Dq, Dq);
    hgemm<<<gD, 256, SMEM_REQ>>>(xh, wqh, bq, nullptr, qh, MROWS, Dq, Dq, 0);

    // s1: K chain
    ttrans_kernel<<<dim3(Dq/32, Dq/32), 256, 0, s1>>>(wk, wkh, Dq, Dq);
    hgemm<<<gD, 256, SMEM_REQ, s1>>>(xh, wkh, bk, nullptr, kh, MROWS, Dq, Dq, 0);
    cudaEventRecord(eK, s1);

    // s2: V chain
    ttrans_kernel<<<dim3(Dq/32, Dq/32), 256, 0, s2>>>(wv, wvh, Dq, Dq);
    hgemm<<<gD, 256, SMEM_REQ, s2>>>(xh, wvh, bv, nullptr, vh, MROWS, Dq, Dq, 0);
    cudaEventRecord(eV, s2);

    // join K, V into default before attention
    cudaStreamWaitEvent(0, eK, 0);
    cudaStreamWaitEvent(0, eV, 0);
    attention_hmma<<<dim3(Sq/64, Hq, Bq), 128>>>(qh, kh, vh, mask, ah);

    // join weight stream before O-proj
    cudaStreamWaitEvent(0, eW, 0);
    hgemm<<<gD, 256, SMEM_REQ>>>(ah, woh, bo, tmp, nullptr, MROWS, Dq, Dq, 0);
    residual_ln<<<MROWS, 256>>>(x, tmp, l1a, l1b, x1, x1h);

    hgemm<<<gF, 256, SMEM_REQ>>>(x1h, w1h, b1, nullptr, fh, MROWS, DFFq, Dq, 1);
    hgemm<<<gD, 256, SMEM_REQ>>>(fh, w2h, b2, tmp, nullptr, MROWS, Dq, DFFq, 0);
    residual_ln<<<MROWS, 256>>>(x1, tmp, l2a, l2b, out, nullptr);
}

// round 16
// speedup vs baseline: 9.3132x; 1.0075x over previous
// r15b: fused QKV GEMM (N=3072) + 128-row attention Q-tile (hash-bump resubmission)
#include <cuda_runtime.h>
#include <cuda_fp16.h>
#include <math.h>
#include <stdint.h>

#define Bq   8
#define Sq   1024
#define Dq   1024
#define Hq   16
#define DKq  64
#define DFFq 4096
#define MROWS (Bq * Sq)
#define NQKV 3072

typedef __half h16;

// ---------------- scratch ----------------
__device__ float g_tmp[MROWS * Dq];
__device__ float g_x1 [MROWS * Dq];
__device__ h16 g_qkv[MROWS * NQKV];
__device__ h16 g_xh [MROWS * Dq];
__device__ h16 g_ah [MROWS * Dq];
__device__ h16 g_x1h[MROWS * Dq];
__device__ h16 g_fh [MROWS * DFFq];
__device__ h16 g_wcat[NQKV * Dq];
__device__ float g_bcat[NQKV];
__device__ h16 g_woh[Dq * Dq];
__device__ h16 g_w1h[Dq * DFFq];
__device__ h16 g_w2h[DFFq * Dq];

// ---------------- helpers ----------------
__device__ __forceinline__ uint32_t smem_u32(const void* p) {
    uint32_t a;
    asm("{ .reg .u64 t; cvta.to.shared.u64 t, %1; cvt.u32.u64 %0, t; }" : "=r"(a) : "l"(p));
    return a;
}
__device__ __forceinline__ void cpa16(uint32_t s, const void* g) {
    asm volatile("cp.async.cg.shared.global [%0], [%1], 16;" :: "r"(s), "l"(g));
}
#define CP_COMMIT() asm volatile("cp.async.commit_group;" ::: "memory")
#define CP_WAIT1()  asm volatile("cp.async.wait_group 1;" ::: "memory")
#define CP_WAIT0()  asm volatile("cp.async.wait_group 0;" ::: "memory")
#define LDMX4(r0,r1,r2,r3,addr)                                               \
    asm volatile("ldmatrix.sync.aligned.m8n8.x4.shared.b16 {%0,%1,%2,%3},[%4];" \
        : "=r"(r0), "=r"(r1), "=r"(r2), "=r"(r3) : "r"(addr))
#define LDMX4T(r0,r1,r2,r3,addr)                                              \
    asm volatile("ldmatrix.sync.aligned.m8n8.x4.trans.shared.b16 {%0,%1,%2,%3},[%4];" \
        : "=r"(r0), "=r"(r1), "=r"(r2), "=r"(r3) : "r"(addr))
#define HMMA(d,a,b)                                                           \
    asm volatile("mma.sync.aligned.m16n8k16.row.col.f32.f16.f16.f32 "         \
        "{%0,%1,%2,%3},{%4,%5,%6,%7},{%8,%9},{%0,%1,%2,%3};"                  \
        : "+f"((d)[0]), "+f"((d)[1]), "+f"((d)[2]), "+f"((d)[3])              \
        : "r"((a)[0]), "r"((a)[1]), "r"((a)[2]), "r"((a)[3]),                 \
          "r"((b)[0]), "r"((b)[1]))

// ---------------- fp16 HMMA GEMM: C = Ah @ Bh^T + bias ---------------------
// 1-term, BM=128 BN=256 BK=64, 256 thr, warp tile 64x64, double-buffered.
#define BM 128
#define BN 256
#define BK 64
#define OFF_A 0
#define OFF_B 16384
#define BUFB  49152
#define SMEM_REQ (2 * BUFB)

__global__ __launch_bounds__(256) void hgemm(
    const h16* __restrict__ Ahb, const h16* __restrict__ Bhb,
    const float* __restrict__ bias, float* __restrict__ C,
    h16* __restrict__ Ch,
    int M, int N, int K, int doRelu)
{
    extern __shared__ char smem[];
    const uint32_t sb = smem_u32(smem);
    const int tid  = threadIdx.x;
    const int warp = tid >> 5, lane = tid & 31;
    const int bm = blockIdx.y * BM, bn = blockIdx.x * BN;
    const int m0w = (warp & 1) * 64, n0w = (warp >> 1) * 64;

    const int rL = tid >> 3, cL = tid & 7;
    const uint32_t sRowOff = (uint32_t)rL * 128 + (((uint32_t)(cL ^ (rL & 7))) << 4);
    const h16* gA = Ahb + (size_t)(bm + rL) * K + cL * 8;
    const h16* gB = Bhb + (size_t)(bn + rL) * K + cL * 8;
    const size_t rstep = (size_t)32 * K;

    float acc[4][8][4];
#pragma unroll
    for (int i = 0; i < 4; i++)
#pragma unroll
        for (int j = 0; j < 8; j++)
#pragma unroll
            for (int r = 0; r < 4; r++) acc[i][j][r] = 0.f;

    const int arow0 = m0w + (lane & 15);
    const int akc   = lane >> 4;
    const int brow0 = n0w + ((lane >> 4) << 3) + (lane & 7);
    const int bkc   = (lane >> 3) & 1;

    auto LOAD = [&](int c, int buf) {
        const uint32_t s = sb + (uint32_t)buf * BUFB;
        const size_t k0 = (size_t)c * BK;
#pragma unroll
        for (int i = 0; i < 4; i++) {
            const uint32_t so = sRowOff + (uint32_t)i * 4096;
            cpa16(s + OFF_A + so, gA + (size_t)i * rstep + k0);
        }
#pragma unroll
        for (int i = 0; i < 8; i++) {
            const uint32_t so = sRowOff + (uint32_t)i * 4096;
            cpa16(s + OFF_B + so, gB + (size_t)i * rstep + k0);
        }
    };

    auto COMPUTE = [&](int buf) {
        const uint32_t s = sb + (uint32_t)buf * BUFB;
#pragma unroll
        for (int ks = 0; ks < 4; ks++) {
            uint32_t bh[8][2];
#pragma unroll
            for (int bt = 0; bt < 4; bt++) {
                const int row = brow0 + bt * 16;
                const int kc  = ks * 2 + bkc;
                const uint32_t off = (uint32_t)row * 128 + (((uint32_t)(kc ^ (row & 7))) << 4);
                LDMX4(bh[2*bt][0], bh[2*bt][1], bh[2*bt+1][0], bh[2*bt+1][1], s + OFF_B + off);
            }
#pragma unroll
            for (int mt = 0; mt < 4; mt++) {
                const int row = arow0 + mt * 16;
                const int kc  = ks * 2 + akc;
                const uint32_t off = (uint32_t)row * 128 + (((uint32_t)(kc ^ (row & 7))) << 4);
                uint32_t a[4];
                LDMX4(a[0], a[1], a[2], a[3], s + OFF_A + off);
#pragma unroll
                for (int nt = 0; nt < 8; nt++) HMMA(acc[mt][nt], a, bh[nt]);
            }
        }
    };

    const int chunks = K / BK;
    LOAD(0, 0);
    CP_COMMIT();
#pragma unroll 1
    for (int c = 0; c < chunks; c++) {
        if (c + 1 < chunks) {
            LOAD(c + 1, (c + 1) & 1);
            CP_COMMIT();
            CP_WAIT1();
        } else {
            CP_WAIT0();
        }
        __syncthreads();
        COMPUTE(c & 1);
        __syncthreads();
    }

#pragma unroll
    for (int mt = 0; mt < 4; mt++) {
        const int mr = bm + m0w + mt * 16 + (lane >> 2);
#pragma unroll
        for (int nt = 0; nt < 8; nt++) {
            const int col = bn + n0w + nt * 8 + 2 * (lane & 3);
            const float b0 = bias[col], b1 = bias[col + 1];
            float v0 = acc[mt][nt][0] + b0, v1 = acc[mt][nt][1] + b1;
            float v2 = acc[mt][nt][2] + b0, v3 = acc[mt][nt][3] + b1;
            if (doRelu) {
                v0 = fmaxf(v0, 0.f); v1 = fmaxf(v1, 0.f);
                v2 = fmaxf(v2, 0.f); v3 = fmaxf(v3, 0.f);
            }
            if (C) {
                *(float2*)(C + (size_t)mr * N + col)       = make_float2(v0, v1);
                *(float2*)(C + (size_t)(mr + 8) * N + col) = make_float2(v2, v3);
            }
            if (Ch) {
                *(__half2*)(Ch + (size_t)mr * N + col)       = __floats2half2_rn(v0, v1);
                *(__half2*)(Ch + (size_t)(mr + 8) * N + col) = __floats2half2_rn(v2, v3);
            }
        }
    }
}

// ---------------- pre-pass kernels ----------------
__global__ __launch_bounds__(256) void vround_kernel(
    const float* __restrict__ s, h16* __restrict__ h, int n)
{
    int i = (blockIdx.x * 256 + threadIdx.x) * 4;
    if (i >= n) return;
    float4 v = *(const float4*)(s + i);
    *(__half2*)(h+i)   = __floats2half2_rn(v.x, v.y);
    *(__half2*)(h+i+2) = __floats2half2_rn(v.z, v.w);
}

__global__ __launch_bounds__(256) void ttrans_kernel(
    const float* __restrict__ W, h16* __restrict__ Th, int K, int N)
{
    __shared__ float t[32][33];
    const int n0 = blockIdx.x * 32, k0 = blockIdx.y * 32;
    const int tx = threadIdx.x & 31, ty = threadIdx.x >> 5;
#pragma unroll
    for (int i = ty; i < 32; i += 8)
        t[i][tx] = W[(size_t)(k0 + i) * N + n0 + tx];
    __syncthreads();
#pragma unroll
    for (int i = ty; i < 32; i += 8)
        Th[(size_t)(n0 + i) * K + k0 + tx] = __float2half_rn(t[tx][i]);
}

__global__ __launch_bounds__(256) void bcat_kernel(
    const float* __restrict__ a, const float* __restrict__ b,
    const float* __restrict__ c, float* __restrict__ o)
{
    int i = blockIdx.x * 256 + threadIdx.x;
    if (i < 1024) o[i] = a[i];
    else if (i < 2048) o[i] = b[i - 1024];
    else if (i < 3072) o[i] = c[i - 2048];
}

// ---------------- HMMA flash attention: 128 q-rows/block, 8 warps ----------
// QKV packed: row stride NQKV; Q col h*64, K col 1024+h*64, V col 2048+h*64.
__global__ __launch_bounds__(256) void attention_hmma(
    const h16* __restrict__ QKV, const int* __restrict__ mask,
    h16* __restrict__ OH)
{
    __shared__ h16 Qs[128 * 64];
    __shared__ h16 Ks[64 * 64];
    __shared__ h16 Vs[64 * 64];
    __shared__ int ms[64];

    const int b = blockIdx.z, h = blockIdx.y, qt = blockIdx.x;
    const int tid = threadIdx.x, warp = tid >> 5, lane = tid & 31;
    const uint32_t qsb = smem_u32(Qs), ksb = smem_u32(Ks), vsb = smem_u32(Vs);

    const int lrq = tid >> 1, lcq = (tid & 1) * 4;
    const int lrk = tid >> 2, lck = (tid & 3) * 2;

    const h16* qg  = QKV + (size_t)(b * Sq + qt * 128 + lrq) * NQKV + h * 64;
    const h16* kgb = QKV + (size_t)(b * Sq + lrk) * NQKV + 1024 + h * 64;
    const h16* vgb = QKV + (size_t)(b * Sq + lrk) * NQKV + 2048 + h * 64;

#pragma unroll
    for (int c = 0; c < 4; c++) {
        const int ch = lcq + c;
        const uint32_t sw = (uint32_t)lrq * 128 + (((uint32_t)(ch ^ (lrq & 7))) << 4);
        cpa16(qsb + sw, qg + ch * 8);
    }
#pragma unroll
    for (int c = 0; c < 2; c++) {
        const int ch = lck + c;
        const uint32_t sw = (uint32_t)lrk * 128 + (((uint32_t)(ch ^ (lrk & 7))) << 4);
        cpa16(ksb + sw, kgb + ch * 8);
        cpa16(vsb + sw, vgb + ch * 8);
    }
    if (tid < 64) ms[tid] = mask[b * Sq + tid];
    CP_COMMIT();
    CP_WAIT0();
    __syncthreads();

    uint32_t qf[4][4];
    {
        const int row = warp * 16 + (lane & 15);
        const int kb = lane >> 4;
#pragma unroll
        for (int kf = 0; kf < 4; kf++) {
            const int kc = kf * 2 + kb;
            const uint32_t off = (uint32_t)row * 128 + (((uint32_t)(kc ^ (row & 7))) << 4);
            LDMX4(qf[kf][0], qf[kf][1], qf[kf][2], qf[kf][3], qsb + off);
        }
    }

    float oacc[8][4];
#pragma unroll
    for (int t = 0; t < 8; t++)
#pragma unroll
        for (int r = 0; r < 4; r++) oacc[t][r] = 0.f;
    float lsum0 = 0.f, lsum1 = 0.f;

    const int sb_row = ((lane >> 4) << 3) + (lane & 7);
    const int sb_kc  = (lane >> 3) & 1;
    const int vrow   = ((lane >> 3) & 1) * 8 + (lane & 7);
    const int vchb   = lane >> 4;
    const int mcol   = 2 * (lane & 3);

#pragma unroll 1
    for (int c = 0; c < 16; c++) {
        float sacc[8][4];
#pragma unroll
        for (int t = 0; t < 8; t++)
#pragma unroll
            for (int r = 0; r < 4; r++) sacc[t][r] = 0.f;
#pragma unroll
        for (int jt = 0; jt < 4; jt++) {
            const int row = jt * 16 + sb_row;
#pragma unroll
            for (int kf = 0; kf < 4; kf++) {
                const int kc = kf * 2 + sb_kc;
                const uint32_t off = (uint32_t)row * 128 + (((uint32_t)(kc ^ (row & 7))) << 4);
                uint32_t bb[4];
                LDMX4(bb[0], bb[1], bb[2], bb[3], ksb + off);
                HMMA(sacc[2*jt],   qf[kf], (bb));
                HMMA(sacc[2*jt+1], qf[kf], (bb + 2));
            }
        }

        uint32_t pf[4][4];
#pragma unroll
        for (int t = 0; t < 8; t++) {
            const int col = t * 8 + mcol;
            const int m0 = ms[col], m1 = ms[col + 1];
            float p0 = m0 ? __expf(0.125f * sacc[t][0]) : 0.f;
            float p1 = m1 ? __expf(0.125f * sacc[t][1]) : 0.f;
            float p2 = m0 ? __expf(0.125f * sacc[t][2]) : 0.f;
            float p3 = m1 ? __expf(0.125f * sacc[t][3]) : 0.f;
            lsum0 += p0 + p1;
            lsum1 += p2 + p3;
            __half2 a01 = __floats2half2_rn(p0, p1);
            __half2 a23 = __floats2half2_rn(p2, p3);
            pf[t >> 1][(t & 1) * 2 + 0] = *(uint32_t*)&a01;
            pf[t >> 1][(t & 1) * 2 + 1] = *(uint32_t*)&a23;
        }

#pragma unroll
        for (int np = 0; np < 4; np++) {
            const int chunk = np * 2 + vchb;
#pragma unroll
            for (int kt = 0; kt < 4; kt++) {
                const int r = kt * 16 + vrow;
                const uint32_t off = (uint32_t)r * 128 + (((uint32_t)(chunk ^ (r & 7))) << 4);
                uint32_t vb[4];
                LDMX4T(vb[0], vb[1], vb[2], vb[3], vsb + off);
                HMMA(oacc[2*np],   pf[kt], (vb));
                HMMA(oacc[2*np+1], pf[kt], (vb + 2));
            }
        }

        if (c < 15) {
            __syncthreads();
            const size_t gofs = (size_t)(c + 1) * 64 * NQKV;
#pragma unroll
            for (int cc = 0; cc < 2; cc++) {
                const int ch = lck + cc;
                const uint32_t sw = (uint32_t)lrk * 128 + (((uint32_t)(ch ^ (lrk & 7))) << 4);
                cpa16(ksb + sw, kgb + gofs + ch * 8);
                cpa16(vsb + sw, vgb + gofs + ch * 8);
            }
            if (tid < 64) ms[tid] = mask[b * Sq + (c + 1) * 64 + tid];
            CP_COMMIT();
            CP_WAIT0();
            __syncthreads();
        }
    }

    lsum0 += __shfl_xor_sync(0xffffffffu, lsum0, 1);
    lsum0 += __shfl_xor_sync(0xffffffffu, lsum0, 2);
    lsum1 += __shfl_xor_sync(0xffffffffu, lsum1, 1);
    lsum1 += __shfl_xor_sync(0xffffffffu, lsum1, 2);
    const float inv0 = 1.f / lsum0, inv1 = 1.f / lsum1;

    const int qr0 = qt * 128 + warp * 16 + (lane >> 2);
    const size_t gr0 = (size_t)(b * Sq + qr0) * Dq;
    const size_t gr1 = gr0 + (size_t)8 * Dq;
#pragma unroll
    for (int t = 0; t < 8; t++) {
        const int col = h * 64 + t * 8 + mcol;
        *(__half2*)(OH + gr0 + col) = __floats2half2_rn(oacc[t][0] * inv0, oacc[t][1] * inv0);
        *(__half2*)(OH + gr1 + col) = __floats2half2_rn(oacc[t][2] * inv1, oacc[t][3] * inv1);
    }
}

// ---------------- residual + LayerNorm (opt fp16 out) ----------------
__global__ __launch_bounds__(256) void residual_ln(
    const float* __restrict__ X, const float* __restrict__ Y,
    const float* __restrict__ Aw, const float* __restrict__ Bw,
    float* __restrict__ out, h16* __restrict__ oh)
{
    const int row = blockIdx.x, tid = threadIdx.x;
    const size_t base = (size_t)row * Dq + tid * 4;
    float4 xv = *(const float4*)(X + base);
    float4 yv = *(const float4*)(Y + base);
    float4 v = make_float4(xv.x+yv.x, xv.y+yv.y, xv.z+yv.z, xv.w+yv.w);

    float s = v.x+v.y+v.z+v.w;
    float ss = v.x*v.x+v.y*v.y+v.z*v.z+v.w*v.w;
#pragma unroll
    for (int o = 16; o > 0; o >>= 1) {
        s  += __shfl_xor_sync(0xffffffffu, s, o);
        ss += __shfl_xor_sync(0xffffffffu, ss, o);
    }
    __shared__ float rs[8], rss[8];
    const int w = tid >> 5, lane = tid & 31;
    if (lane == 0) { rs[w] = s; rss[w] = ss; }
    __syncthreads();
    if (tid == 0) {
        float S = 0.f, SS = 0.f;
#pragma unroll
        for (int i = 0; i < 8; i++) { S += rs[i]; SS += rss[i]; }
        rs[0] = S; rss[0] = SS;
    }
    __syncthreads();
    const float mean = rs[0] * (1.f / Dq);
    const float var  = rss[0] * (1.f / Dq) - mean * mean;
    const float rstd = rsqrtf(var + 1e-6f);

    float4 a4 = *(const float4*)(Aw + tid * 4);
    float4 b4 = *(const float4*)(Bw + tid * 4);
    float4 o4;
    o4.x = a4.x * (v.x - mean) * rstd + b4.x;
    o4.y = a4.y * (v.y - mean) * rstd + b4.y;
    o4.z = a4.z * (v.z - mean) * rstd + b4.z;
    o4.w = a4.w * (v.w - mean) * rstd + b4.w;
    *(float4*)(out + base) = o4;
    if (oh) {
        *(__half2*)(oh+base)   = __floats2half2_rn(o4.x, o4.y);
        *(__half2*)(oh+base+2) = __floats2half2_rn(o4.z, o4.w);
    }
}

// ---------------- kernel_launch ----------------
extern "C" void kernel_launch(void* const* d_in, const int* in_sizes, int n_in,
                              void* d_out, int out_size)
{
    const float* x   = (const float*)d_in[0];
    const int* mask  = (const int*)d_in[1];
    const float* wq  = (const float*)d_in[2];
    const float* bq  = (const float*)d_in[3];
    const float* wk  = (const float*)d_in[4];
    const float* bk  = (const float*)d_in[5];
    const float* wv  = (const float*)d_in[6];
    const float* bv  = (const float*)d_in[7];
    const float* wo  = (const float*)d_in[8];
    const float* bo  = (const float*)d_in[9];
    const float* l1a = (const float*)d_in[10];
    const float* l1b = (const float*)d_in[11];
    const float* l2a = (const float*)d_in[12];
    const float* l2b = (const float*)d_in[13];
    const float* w1  = (const float*)d_in[14];
    const float* b1  = (const float*)d_in[15];
    const float* w2  = (const float*)d_in[16];
    const float* b2  = (const float*)d_in[17];
    float* out = (float*)d_out;

    float *tmp, *x1, *bcat;
    h16 *qkv,*xh,*ah,*x1h,*fh,*wcat,*woh,*w1h,*w2h;
    cudaGetSymbolAddress((void**)&tmp, g_tmp);
    cudaGetSymbolAddress((void**)&x1, g_x1);
    cudaGetSymbolAddress((void**)&qkv, g_qkv);
    cudaGetSymbolAddress((void**)&xh, g_xh);
    cudaGetSymbolAddress((void**)&ah, g_ah);
    cudaGetSymbolAddress((void**)&x1h, g_x1h);
    cudaGetSymbolAddress((void**)&fh, g_fh);
    cudaGetSymbolAddress((void**)&wcat, g_wcat);
    cudaGetSymbolAddress((void**)&bcat, g_bcat);
    cudaGetSymbolAddress((void**)&woh, g_woh);
    cudaGetSymbolAddress((void**)&w1h, g_w1h);
    cudaGetSymbolAddress((void**)&w2h, g_w2h);

    static int inited = 0;
    static cudaStream_t s1, s3;
    static cudaEvent_t eFork, eK, eW;
    if (!inited) {
        cudaFuncSetAttribute(hgemm, cudaFuncAttributeMaxDynamicSharedMemorySize, SMEM_REQ);
        cudaStreamCreateWithFlags(&s1, cudaStreamNonBlocking);
        cudaStreamCreateWithFlags(&s3, cudaStreamNonBlocking);
        cudaEventCreateWithFlags(&eFork, cudaEventDisableTiming);
        cudaEventCreateWithFlags(&eK,    cudaEventDisableTiming);
        cudaEventCreateWithFlags(&eW,    cudaEventDisableTiming);
        inited = 1;
    }

    const dim3 gQKV(NQKV / BN, MROWS / BM);  // (12, 64)
    const dim3 gD(Dq / BN, MROWS / BM);      // (4, 64)
    const dim3 gF(DFFq / BN, MROWS / BM);    // (16, 64)

    cudaEventRecord(eFork, 0);
    cudaStreamWaitEvent(s1, eFork, 0);
    cudaStreamWaitEvent(s3, eFork, 0);

    // s1: QKV weight prep (independent of x)
    bcat_kernel<<<12, 256, 0, s1>>>(bq, bk, bv, bcat);
    ttrans_kernel<<<dim3(Dq/32, Dq/32), 256, 0, s1>>>(wq, wcat, Dq, Dq);
    ttrans_kernel<<<dim3(Dq/32, Dq/32), 256, 0, s1>>>(wk, wcat + (size_t)1024 * Dq, Dq, Dq);
    ttrans_kernel<<<dim3(Dq/32, Dq/32), 256, 0, s1>>>(wv, wcat + (size_t)2048 * Dq, Dq, Dq);
    cudaEventRecord(eK, s1);

    // s3: tail weights
    ttrans_kernel<<<dim3(Dq/32, Dq/32), 256, 0, s3>>>(wo, woh, Dq, Dq);
    ttrans_kernel<<<dim3(DFFq/32, Dq/32), 256, 0, s3>>>(w1, w1h, Dq, DFFq);
    ttrans_kernel<<<dim3(Dq/32, DFFq/32), 256, 0, s3>>>(w2, w2h, DFFq, Dq);
    cudaEventRecord(eW, s3);

    // default: activations
    vround_kernel<<<MROWS * Dq / 1024, 256>>>(x, xh, MROWS * Dq);
    cudaStreamWaitEvent(0, eK, 0);
    hgemm<<<gQKV, 256, SMEM_REQ>>>(xh, wcat, bcat, nullptr, qkv, MROWS, NQKV, Dq, 0);

    attention_hmma<<<dim3(Sq/128, Hq, Bq), 256>>>(qkv, mask, ah);

    cudaStreamWaitEvent(0, eW, 0);
    hgemm<<<gD, 256, SMEM_REQ>>>(ah, woh, bo, tmp, nullptr, MROWS, Dq, Dq, 0);
    residual_ln<<<MROWS, 256>>>(x, tmp, l1a, l1b, x1, x1h);

    hgemm<<<gF, 256, SMEM_REQ>>>(x1h, w1h, b1, nullptr, fh, MROWS, DFFq, Dq, 1);
    hgemm<<<gD, 256, SMEM_REQ>>>(fh, w2h, b2, tmp, nullptr, MROWS, Dq, DFFq, 0);
    residual_ln<<<MROWS, 256>>>(x1, tmp, l2a, l2b, out, nullptr);
}